// round 2
// baseline (speedup 1.0000x reference)
#include <cuda_runtime.h>
#include <cstdint>
#include <cstddef>

// Problem constants
#define BATCH   2
#define TSEQ    2048
#define DMODEL  1024
#define NHEADS  16
#define DKEY    64
#define DFF     4096
#define NTOK    (BATCH*TSEQ)          // 4096
#define QKVROW  (3*NHEADS*DKEY)       // 3072

// ---------------- scratch (static device allocations are allowed) ----------
__device__ float g_xn  [(size_t)NTOK*DMODEL];   // LN1(X)
__device__ float g_qkv [(size_t)NTOK*QKVROW];   // qkv projections
__device__ float g_ctx [(size_t)NTOK*DMODEL];   // attention context
__device__ float g_x1  [(size_t)NTOK*DMODEL];   // X + attn_out
__device__ float g_xn2 [(size_t)NTOK*DMODEL];   // LN2(x1)
__device__ float g_h   [(size_t)NTOK*DFF];      // relu(ffn1)

// ---------------- LayerNorm: one block per row, d=1024 ---------------------
__inline__ __device__ float warp_sum(float v) {
    #pragma unroll
    for (int o = 16; o > 0; o >>= 1) v += __shfl_xor_sync(0xffffffffu, v, o);
    return v;
}

__global__ __launch_bounds__(256) void ln_kernel(
    const float* __restrict__ x, const float* __restrict__ g,
    const float* __restrict__ b, float* __restrict__ y)
{
    const int row = blockIdx.x;
    const int tid = threadIdx.x;
    const float* xr = x + (size_t)row * DMODEL;

    float4 v = reinterpret_cast<const float4*>(xr)[tid];   // 256 threads * 4 = 1024
    float s  = v.x + v.y + v.z + v.w;
    float sq = v.x*v.x + v.y*v.y + v.z*v.z + v.w*v.w;

    __shared__ float sh_s[8], sh_q[8];
    float ws = warp_sum(s), wq = warp_sum(sq);
    int warp = tid >> 5, lane = tid & 31;
    if (lane == 0) { sh_s[warp] = ws; sh_q[warp] = wq; }
    __syncthreads();
    __shared__ float sh_mean, sh_rstd;
    if (tid == 0) {
        float ts = 0.f, tq = 0.f;
        #pragma unroll
        for (int i = 0; i < 8; i++) { ts += sh_s[i]; tq += sh_q[i]; }
        float mean = ts * (1.0f / DMODEL);
        float var  = tq * (1.0f / DMODEL) - mean * mean;
        sh_mean = mean;
        sh_rstd = rsqrtf(var + 1e-5f);
    }
    __syncthreads();
    float mean = sh_mean, rstd = sh_rstd;

    float4 gv = reinterpret_cast<const float4*>(g)[tid];
    float4 bv = reinterpret_cast<const float4*>(b)[tid];
    float4 o;
    o.x = (v.x - mean) * rstd * gv.x + bv.x;
    o.y = (v.y - mean) * rstd * gv.y + bv.y;
    o.z = (v.z - mean) * rstd * gv.z + bv.z;
    o.w = (v.w - mean) * rstd * gv.w + bv.w;
    reinterpret_cast<float4*>(y + (size_t)row * DMODEL)[tid] = o;
}

// ---------------- SGEMM: C = A@B + bias (+res)(+relu) ----------------------
// A[M,K] row-major, B[K,N] row-major, all dims multiples of 128/8.
template<bool RELU, bool RES>
__global__ __launch_bounds__(256) void sgemm128(
    const float* __restrict__ A, const float* __restrict__ B,
    const float* __restrict__ bias, const float* __restrict__ res,
    float* __restrict__ C, int M, int N, int K)
{
    constexpr int BM = 128, BN = 128, BK = 8, TM = 8, TN = 8;
    __shared__ float As[BK][BM];
    __shared__ float Bs[BK][BN];

    const int tid = threadIdx.x;
    const int bm = blockIdx.y * BM;
    const int bn = blockIdx.x * BN;

    const int aRow = tid >> 1;          // 0..127
    const int aCol = (tid & 1) * 4;     // 0 or 4
    const int bRow = tid >> 5;          // 0..7
    const int bCol = (tid & 31) * 4;    // 0..124

    const int tr = (tid >> 4) * TM;     // 0..120
    const int tc = (tid & 15) * TN;     // 0..120

    float acc[TM][TN];
    #pragma unroll
    for (int i = 0; i < TM; i++)
        #pragma unroll
        for (int j = 0; j < TN; j++) acc[i][j] = 0.f;

    const float* Ap = A + (size_t)(bm + aRow) * K + aCol;
    const float* Bp = B + (size_t)bRow * N + bn + bCol;

    for (int k0 = 0; k0 < K; k0 += BK) {
        float4 av = *reinterpret_cast<const float4*>(Ap + k0);
        As[aCol + 0][aRow] = av.x;
        As[aCol + 1][aRow] = av.y;
        As[aCol + 2][aRow] = av.z;
        As[aCol + 3][aRow] = av.w;
        float4 bv = *reinterpret_cast<const float4*>(Bp + (size_t)k0 * N);
        *reinterpret_cast<float4*>(&Bs[bRow][bCol]) = bv;
        __syncthreads();

        #pragma unroll
        for (int k = 0; k < BK; k++) {
            float rm[TM], rn[TN];
            float4 m0 = *reinterpret_cast<const float4*>(&As[k][tr]);
            float4 m1 = *reinterpret_cast<const float4*>(&As[k][tr + 4]);
            rm[0]=m0.x; rm[1]=m0.y; rm[2]=m0.z; rm[3]=m0.w;
            rm[4]=m1.x; rm[5]=m1.y; rm[6]=m1.z; rm[7]=m1.w;
            float4 n0 = *reinterpret_cast<const float4*>(&Bs[k][tc]);
            float4 n1 = *reinterpret_cast<const float4*>(&Bs[k][tc + 4]);
            rn[0]=n0.x; rn[1]=n0.y; rn[2]=n0.z; rn[3]=n0.w;
            rn[4]=n1.x; rn[5]=n1.y; rn[6]=n1.z; rn[7]=n1.w;
            #pragma unroll
            for (int i = 0; i < TM; i++)
                #pragma unroll
                for (int j = 0; j < TN; j++)
                    acc[i][j] += rm[i] * rn[j];
        }
        __syncthreads();
    }

    #pragma unroll
    for (int i = 0; i < TM; i++) {
        const size_t row = (size_t)(bm + tr + i);
        #pragma unroll
        for (int j = 0; j < TN; j += 4) {
            const int col = bn + tc + j;
            float4 bb = *reinterpret_cast<const float4*>(&bias[col]);
            float4 o;
            o.x = acc[i][j+0] + bb.x;
            o.y = acc[i][j+1] + bb.y;
            o.z = acc[i][j+2] + bb.z;
            o.w = acc[i][j+3] + bb.w;
            if (RELU) {
                o.x = fmaxf(o.x, 0.f); o.y = fmaxf(o.y, 0.f);
                o.z = fmaxf(o.z, 0.f); o.w = fmaxf(o.w, 0.f);
            }
            if (RES) {
                float4 rr = *reinterpret_cast<const float4*>(&res[row * N + col]);
                o.x += rr.x; o.y += rr.y; o.z += rr.z; o.w += rr.w;
            }
            *reinterpret_cast<float4*>(&C[row * N + col]) = o;
        }
    }
}

// ---------------- Flash attention (causal, fp32) ----------------------------
// grid: (TSEQ/BQ, BATCH*NHEADS), block: 128 threads, 1 query row / thread.
__global__ __launch_bounds__(128) void flash_attn(
    const float* __restrict__ qkv, float* __restrict__ ctx)
{
    constexpr int BQ = 128, BK = 64, DK = DKEY;
    __shared__ float Qs[BQ][DK + 4];     // +4 floats keeps 16B alignment, kills conflicts
    __shared__ float Ks[BK][DK];
    __shared__ float Vs[BK][DK];

    const int tid = threadIdx.x;
    const int q0  = blockIdx.x * BQ;
    const int bh  = blockIdx.y;
    const int b   = bh >> 4, h = bh & 15;
    const int q_idx = q0 + tid;

    const float* base = qkv + (size_t)b * TSEQ * QKVROW + (size_t)h * DK;

    // cooperative, coalesced Q tile load: 128 rows x 64 floats
    #pragma unroll
    for (int i = 0; i < (BQ * DK) / (4 * 128); i++) {   // 16 float4s / thread
        int lin = i * 128 + tid;          // 0..2047
        int row = lin >> 4;
        int c4  = (lin & 15) * 4;
        *reinterpret_cast<float4*>(&Qs[row][c4]) =
            *reinterpret_cast<const float4*>(base + (size_t)(q0 + row) * QKVROW + c4);
    }
    __syncthreads();

    float4 qv[16];
    #pragma unroll
    for (int i = 0; i < 16; i++)
        qv[i] = reinterpret_cast<const float4*>(&Qs[tid][0])[i];

    float4 ov[16];
    #pragma unroll
    for (int i = 0; i < 16; i++) ov[i] = make_float4(0.f, 0.f, 0.f, 0.f);
    float m = -1e30f, l = 0.f;

    const int nkt = (q0 + BQ) / BK;      // causal: keys < q0+BQ
    for (int kt = 0; kt < nkt; kt++) {
        const int k0 = kt * BK;
        __syncthreads();                 // prior tile fully consumed
        #pragma unroll
        for (int i = 0; i < (BK * DK) / (4 * 128); i++) {  // 8 float4s / thread
            int lin = i * 128 + tid;
            int row = lin >> 4;
            int c4  = (lin & 15) * 4;
            const float* kp = base + (size_t)(k0 + row) * QKVROW + NHEADS * DK + c4;
            const float* vp = base + (size_t)(k0 + row) * QKVROW + 2 * NHEADS * DK + c4;
            *reinterpret_cast<float4*>(&Ks[row][c4]) = *reinterpret_cast<const float4*>(kp);
            *reinterpret_cast<float4*>(&Vs[row][c4]) = *reinterpret_cast<const float4*>(vp);
        }
        __syncthreads();

        const bool needmask = (k0 + BK - 1) > q_idx;

        #pragma unroll
        for (int c = 0; c < 2; c++) {    // two chunks of 32 keys
            float s[32];
            #pragma unroll
            for (int j = 0; j < 32; j++) {
                const int kj = c * 32 + j;
                const float4* krow = reinterpret_cast<const float4*>(&Ks[kj][0]);
                float sj = 0.f;
                #pragma unroll
                for (int d = 0; d < 16; d++) {
                    float4 kv = krow[d];   // broadcast LDS.128
                    sj += qv[d].x * kv.x + qv[d].y * kv.y
                        + qv[d].z * kv.z + qv[d].w * kv.w;
                }
                sj *= 0.125f;              // 1/sqrt(64)
                if (needmask && (k0 + kj > q_idx)) sj = -1e30f;
                s[j] = sj;
            }
            float mc = s[0];
            #pragma unroll
            for (int j = 1; j < 32; j++) mc = fmaxf(mc, s[j]);
            float mnew  = fmaxf(m, mc);
            float alpha = __expf(m - mnew);
            l *= alpha;
            #pragma unroll
            for (int i = 0; i < 16; i++) {
                ov[i].x *= alpha; ov[i].y *= alpha;
                ov[i].z *= alpha; ov[i].w *= alpha;
            }
            m = mnew;
            #pragma unroll
            for (int j = 0; j < 32; j++) {
                float p = __expf(s[j] - mnew);
                l += p;
                const float4* vrow = reinterpret_cast<const float4*>(&Vs[c * 32 + j][0]);
                #pragma unroll
                for (int d = 0; d < 16; d++) {
                    float4 vv = vrow[d];   // broadcast LDS.128
                    ov[d].x += p * vv.x; ov[d].y += p * vv.y;
                    ov[d].z += p * vv.z; ov[d].w += p * vv.w;
                }
            }
        }
    }

    const float inv = 1.f / l;
    float* cp = ctx + ((size_t)(b * TSEQ + q_idx)) * DMODEL + h * DK;
    #pragma unroll
    for (int d = 0; d < 16; d++) {
        float4 o;
        o.x = ov[d].x * inv; o.y = ov[d].y * inv;
        o.z = ov[d].z * inv; o.w = ov[d].w * inv;
        reinterpret_cast<float4*>(cp)[d] = o;
    }
}

// ---------------- launch ----------------------------------------------------
extern "C" void kernel_launch(void* const* d_in, const int* in_sizes, int n_in,
                              void* d_out, int out_size)
{
    (void)in_sizes; (void)n_in; (void)out_size;
    const float* X     = (const float*)d_in[0];
    const float* Wqkv  = (const float*)d_in[1];
    const float* bqkv  = (const float*)d_in[2];
    const float* Wo    = (const float*)d_in[3];
    const float* bo    = (const float*)d_in[4];
    const float* W1    = (const float*)d_in[5];
    const float* b1    = (const float*)d_in[6];
    const float* W2    = (const float*)d_in[7];
    const float* b2    = (const float*)d_in[8];
    const float* ln1g  = (const float*)d_in[9];
    const float* ln1b  = (const float*)d_in[10];
    const float* ln2g  = (const float*)d_in[11];
    const float* ln2b  = (const float*)d_in[12];
    float* out = (float*)d_out;

    float *xn, *qkv, *ctx, *x1, *xn2, *hbuf;
    cudaGetSymbolAddress((void**)&xn,   g_xn);
    cudaGetSymbolAddress((void**)&qkv,  g_qkv);
    cudaGetSymbolAddress((void**)&ctx,  g_ctx);
    cudaGetSymbolAddress((void**)&x1,   g_x1);
    cudaGetSymbolAddress((void**)&xn2,  g_xn2);
    cudaGetSymbolAddress((void**)&hbuf, g_h);

    // 1. LN1
    ln_kernel<<<NTOK, 256>>>(X, ln1g, ln1b, xn);
    // 2. QKV = LN1(X) @ Wqkv + bqkv        [4096,3072]
    sgemm128<false,false><<<dim3(QKVROW/128, NTOK/128), 256>>>(
        xn, Wqkv, bqkv, nullptr, qkv, NTOK, QKVROW, DMODEL);
    // 3. causal attention -> ctx           [4096,1024]
    flash_attn<<<dim3(TSEQ/128, BATCH*NHEADS), 128>>>(qkv, ctx);
    // 4. x1 = ctx @ Wo + bo + X
    sgemm128<false,true><<<dim3(DMODEL/128, NTOK/128), 256>>>(
        ctx, Wo, bo, X, x1, NTOK, DMODEL, DMODEL);
    // 5. LN2
    ln_kernel<<<NTOK, 256>>>(x1, ln2g, ln2b, xn2);
    // 6. h = relu(xn2 @ W1 + b1)            [4096,4096]
    sgemm128<true,false><<<dim3(DFF/128, NTOK/128), 256>>>(
        xn2, W1, b1, nullptr, hbuf, NTOK, DFF, DMODEL);
    // 7. out = h @ W2 + b2 + x1
    sgemm128<false,true><<<dim3(DMODEL/128, NTOK/128), 256>>>(
        hbuf, W2, b2, x1, out, NTOK, DMODEL, DFF);
}

// round 4
// speedup vs baseline: 1.4725x; 1.4725x over previous
#include <cuda_runtime.h>
#include <cuda_bf16.h>
#include <cstdint>
#include <cstddef>

// Problem constants
#define BATCH   2
#define TSEQ    2048
#define DMODEL  1024
#define NHEADS  16
#define DKEY    64
#define DFF     4096
#define NTOK    (BATCH*TSEQ)          // 4096
#define QKVROW  (3*NHEADS*DKEY)       // 3072

// ---------------- scratch ----------------------------------------------------
__device__ float g_xn  [(size_t)NTOK*DMODEL];
__device__ float g_qkv [(size_t)NTOK*QKVROW];
__device__ float g_ctx [(size_t)NTOK*DMODEL];
__device__ float g_x1  [(size_t)NTOK*DMODEL];
__device__ float g_xn2 [(size_t)NTOK*DMODEL];
__device__ float g_h   [(size_t)NTOK*DFF];

// transposed bf16 hi/lo weights  [N, K] K-major
__device__ __nv_bfloat16 g_wqkv_hi[(size_t)QKVROW*DMODEL];
__device__ __nv_bfloat16 g_wqkv_lo[(size_t)QKVROW*DMODEL];
__device__ __nv_bfloat16 g_wo_hi  [(size_t)DMODEL*DMODEL];
__device__ __nv_bfloat16 g_wo_lo  [(size_t)DMODEL*DMODEL];
__device__ __nv_bfloat16 g_w1_hi  [(size_t)DFF*DMODEL];
__device__ __nv_bfloat16 g_w1_lo  [(size_t)DFF*DMODEL];
__device__ __nv_bfloat16 g_w2_hi  [(size_t)DMODEL*DFF];
__device__ __nv_bfloat16 g_w2_lo  [(size_t)DMODEL*DFF];

// ---------------- helpers ----------------------------------------------------
__device__ __forceinline__ uint32_t smem_u32(const void* p) {
    uint32_t a;
    asm("{ .reg .u64 t; cvta.to.shared.u64 t, %1; cvt.u32.u64 %0, t; }"
        : "=r"(a) : "l"(p));
    return a;
}
#define CP_ASYNC16(dst, src) \
    asm volatile("cp.async.cg.shared.global [%0], [%1], 16;" :: "r"(dst), "l"(src) : "memory")
#define CP_COMMIT() asm volatile("cp.async.commit_group;" ::: "memory")
#define CP_WAIT0()  asm volatile("cp.async.wait_group 0;"  ::: "memory")
#define STS64(addr, v0, v1) \
    asm volatile("st.shared.v2.b32 [%0], {%1,%2};" :: "r"(addr), "r"(v0), "r"(v1) : "memory")

__device__ __forceinline__ void ldmat4(uint32_t (&r)[4], uint32_t addr) {
    asm volatile("ldmatrix.sync.aligned.m8n8.x4.shared.b16 {%0,%1,%2,%3}, [%4];"
        : "=r"(r[0]), "=r"(r[1]), "=r"(r[2]), "=r"(r[3]) : "r"(addr));
}
__device__ __forceinline__ void mma16816(float (&d)[4], const uint32_t (&a)[4],
                                         const uint32_t b0, const uint32_t b1) {
    asm volatile("mma.sync.aligned.m16n8k16.row.col.f32.bf16.bf16.f32 "
        "{%0,%1,%2,%3}, {%4,%5,%6,%7}, {%8,%9}, {%0,%1,%2,%3};"
        : "+f"(d[0]), "+f"(d[1]), "+f"(d[2]), "+f"(d[3])
        : "r"(a[0]), "r"(a[1]), "r"(a[2]), "r"(a[3]), "r"(b0), "r"(b1));
}
__device__ __forceinline__ uint32_t b2u(__nv_bfloat162 v) {
    union { __nv_bfloat162 h; uint32_t u; } c; c.h = v; return c.u;
}

// ---------------- LayerNorm --------------------------------------------------
__inline__ __device__ float warp_sum(float v) {
    #pragma unroll
    for (int o = 16; o > 0; o >>= 1) v += __shfl_xor_sync(0xffffffffu, v, o);
    return v;
}

__global__ __launch_bounds__(256) void ln_kernel(
    const float* __restrict__ x, const float* __restrict__ g,
    const float* __restrict__ b, float* __restrict__ y)
{
    const int row = blockIdx.x;
    const int tid = threadIdx.x;
    const float* xr = x + (size_t)row * DMODEL;

    float4 v = reinterpret_cast<const float4*>(xr)[tid];
    float s  = v.x + v.y + v.z + v.w;
    float sq = v.x*v.x + v.y*v.y + v.z*v.z + v.w*v.w;

    __shared__ float sh_s[8], sh_q[8];
    float ws = warp_sum(s), wq = warp_sum(sq);
    int warp = tid >> 5, lane = tid & 31;
    if (lane == 0) { sh_s[warp] = ws; sh_q[warp] = wq; }
    __syncthreads();
    __shared__ float sh_mean, sh_rstd;
    if (tid == 0) {
        float ts = 0.f, tq = 0.f;
        #pragma unroll
        for (int i = 0; i < 8; i++) { ts += sh_s[i]; tq += sh_q[i]; }
        float mean = ts * (1.0f / DMODEL);
        float var  = tq * (1.0f / DMODEL) - mean * mean;
        sh_mean = mean; sh_rstd = rsqrtf(var + 1e-5f);
    }
    __syncthreads();
    float mean = sh_mean, rstd = sh_rstd;

    float4 gv = reinterpret_cast<const float4*>(g)[tid];
    float4 bv = reinterpret_cast<const float4*>(b)[tid];
    float4 o;
    o.x = (v.x - mean) * rstd * gv.x + bv.x;
    o.y = (v.y - mean) * rstd * gv.y + bv.y;
    o.z = (v.z - mean) * rstd * gv.z + bv.z;
    o.w = (v.w - mean) * rstd * gv.w + bv.w;
    reinterpret_cast<float4*>(y + (size_t)row * DMODEL)[tid] = o;
}

// ---------------- weight transpose + bf16 split: W[K,N] -> hi/lo[N,K] --------
__global__ __launch_bounds__(256) void wconv(
    const float* __restrict__ W, __nv_bfloat16* __restrict__ hi,
    __nv_bfloat16* __restrict__ lo, int K, int N)
{
    __shared__ float t[32][33];
    const int n0 = blockIdx.x * 32, k0 = blockIdx.y * 32;
    const int tx = threadIdx.x & 31, ty = threadIdx.x >> 5;
    #pragma unroll
    for (int j = 0; j < 4; j++)
        t[ty + j*8][tx] = W[(size_t)(k0 + ty + j*8) * N + n0 + tx];
    __syncthreads();
    #pragma unroll
    for (int j = 0; j < 4; j++) {
        int n = ty + j*8;
        float x = t[tx][n];
        __nv_bfloat16 h = __float2bfloat16_rn(x);
        float l = x - __bfloat162float(h);
        hi[(size_t)(n0 + n) * K + k0 + tx] = h;
        lo[(size_t)(n0 + n) * K + k0 + tx] = __float2bfloat16_rn(l);
    }
}

// ---------------- HMMA GEMM: C[M,N] = A[M,K](f32) @ Bt[N,K](bf16 hi/lo) ------
// split-bf16: D += Ahi*Bhi + Ahi*Blo + Alo*Bhi
// CTA 128x128, 8 warps (warp tile 32x64), K_chunk=32, double-buffered smem.
// Row pitch 80B: ldmatrix row addrs hit distinct banks (20*r mod 32 distinct).
#define PITCHB   80u
#define TILE_B   (128u * PITCHB)       // 10240 bytes per operand tile
#define STAGE_B  (4u * TILE_B)         // Ah, Al, Bh, Bl
#define SMEM_TOT (2u * STAGE_B)        // 81920

template<bool RELU, bool RES>
__global__ __launch_bounds__(256, 1) void gemm_mma(
    const float* __restrict__ A,
    const __nv_bfloat16* __restrict__ Bhi, const __nv_bfloat16* __restrict__ Blo,
    const float* __restrict__ bias, const float* __restrict__ res,
    float* __restrict__ C, int N, int K)
{
    extern __shared__ char sm[];
    const int tid = threadIdx.x, wid = tid >> 5, lane = tid & 31;
    const int m0 = blockIdx.y * 128, n0 = blockIdx.x * 128;
    const uint32_t sb = smem_u32(sm);

    const int mw = (wid & 3) * 32;      // warp M offset
    const int nw = (wid >> 2) * 64;     // warp N offset
    const int lg = lane >> 3, lr = lane & 7;

    // per-thread load indices
    const int arow = tid >> 1;               // A: 2 quads per row pattern below
    float d[2][8][4];
    #pragma unroll
    for (int mt = 0; mt < 2; mt++)
        #pragma unroll
        for (int nt = 0; nt < 8; nt++)
            #pragma unroll
            for (int i = 0; i < 4; i++) d[mt][nt][i] = 0.f;

    const int nkt = K >> 5;    // K_chunk = 32
    (void)arow;

    // ---- B async loader: raw bf16 copy ----
    auto loadB = [&](int s, int k0) {
        const uint32_t BhS = sb + (uint32_t)s * STAGE_B + 2u * TILE_B;
        const uint32_t BlS = BhS + TILE_B;
        const __nv_bfloat16* BhB = Bhi + (size_t)n0 * K + k0;
        const __nv_bfloat16* BlB = Blo + (size_t)n0 * K + k0;
        #pragma unroll
        for (int i = 0; i < 2; i++) {
            int lin = i * 256 + tid;
            int row = lin >> 2, q = lin & 3;
            uint32_t off = (uint32_t)row * PITCHB + (uint32_t)q * 16u;
            CP_ASYNC16(BhS + off, (const char*)(BhB + (size_t)row * K) + q * 16);
            CP_ASYNC16(BlS + off, (const char*)(BlB + (size_t)row * K) + q * 16);
        }
        CP_COMMIT();
    };
    // ---- A prefetch to regs ----
    float4 ap[4];
    auto prefA = [&](int k0) {
        const float* Ab = A + (size_t)m0 * K + k0;
        #pragma unroll
        for (int i = 0; i < 4; i++) {
            int lin = i * 256 + tid;
            int row = lin >> 3, q = lin & 7;
            ap[i] = *reinterpret_cast<const float4*>(Ab + (size_t)row * K + q * 4);
        }
    };
    // ---- A convert + store (hi/lo split) ----
    auto storeA = [&](int s) {
        const uint32_t AhS = sb + (uint32_t)s * STAGE_B;
        const uint32_t AlS = AhS + TILE_B;
        #pragma unroll
        for (int i = 0; i < 4; i++) {
            int lin = i * 256 + tid;
            int row = lin >> 3, q = lin & 7;
            float4 v = ap[i];
            __nv_bfloat16 hx = __float2bfloat16_rn(v.x);
            __nv_bfloat16 hy = __float2bfloat16_rn(v.y);
            __nv_bfloat16 hz = __float2bfloat16_rn(v.z);
            __nv_bfloat16 hw = __float2bfloat16_rn(v.w);
            __nv_bfloat162 h01; h01.x = hx; h01.y = hy;
            __nv_bfloat162 h23; h23.x = hz; h23.y = hw;
            __nv_bfloat162 l01 = __floats2bfloat162_rn(v.x - __bfloat162float(hx),
                                                       v.y - __bfloat162float(hy));
            __nv_bfloat162 l23 = __floats2bfloat162_rn(v.z - __bfloat162float(hz),
                                                       v.w - __bfloat162float(hw));
            uint32_t off = (uint32_t)row * PITCHB + (uint32_t)q * 8u;
            STS64(AhS + off, b2u(h01), b2u(h23));
            STS64(AlS + off, b2u(l01), b2u(l23));
        }
    };
    // ---- MMA over one staged K32 chunk ----
    auto mmaStage = [&](int s) {
        const uint32_t AhS = sb + (uint32_t)s * STAGE_B;
        const uint32_t AlS = AhS + TILE_B;
        const uint32_t BhS = AhS + 2u * TILE_B;
        const uint32_t BlS = AhS + 3u * TILE_B;
        #pragma unroll
        for (int kh = 0; kh < 2; kh++) {
            uint32_t ah[2][4], al[2][4];
            #pragma unroll
            for (int mt = 0; mt < 2; mt++) {
                uint32_t roff = (uint32_t)(mw + mt*16 + lr + ((lg & 1) << 3)) * PITCHB
                              + (uint32_t)(kh*16 + ((lg >> 1) << 3)) * 2u;
                ldmat4(ah[mt], AhS + roff);
                ldmat4(al[mt], AlS + roff);
            }
            #pragma unroll
            for (int bt = 0; bt < 4; bt++) {
                uint32_t roff = (uint32_t)(nw + bt*16 + lr + ((lg & 2) ? 8 : 0)) * PITCHB
                              + (uint32_t)(kh*16 + ((lg & 1) << 3)) * 2u;
                uint32_t bh[4], bl[4];
                ldmat4(bh, BhS + roff);
                ldmat4(bl, BlS + roff);
                #pragma unroll
                for (int mt = 0; mt < 2; mt++) {
                    mma16816(d[mt][2*bt+0], ah[mt], bh[0], bh[1]);
                    mma16816(d[mt][2*bt+0], ah[mt], bl[0], bl[1]);
                    mma16816(d[mt][2*bt+0], al[mt], bh[0], bh[1]);
                    mma16816(d[mt][2*bt+1], ah[mt], bh[2], bh[3]);
                    mma16816(d[mt][2*bt+1], ah[mt], bl[2], bl[3]);
                    mma16816(d[mt][2*bt+1], al[mt], bh[2], bh[3]);
                }
            }
        }
    };

    // ---- pipeline ----
    prefA(0);
    loadB(0, 0);
    storeA(0);
    CP_WAIT0();
    __syncthreads();

    for (int kt = 0; kt < nkt; kt++) {
        const int s = kt & 1;
        const bool more = (kt + 1) < nkt;
        if (more) { prefA((kt + 1) << 5); loadB(s ^ 1, (kt + 1) << 5); }
        mmaStage(s);
        if (more) { storeA(s ^ 1); CP_WAIT0(); }
        __syncthreads();
    }

    // ---- epilogue ----
    const int qr = lane >> 2;        // 0..7
    const int qc = (lane & 3) * 2;   // 0,2,4,6
    #pragma unroll
    for (int mt = 0; mt < 2; mt++) {
        const int r0 = m0 + mw + mt * 16 + qr;
        const int r1 = r0 + 8;
        #pragma unroll
        for (int nt = 0; nt < 8; nt++) {
            const int c = n0 + nw + nt * 8 + qc;
            float2 bb = *reinterpret_cast<const float2*>(bias + c);
            float2 o0, o1;
            o0.x = d[mt][nt][0] + bb.x; o0.y = d[mt][nt][1] + bb.y;
            o1.x = d[mt][nt][2] + bb.x; o1.y = d[mt][nt][3] + bb.y;
            if (RELU) {
                o0.x = fmaxf(o0.x, 0.f); o0.y = fmaxf(o0.y, 0.f);
                o1.x = fmaxf(o1.x, 0.f); o1.y = fmaxf(o1.y, 0.f);
            }
            if (RES) {
                float2 u0 = *reinterpret_cast<const float2*>(res + (size_t)r0 * N + c);
                float2 u1 = *reinterpret_cast<const float2*>(res + (size_t)r1 * N + c);
                o0.x += u0.x; o0.y += u0.y; o1.x += u1.x; o1.y += u1.y;
            }
            *reinterpret_cast<float2*>(C + (size_t)r0 * N + c) = o0;
            *reinterpret_cast<float2*>(C + (size_t)r1 * N + c) = o1;
        }
    }
}

// ---------------- Flash attention (causal, fp32) -----------------------------
__global__ __launch_bounds__(128) void flash_attn(
    const float* __restrict__ qkv, float* __restrict__ ctx)
{
    constexpr int BQ = 128, BK = 64, DK = DKEY;
    __shared__ float Qs[BQ][DK + 4];
    __shared__ float Ks[BK][DK];
    __shared__ float Vs[BK][DK];

    const int tid = threadIdx.x;
    const int q0  = blockIdx.x * BQ;
    const int bh  = blockIdx.y;
    const int b   = bh >> 4, h = bh & 15;
    const int q_idx = q0 + tid;

    const float* base = qkv + (size_t)b * TSEQ * QKVROW + (size_t)h * DK;

    #pragma unroll
    for (int i = 0; i < (BQ * DK) / (4 * 128); i++) {
        int lin = i * 128 + tid;
        int row = lin >> 4;
        int c4  = (lin & 15) * 4;
        *reinterpret_cast<float4*>(&Qs[row][c4]) =
            *reinterpret_cast<const float4*>(base + (size_t)(q0 + row) * QKVROW + c4);
    }
    __syncthreads();

    float4 qv[16];
    #pragma unroll
    for (int i = 0; i < 16; i++)
        qv[i] = reinterpret_cast<const float4*>(&Qs[tid][0])[i];

    float4 ov[16];
    #pragma unroll
    for (int i = 0; i < 16; i++) ov[i] = make_float4(0.f, 0.f, 0.f, 0.f);
    float m = -1e30f, l = 0.f;

    const int nkt = (q0 + BQ) / BK;
    for (int kt = 0; kt < nkt; kt++) {
        const int k0 = kt * BK;
        __syncthreads();
        #pragma unroll
        for (int i = 0; i < (BK * DK) / (4 * 128); i++) {
            int lin = i * 128 + tid;
            int row = lin >> 4;
            int c4  = (lin & 15) * 4;
            const float* kp = base + (size_t)(k0 + row) * QKVROW + NHEADS * DK + c4;
            const float* vp = base + (size_t)(k0 + row) * QKVROW + 2 * NHEADS * DK + c4;
            *reinterpret_cast<float4*>(&Ks[row][c4]) = *reinterpret_cast<const float4*>(kp);
            *reinterpret_cast<float4*>(&Vs[row][c4]) = *reinterpret_cast<const float4*>(vp);
        }
        __syncthreads();

        const bool needmask = (k0 + BK - 1) > q_idx;

        #pragma unroll
        for (int c = 0; c < 2; c++) {
            float s[32];
            #pragma unroll
            for (int j = 0; j < 32; j++) {
                const int kj = c * 32 + j;
                const float4* krow = reinterpret_cast<const float4*>(&Ks[kj][0]);
                float sj = 0.f;
                #pragma unroll
                for (int dd = 0; dd < 16; dd++) {
                    float4 kv = krow[dd];
                    sj += qv[dd].x * kv.x + qv[dd].y * kv.y
                        + qv[dd].z * kv.z + qv[dd].w * kv.w;
                }
                sj *= 0.125f;
                if (needmask && (k0 + kj > q_idx)) sj = -1e30f;
                s[j] = sj;
            }
            float mc = s[0];
            #pragma unroll
            for (int j = 1; j < 32; j++) mc = fmaxf(mc, s[j]);
            float mnew  = fmaxf(m, mc);
            float alpha = __expf(m - mnew);
            l *= alpha;
            #pragma unroll
            for (int i = 0; i < 16; i++) {
                ov[i].x *= alpha; ov[i].y *= alpha;
                ov[i].z *= alpha; ov[i].w *= alpha;
            }
            m = mnew;
            #pragma unroll
            for (int j = 0; j < 32; j++) {
                float p = __expf(s[j] - mnew);
                l += p;
                const float4* vrow = reinterpret_cast<const float4*>(&Vs[c * 32 + j][0]);
                #pragma unroll
                for (int dd = 0; dd < 16; dd++) {
                    float4 vv = vrow[dd];
                    ov[dd].x += p * vv.x; ov[dd].y += p * vv.y;
                    ov[dd].z += p * vv.z; ov[dd].w += p * vv.w;
                }
            }
        }
    }

    const float inv = 1.f / l;
    float* cp = ctx + ((size_t)(b * TSEQ + q_idx)) * DMODEL + h * DK;
    #pragma unroll
    for (int dd = 0; dd < 16; dd++) {
        float4 o;
        o.x = ov[dd].x * inv; o.y = ov[dd].y * inv;
        o.z = ov[dd].z * inv; o.w = ov[dd].w * inv;
        reinterpret_cast<float4*>(cp)[dd] = o;
    }
}

// ---------------- launch ------------------------------------------------------
extern "C" void kernel_launch(void* const* d_in, const int* in_sizes, int n_in,
                              void* d_out, int out_size)
{
    (void)in_sizes; (void)n_in; (void)out_size;
    const float* X     = (const float*)d_in[0];
    const float* Wqkv  = (const float*)d_in[1];
    const float* bqkv  = (const float*)d_in[2];
    const float* Wo    = (const float*)d_in[3];
    const float* bo    = (const float*)d_in[4];
    const float* W1    = (const float*)d_in[5];
    const float* b1    = (const float*)d_in[6];
    const float* W2    = (const float*)d_in[7];
    const float* b2    = (const float*)d_in[8];
    const float* ln1g  = (const float*)d_in[9];
    const float* ln1b  = (const float*)d_in[10];
    const float* ln2g  = (const float*)d_in[11];
    const float* ln2b  = (const float*)d_in[12];
    float* out = (float*)d_out;

    float *xn, *qkv, *ctx, *x1, *xn2, *hbuf;
    cudaGetSymbolAddress((void**)&xn,   g_xn);
    cudaGetSymbolAddress((void**)&qkv,  g_qkv);
    cudaGetSymbolAddress((void**)&ctx,  g_ctx);
    cudaGetSymbolAddress((void**)&x1,   g_x1);
    cudaGetSymbolAddress((void**)&xn2,  g_xn2);
    cudaGetSymbolAddress((void**)&hbuf, g_h);

    __nv_bfloat16 *wqkv_hi, *wqkv_lo, *wo_hi, *wo_lo, *w1_hi, *w1_lo, *w2_hi, *w2_lo;
    cudaGetSymbolAddress((void**)&wqkv_hi, g_wqkv_hi);
    cudaGetSymbolAddress((void**)&wqkv_lo, g_wqkv_lo);
    cudaGetSymbolAddress((void**)&wo_hi,   g_wo_hi);
    cudaGetSymbolAddress((void**)&wo_lo,   g_wo_lo);
    cudaGetSymbolAddress((void**)&w1_hi,   g_w1_hi);
    cudaGetSymbolAddress((void**)&w1_lo,   g_w1_lo);
    cudaGetSymbolAddress((void**)&w2_hi,   g_w2_hi);
    cudaGetSymbolAddress((void**)&w2_lo,   g_w2_lo);

    // idempotent, executed host-side every call (not captured into the graph)
    cudaFuncSetAttribute(gemm_mma<false,false>, cudaFuncAttributeMaxDynamicSharedMemorySize, SMEM_TOT);
    cudaFuncSetAttribute(gemm_mma<false,true>,  cudaFuncAttributeMaxDynamicSharedMemorySize, SMEM_TOT);
    cudaFuncSetAttribute(gemm_mma<true,false>,  cudaFuncAttributeMaxDynamicSharedMemorySize, SMEM_TOT);

    // weight transpose + split (deterministic each call)
    wconv<<<dim3(QKVROW/32, DMODEL/32), 256>>>(Wqkv, wqkv_hi, wqkv_lo, DMODEL, QKVROW);
    wconv<<<dim3(DMODEL/32, DMODEL/32), 256>>>(Wo,   wo_hi,   wo_lo,   DMODEL, DMODEL);
    wconv<<<dim3(DFF/32,    DMODEL/32), 256>>>(W1,   w1_hi,   w1_lo,   DMODEL, DFF);
    wconv<<<dim3(DMODEL/32, DFF/32),    256>>>(W2,   w2_hi,   w2_lo,   DFF,    DMODEL);

    // 1. LN1
    ln_kernel<<<NTOK, 256>>>(X, ln1g, ln1b, xn);
    // 2. QKV = LN1(X) @ Wqkv + bqkv
    gemm_mma<false,false><<<dim3(QKVROW/128, NTOK/128), 256, SMEM_TOT>>>(
        xn, wqkv_hi, wqkv_lo, bqkv, nullptr, qkv, QKVROW, DMODEL);
    // 3. attention
    flash_attn<<<dim3(TSEQ/128, BATCH*NHEADS), 128>>>(qkv, ctx);
    // 4. x1 = ctx @ Wo + bo + X
    gemm_mma<false,true><<<dim3(DMODEL/128, NTOK/128), 256, SMEM_TOT>>>(
        ctx, wo_hi, wo_lo, bo, X, x1, DMODEL, DMODEL);
    // 5. LN2
    ln_kernel<<<NTOK, 256>>>(x1, ln2g, ln2b, xn2);
    // 6. h = relu(xn2 @ W1 + b1)
    gemm_mma<true,false><<<dim3(DFF/128, NTOK/128), 256, SMEM_TOT>>>(
        xn2, w1_hi, w1_lo, b1, nullptr, hbuf, DFF, DMODEL);
    // 7. out = h @ W2 + b2 + x1
    gemm_mma<false,true><<<dim3(DMODEL/128, NTOK/128), 256, SMEM_TOT>>>(
        hbuf, w2_hi, w2_lo, b2, x1, out, DMODEL, DFF);
}

// round 5
// speedup vs baseline: 3.2821x; 2.2290x over previous
#include <cuda_runtime.h>
#include <cuda_bf16.h>
#include <cstdint>
#include <cstddef>

// Problem constants
#define BATCH   2
#define TSEQ    2048
#define DMODEL  1024
#define NHEADS  16
#define DKEY    64
#define DFF     4096
#define NTOK    (BATCH*TSEQ)          // 4096
#define QKVROW  (3*NHEADS*DKEY)       // 3072

// ---------------- scratch ----------------------------------------------------
__device__ float g_xn  [(size_t)NTOK*DMODEL];
__device__ float g_qkv [(size_t)NTOK*QKVROW];
__device__ float g_ctx [(size_t)NTOK*DMODEL];
__device__ float g_x1  [(size_t)NTOK*DMODEL];
__device__ float g_xn2 [(size_t)NTOK*DMODEL];
__device__ float g_h   [(size_t)NTOK*DFF];

// transposed bf16 hi/lo weights  [N, K] K-major
__device__ __nv_bfloat16 g_wqkv_hi[(size_t)QKVROW*DMODEL];
__device__ __nv_bfloat16 g_wqkv_lo[(size_t)QKVROW*DMODEL];
__device__ __nv_bfloat16 g_wo_hi  [(size_t)DMODEL*DMODEL];
__device__ __nv_bfloat16 g_wo_lo  [(size_t)DMODEL*DMODEL];
__device__ __nv_bfloat16 g_w1_hi  [(size_t)DFF*DMODEL];
__device__ __nv_bfloat16 g_w1_lo  [(size_t)DFF*DMODEL];
__device__ __nv_bfloat16 g_w2_hi  [(size_t)DMODEL*DFF];
__device__ __nv_bfloat16 g_w2_lo  [(size_t)DMODEL*DFF];

// attention bf16 operands
// Q (scaled by 1/8) + K, layout [tok][2048] (Q cols 0..1023, K cols 1024..2047)
__device__ __nv_bfloat16 g_qkh[(size_t)NTOK*2048];
__device__ __nv_bfloat16 g_qkl[(size_t)NTOK*2048];
// V transposed per (b,h): [bh][d][t]
__device__ __nv_bfloat16 g_vth[(size_t)BATCH*NHEADS*DKEY*TSEQ];
__device__ __nv_bfloat16 g_vtl[(size_t)BATCH*NHEADS*DKEY*TSEQ];

// ---------------- helpers ----------------------------------------------------
__device__ __forceinline__ uint32_t smem_u32(const void* p) {
    uint32_t a;
    asm("{ .reg .u64 t; cvta.to.shared.u64 t, %1; cvt.u32.u64 %0, t; }"
        : "=r"(a) : "l"(p));
    return a;
}
#define CP_ASYNC16(dst, src) \
    asm volatile("cp.async.cg.shared.global [%0], [%1], 16;" :: "r"(dst), "l"(src) : "memory")
#define CP_COMMIT() asm volatile("cp.async.commit_group;" ::: "memory")
#define CP_WAIT0()  asm volatile("cp.async.wait_group 0;"  ::: "memory")
#define CP_WAIT1()  asm volatile("cp.async.wait_group 1;"  ::: "memory")
#define STS64(addr, v0, v1) \
    asm volatile("st.shared.v2.b32 [%0], {%1,%2};" :: "r"(addr), "r"(v0), "r"(v1) : "memory")

__device__ __forceinline__ void ldmat4(uint32_t (&r)[4], uint32_t addr) {
    asm volatile("ldmatrix.sync.aligned.m8n8.x4.shared.b16 {%0,%1,%2,%3}, [%4];"
        : "=r"(r[0]), "=r"(r[1]), "=r"(r[2]), "=r"(r[3]) : "r"(addr));
}
__device__ __forceinline__ void mma16816(float (&d)[4], const uint32_t (&a)[4],
                                         const uint32_t b0, const uint32_t b1) {
    asm volatile("mma.sync.aligned.m16n8k16.row.col.f32.bf16.bf16.f32 "
        "{%0,%1,%2,%3}, {%4,%5,%6,%7}, {%8,%9}, {%0,%1,%2,%3};"
        : "+f"(d[0]), "+f"(d[1]), "+f"(d[2]), "+f"(d[3])
        : "r"(a[0]), "r"(a[1]), "r"(a[2]), "r"(a[3]), "r"(b0), "r"(b1));
}
__device__ __forceinline__ uint32_t b2u(__nv_bfloat162 v) {
    union { __nv_bfloat162 h; uint32_t u; } c; c.h = v; return c.u;
}

// ---------------- LayerNorm --------------------------------------------------
__inline__ __device__ float warp_sum(float v) {
    #pragma unroll
    for (int o = 16; o > 0; o >>= 1) v += __shfl_xor_sync(0xffffffffu, v, o);
    return v;
}

__global__ __launch_bounds__(256) void ln_kernel(
    const float* __restrict__ x, const float* __restrict__ g,
    const float* __restrict__ b, float* __restrict__ y)
{
    const int row = blockIdx.x;
    const int tid = threadIdx.x;
    const float* xr = x + (size_t)row * DMODEL;

    float4 v = reinterpret_cast<const float4*>(xr)[tid];
    float s  = v.x + v.y + v.z + v.w;
    float sq = v.x*v.x + v.y*v.y + v.z*v.z + v.w*v.w;

    __shared__ float sh_s[8], sh_q[8];
    float ws = warp_sum(s), wq = warp_sum(sq);
    int warp = tid >> 5, lane = tid & 31;
    if (lane == 0) { sh_s[warp] = ws; sh_q[warp] = wq; }
    __syncthreads();
    __shared__ float sh_mean, sh_rstd;
    if (tid == 0) {
        float ts = 0.f, tq = 0.f;
        #pragma unroll
        for (int i = 0; i < 8; i++) { ts += sh_s[i]; tq += sh_q[i]; }
        float mean = ts * (1.0f / DMODEL);
        float var  = tq * (1.0f / DMODEL) - mean * mean;
        sh_mean = mean; sh_rstd = rsqrtf(var + 1e-5f);
    }
    __syncthreads();
    float mean = sh_mean, rstd = sh_rstd;

    float4 gv = reinterpret_cast<const float4*>(g)[tid];
    float4 bv = reinterpret_cast<const float4*>(b)[tid];
    float4 o;
    o.x = (v.x - mean) * rstd * gv.x + bv.x;
    o.y = (v.y - mean) * rstd * gv.y + bv.y;
    o.z = (v.z - mean) * rstd * gv.z + bv.z;
    o.w = (v.w - mean) * rstd * gv.w + bv.w;
    reinterpret_cast<float4*>(y + (size_t)row * DMODEL)[tid] = o;
}

// ---------------- weight transpose + bf16 split: W[K,N] -> hi/lo[N,K] --------
__global__ __launch_bounds__(256) void wconv(
    const float* __restrict__ W, __nv_bfloat16* __restrict__ hi,
    __nv_bfloat16* __restrict__ lo, int K, int N)
{
    __shared__ float t[32][33];
    const int n0 = blockIdx.x * 32, k0 = blockIdx.y * 32;
    const int tx = threadIdx.x & 31, ty = threadIdx.x >> 5;
    #pragma unroll
    for (int j = 0; j < 4; j++)
        t[ty + j*8][tx] = W[(size_t)(k0 + ty + j*8) * N + n0 + tx];
    __syncthreads();
    #pragma unroll
    for (int j = 0; j < 4; j++) {
        int n = ty + j*8;
        float x = t[tx][n];
        __nv_bfloat16 h = __float2bfloat16_rn(x);
        float l = x - __bfloat162float(h);
        hi[(size_t)(n0 + n) * K + k0 + tx] = h;
        lo[(size_t)(n0 + n) * K + k0 + tx] = __float2bfloat16_rn(l);
    }
}

// ---------------- QK convert: qkv f32 -> bf16 hi/lo (Q scaled by 1/8) --------
__global__ __launch_bounds__(256) void qkconv(
    const float* __restrict__ qkv,
    __nv_bfloat16* __restrict__ hi, __nv_bfloat16* __restrict__ lo)
{
    const int idx = blockIdx.x * 256 + threadIdx.x;   // one float4 / thread
    const int tok = idx >> 9;                         // 512 float4 per row
    const int c4  = (idx & 511) << 2;
    const float sc = (c4 < 1024) ? 0.125f : 1.0f;
    float4 v = *reinterpret_cast<const float4*>(qkv + (size_t)tok * QKVROW + c4);
    v.x *= sc; v.y *= sc; v.z *= sc; v.w *= sc;
    __nv_bfloat16 hx = __float2bfloat16_rn(v.x);
    __nv_bfloat16 hy = __float2bfloat16_rn(v.y);
    __nv_bfloat16 hz = __float2bfloat16_rn(v.z);
    __nv_bfloat16 hw = __float2bfloat16_rn(v.w);
    __nv_bfloat162 h01; h01.x = hx; h01.y = hy;
    __nv_bfloat162 h23; h23.x = hz; h23.y = hw;
    __nv_bfloat162 l01 = __floats2bfloat162_rn(v.x - __bfloat162float(hx),
                                               v.y - __bfloat162float(hy));
    __nv_bfloat162 l23 = __floats2bfloat162_rn(v.z - __bfloat162float(hz),
                                               v.w - __bfloat162float(hw));
    size_t o = (size_t)tok * 2048 + c4;
    *reinterpret_cast<__nv_bfloat162*>(hi + o)     = h01;
    *reinterpret_cast<__nv_bfloat162*>(hi + o + 2) = h23;
    *reinterpret_cast<__nv_bfloat162*>(lo + o)     = l01;
    *reinterpret_cast<__nv_bfloat162*>(lo + o + 2) = l23;
}

// ---------------- V transpose-convert: qkv V part -> vt hi/lo [bh][d][t] ----
__global__ __launch_bounds__(256) void vtconv(
    const float* __restrict__ qkv,
    __nv_bfloat16* __restrict__ vh, __nv_bfloat16* __restrict__ vl)
{
    __shared__ float t[32][33];
    const int t0 = blockIdx.x * 32, d0 = blockIdx.y * 32;
    const int bh = blockIdx.z, b = bh >> 4, h = bh & 15;
    const int tx = threadIdx.x & 31, ty = threadIdx.x >> 5;
    #pragma unroll
    for (int j = 0; j < 4; j++) {
        int tt = ty + j*8;
        t[tt][tx] = qkv[(size_t)(b*TSEQ + t0 + tt) * QKVROW + 2048 + h*64 + d0 + tx];
    }
    __syncthreads();
    #pragma unroll
    for (int j = 0; j < 4; j++) {
        int d = ty + j*8;
        float x = t[tx][d];
        __nv_bfloat16 hh = __float2bfloat16_rn(x);
        float ll = x - __bfloat162float(hh);
        size_t o = ((size_t)bh * 64 + d0 + d) * TSEQ + t0 + tx;
        vh[o] = hh;
        vl[o] = __float2bfloat16_rn(ll);
    }
}

// ---------------- HMMA GEMM (unchanged from round 4) -------------------------
#define PITCHB   80u
#define TILE_B   (128u * PITCHB)
#define STAGE_B  (4u * TILE_B)
#define SMEM_TOT (2u * STAGE_B)        // 81920

template<bool RELU, bool RES>
__global__ __launch_bounds__(256, 1) void gemm_mma(
    const float* __restrict__ A,
    const __nv_bfloat16* __restrict__ Bhi, const __nv_bfloat16* __restrict__ Blo,
    const float* __restrict__ bias, const float* __restrict__ res,
    float* __restrict__ C, int N, int K)
{
    extern __shared__ char sm[];
    const int tid = threadIdx.x, wid = tid >> 5, lane = tid & 31;
    const int m0 = blockIdx.y * 128, n0 = blockIdx.x * 128;
    const uint32_t sb = smem_u32(sm);

    const int mw = (wid & 3) * 32;
    const int nw = (wid >> 2) * 64;
    const int lg = lane >> 3, lr = lane & 7;

    float d[2][8][4];
    #pragma unroll
    for (int mt = 0; mt < 2; mt++)
        #pragma unroll
        for (int nt = 0; nt < 8; nt++)
            #pragma unroll
            for (int i = 0; i < 4; i++) d[mt][nt][i] = 0.f;

    const int nkt = K >> 5;

    auto loadB = [&](int s, int k0) {
        const uint32_t BhS = sb + (uint32_t)s * STAGE_B + 2u * TILE_B;
        const uint32_t BlS = BhS + TILE_B;
        const __nv_bfloat16* BhB = Bhi + (size_t)n0 * K + k0;
        const __nv_bfloat16* BlB = Blo + (size_t)n0 * K + k0;
        #pragma unroll
        for (int i = 0; i < 2; i++) {
            int lin = i * 256 + tid;
            int row = lin >> 2, q = lin & 3;
            uint32_t off = (uint32_t)row * PITCHB + (uint32_t)q * 16u;
            CP_ASYNC16(BhS + off, (const char*)(BhB + (size_t)row * K) + q * 16);
            CP_ASYNC16(BlS + off, (const char*)(BlB + (size_t)row * K) + q * 16);
        }
        CP_COMMIT();
    };
    float4 ap[4];
    auto prefA = [&](int k0) {
        const float* Ab = A + (size_t)m0 * K + k0;
        #pragma unroll
        for (int i = 0; i < 4; i++) {
            int lin = i * 256 + tid;
            int row = lin >> 3, q = lin & 7;
            ap[i] = *reinterpret_cast<const float4*>(Ab + (size_t)row * K + q * 4);
        }
    };
    auto storeA = [&](int s) {
        const uint32_t AhS = sb + (uint32_t)s * STAGE_B;
        const uint32_t AlS = AhS + TILE_B;
        #pragma unroll
        for (int i = 0; i < 4; i++) {
            int lin = i * 256 + tid;
            int row = lin >> 3, q = lin & 7;
            float4 v = ap[i];
            __nv_bfloat16 hx = __float2bfloat16_rn(v.x);
            __nv_bfloat16 hy = __float2bfloat16_rn(v.y);
            __nv_bfloat16 hz = __float2bfloat16_rn(v.z);
            __nv_bfloat16 hw = __float2bfloat16_rn(v.w);
            __nv_bfloat162 h01; h01.x = hx; h01.y = hy;
            __nv_bfloat162 h23; h23.x = hz; h23.y = hw;
            __nv_bfloat162 l01 = __floats2bfloat162_rn(v.x - __bfloat162float(hx),
                                                       v.y - __bfloat162float(hy));
            __nv_bfloat162 l23 = __floats2bfloat162_rn(v.z - __bfloat162float(hz),
                                                       v.w - __bfloat162float(hw));
            uint32_t off = (uint32_t)row * PITCHB + (uint32_t)q * 8u;
            STS64(AhS + off, b2u(h01), b2u(h23));
            STS64(AlS + off, b2u(l01), b2u(l23));
        }
    };
    auto mmaStage = [&](int s) {
        const uint32_t AhS = sb + (uint32_t)s * STAGE_B;
        const uint32_t AlS = AhS + TILE_B;
        const uint32_t BhS = AhS + 2u * TILE_B;
        const uint32_t BlS = AhS + 3u * TILE_B;
        #pragma unroll
        for (int kh = 0; kh < 2; kh++) {
            uint32_t ah[2][4], al[2][4];
            #pragma unroll
            for (int mt = 0; mt < 2; mt++) {
                uint32_t roff = (uint32_t)(mw + mt*16 + lr + ((lg & 1) << 3)) * PITCHB
                              + (uint32_t)(kh*16 + ((lg >> 1) << 3)) * 2u;
                ldmat4(ah[mt], AhS + roff);
                ldmat4(al[mt], AlS + roff);
            }
            #pragma unroll
            for (int bt = 0; bt < 4; bt++) {
                uint32_t roff = (uint32_t)(nw + bt*16 + lr + ((lg & 2) ? 8 : 0)) * PITCHB
                              + (uint32_t)(kh*16 + ((lg & 1) << 3)) * 2u;
                uint32_t bh[4], bl[4];
                ldmat4(bh, BhS + roff);
                ldmat4(bl, BlS + roff);
                #pragma unroll
                for (int mt = 0; mt < 2; mt++) {
                    mma16816(d[mt][2*bt+0], ah[mt], bh[0], bh[1]);
                    mma16816(d[mt][2*bt+0], ah[mt], bl[0], bl[1]);
                    mma16816(d[mt][2*bt+0], al[mt], bh[0], bh[1]);
                    mma16816(d[mt][2*bt+1], ah[mt], bh[2], bh[3]);
                    mma16816(d[mt][2*bt+1], ah[mt], bl[2], bl[3]);
                    mma16816(d[mt][2*bt+1], al[mt], bh[2], bh[3]);
                }
            }
        }
    };

    prefA(0);
    loadB(0, 0);
    storeA(0);
    CP_WAIT0();
    __syncthreads();

    for (int kt = 0; kt < nkt; kt++) {
        const int s = kt & 1;
        const bool more = (kt + 1) < nkt;
        if (more) { prefA((kt + 1) << 5); loadB(s ^ 1, (kt + 1) << 5); }
        mmaStage(s);
        if (more) { storeA(s ^ 1); CP_WAIT0(); }
        __syncthreads();
    }

    const int qr = lane >> 2;
    const int qc = (lane & 3) * 2;
    #pragma unroll
    for (int mt = 0; mt < 2; mt++) {
        const int r0 = m0 + mw + mt * 16 + qr;
        const int r1 = r0 + 8;
        #pragma unroll
        for (int nt = 0; nt < 8; nt++) {
            const int c = n0 + nw + nt * 8 + qc;
            float2 bb = *reinterpret_cast<const float2*>(bias + c);
            float2 o0, o1;
            o0.x = d[mt][nt][0] + bb.x; o0.y = d[mt][nt][1] + bb.y;
            o1.x = d[mt][nt][2] + bb.x; o1.y = d[mt][nt][3] + bb.y;
            if (RELU) {
                o0.x = fmaxf(o0.x, 0.f); o0.y = fmaxf(o0.y, 0.f);
                o1.x = fmaxf(o1.x, 0.f); o1.y = fmaxf(o1.y, 0.f);
            }
            if (RES) {
                float2 u0 = *reinterpret_cast<const float2*>(res + (size_t)r0 * N + c);
                float2 u1 = *reinterpret_cast<const float2*>(res + (size_t)r1 * N + c);
                o0.x += u0.x; o0.y += u0.y; o1.x += u1.x; o1.y += u1.y;
            }
            *reinterpret_cast<float2*>(C + (size_t)r0 * N + c) = o0;
            *reinterpret_cast<float2*>(C + (size_t)r1 * N + c) = o1;
        }
    }
}

// ---------------- MMA flash attention (causal) -------------------------------
// BQ=128 (8 warps x 16 rows), BK=64, double-buffered K/V stages.
// smem pitch 144B -> ldmatrix banks 4r mod 32 distinct.
#define APITCH 144u
#define AQ_B   (128u * APITCH)         // 18432 per Q buffer
#define AKV_B  (64u * APITCH)          // 9216 per operand tile
#define ASTG_B (4u * AKV_B)            // Kh,Kl,Vh,Vl = 36864
#define ASMEM  (2u * AQ_B + 2u * ASTG_B)   // 110592

__global__ __launch_bounds__(256, 1) void flash_mma(
    const __nv_bfloat16* __restrict__ qkh, const __nv_bfloat16* __restrict__ qkl,
    const __nv_bfloat16* __restrict__ vth, const __nv_bfloat16* __restrict__ vtl,
    float* __restrict__ ctx)
{
    extern __shared__ char sm[];
    const int tid = threadIdx.x, wid = tid >> 5, lane = tid & 31;
    const int q0 = (15 - blockIdx.x) * 128;      // heavy blocks first
    const int bh = blockIdx.y, b = bh >> 4, h = bh & 15;
    const int mw = wid * 16;
    const int lg = lane >> 3, lr = lane & 7;
    const int qr = lane >> 2, qc = (lane & 3) * 2;

    const uint32_t sb = smem_u32(sm);
    const uint32_t QH = sb, QL = sb + AQ_B;
    const uint32_t ST = sb + 2u * AQ_B;

    // ---- load Q tile (hi+lo) ----
    {
        const __nv_bfloat16* qb_h = qkh + (size_t)(b*TSEQ + q0) * 2048 + h*64;
        const __nv_bfloat16* qb_l = qkl + (size_t)(b*TSEQ + q0) * 2048 + h*64;
        #pragma unroll
        for (int i = 0; i < 4; i++) {
            int lin = i * 256 + tid;
            int row = lin >> 3, seg = lin & 7;
            uint32_t off = (uint32_t)row * APITCH + (uint32_t)seg * 16u;
            CP_ASYNC16(QH + off, (const char*)(qb_h + (size_t)row * 2048) + seg * 16);
            CP_ASYNC16(QL + off, (const char*)(qb_l + (size_t)row * 2048) + seg * 16);
        }
        CP_COMMIT();
    }

    auto loadKV = [&](int s, int key0) {
        const uint32_t KHs = ST + (uint32_t)s * ASTG_B;
        const uint32_t KLs = KHs + AKV_B;
        const uint32_t VHs = KHs + 2u * AKV_B;
        const uint32_t VLs = KHs + 3u * AKV_B;
        const __nv_bfloat16* kb_h = qkh + (size_t)(b*TSEQ + key0) * 2048 + 1024 + h*64;
        const __nv_bfloat16* kb_l = qkl + (size_t)(b*TSEQ + key0) * 2048 + 1024 + h*64;
        const __nv_bfloat16* vb_h = vth + (size_t)bh * 64 * TSEQ + key0;
        const __nv_bfloat16* vb_l = vtl + (size_t)bh * 64 * TSEQ + key0;
        #pragma unroll
        for (int i = 0; i < 2; i++) {
            int lin = i * 256 + tid;
            int row = lin >> 3, seg = lin & 7;
            uint32_t off = (uint32_t)row * APITCH + (uint32_t)seg * 16u;
            CP_ASYNC16(KHs + off, (const char*)(kb_h + (size_t)row * 2048) + seg * 16);
            CP_ASYNC16(KLs + off, (const char*)(kb_l + (size_t)row * 2048) + seg * 16);
            CP_ASYNC16(VHs + off, (const char*)(vb_h + (size_t)row * TSEQ) + seg * 16);
            CP_ASYNC16(VLs + off, (const char*)(vb_l + (size_t)row * TSEQ) + seg * 16);
        }
        CP_COMMIT();
    };

    const int nkt = q0 / 64 + 2;
    loadKV(0, 0);
    CP_WAIT0();
    __syncthreads();

    // ---- Q fragments to registers ----
    uint32_t qfh[4][4], qfl[4][4];
    #pragma unroll
    for (int kh = 0; kh < 4; kh++) {
        uint32_t roff = (uint32_t)(mw + lr + ((lg & 1) << 3)) * APITCH
                      + (uint32_t)(kh*16 + ((lg >> 1) << 3)) * 2u;
        ldmat4(qfh[kh], QH + roff);
        ldmat4(qfl[kh], QL + roff);
    }

    float o[8][4];
    #pragma unroll
    for (int nt = 0; nt < 8; nt++)
        #pragma unroll
        for (int i = 0; i < 4; i++) o[nt][i] = 0.f;
    float m0r = -1e30f, m1r = -1e30f, l0r = 0.f, l1r = 0.f;

    for (int kt = 0; kt < nkt; kt++) {
        const int s = kt & 1;
        const int key0 = kt * 64;
        const bool more = (kt + 1) < nkt;
        if (more) loadKV(s ^ 1, key0 + 64);
        if (more) { CP_WAIT1(); } else { CP_WAIT0(); }
        __syncthreads();

        if (key0 <= q0 + mw + 15) {   // warp has at least one unmasked row
            const uint32_t KHs = ST + (uint32_t)s * ASTG_B;
            const uint32_t KLs = KHs + AKV_B;
            const uint32_t VHs = KHs + 2u * AKV_B;
            const uint32_t VLs = KHs + 3u * AKV_B;

            // ---- S = Q @ K^T ----
            float sc[8][4];
            #pragma unroll
            for (int nt = 0; nt < 8; nt++)
                #pragma unroll
                for (int i = 0; i < 4; i++) sc[nt][i] = 0.f;

            #pragma unroll
            for (int kh = 0; kh < 4; kh++) {
                #pragma unroll
                for (int bt = 0; bt < 4; bt++) {
                    uint32_t roff = (uint32_t)(bt*16 + lr + ((lg & 2) ? 8 : 0)) * APITCH
                                  + (uint32_t)(kh*16 + ((lg & 1) << 3)) * 2u;
                    uint32_t kfh[4], kfl[4];
                    ldmat4(kfh, KHs + roff);
                    ldmat4(kfl, KLs + roff);
                    mma16816(sc[2*bt+0], qfh[kh], kfh[0], kfh[1]);
                    mma16816(sc[2*bt+0], qfh[kh], kfl[0], kfl[1]);
                    mma16816(sc[2*bt+0], qfl[kh], kfh[0], kfh[1]);
                    mma16816(sc[2*bt+1], qfh[kh], kfh[2], kfh[3]);
                    mma16816(sc[2*bt+1], qfh[kh], kfl[2], kfl[3]);
                    mma16816(sc[2*bt+1], qfl[kh], kfh[2], kfh[3]);
                }
            }

            // ---- causal mask ----
            const int row0 = q0 + mw + qr, row1 = row0 + 8;
            if (key0 + 63 > q0 + mw) {
                #pragma unroll
                for (int nt = 0; nt < 8; nt++) {
                    int c0 = key0 + nt*8 + qc;
                    if (c0     > row0) sc[nt][0] = -1e30f;
                    if (c0 + 1 > row0) sc[nt][1] = -1e30f;
                    if (c0     > row1) sc[nt][2] = -1e30f;
                    if (c0 + 1 > row1) sc[nt][3] = -1e30f;
                }
            }

            // ---- online softmax ----
            float mx0 = -1e30f, mx1 = -1e30f;
            #pragma unroll
            for (int nt = 0; nt < 8; nt++) {
                mx0 = fmaxf(mx0, fmaxf(sc[nt][0], sc[nt][1]));
                mx1 = fmaxf(mx1, fmaxf(sc[nt][2], sc[nt][3]));
            }
            mx0 = fmaxf(mx0, __shfl_xor_sync(0xffffffffu, mx0, 1));
            mx0 = fmaxf(mx0, __shfl_xor_sync(0xffffffffu, mx0, 2));
            mx1 = fmaxf(mx1, __shfl_xor_sync(0xffffffffu, mx1, 1));
            mx1 = fmaxf(mx1, __shfl_xor_sync(0xffffffffu, mx1, 2));
            float mn0 = fmaxf(m0r, mx0), mn1 = fmaxf(m1r, mx1);
            float a0 = __expf(m0r - mn0), a1 = __expf(m1r - mn1);
            float sum0 = 0.f, sum1 = 0.f;
            #pragma unroll
            for (int nt = 0; nt < 8; nt++) {
                sc[nt][0] = __expf(sc[nt][0] - mn0);
                sc[nt][1] = __expf(sc[nt][1] - mn0);
                sc[nt][2] = __expf(sc[nt][2] - mn1);
                sc[nt][3] = __expf(sc[nt][3] - mn1);
                sum0 += sc[nt][0] + sc[nt][1];
                sum1 += sc[nt][2] + sc[nt][3];
            }
            sum0 += __shfl_xor_sync(0xffffffffu, sum0, 1);
            sum0 += __shfl_xor_sync(0xffffffffu, sum0, 2);
            sum1 += __shfl_xor_sync(0xffffffffu, sum1, 1);
            sum1 += __shfl_xor_sync(0xffffffffu, sum1, 2);
            l0r = l0r * a0 + sum0;
            l1r = l1r * a1 + sum1;
            m0r = mn0; m1r = mn1;
            #pragma unroll
            for (int nt = 0; nt < 8; nt++) {
                o[nt][0] *= a0; o[nt][1] *= a0;
                o[nt][2] *= a1; o[nt][3] *= a1;
            }

            // ---- O += P @ V (P in A-fragment layout == accumulator layout) ----
            #pragma unroll
            for (int kh2 = 0; kh2 < 4; kh2++) {
                const int n0t = 2 * kh2, n1t = 2 * kh2 + 1;
                uint32_t pah[4], pal[4];
                {
                    __nv_bfloat162 h0 = __floats2bfloat162_rn(sc[n0t][0], sc[n0t][1]);
                    __nv_bfloat162 h1 = __floats2bfloat162_rn(sc[n0t][2], sc[n0t][3]);
                    __nv_bfloat162 h2 = __floats2bfloat162_rn(sc[n1t][0], sc[n1t][1]);
                    __nv_bfloat162 h3 = __floats2bfloat162_rn(sc[n1t][2], sc[n1t][3]);
                    pah[0] = b2u(h0); pah[1] = b2u(h1); pah[2] = b2u(h2); pah[3] = b2u(h3);
                    __nv_bfloat162 e0 = __floats2bfloat162_rn(
                        sc[n0t][0] - __bfloat162float(h0.x), sc[n0t][1] - __bfloat162float(h0.y));
                    __nv_bfloat162 e1 = __floats2bfloat162_rn(
                        sc[n0t][2] - __bfloat162float(h1.x), sc[n0t][3] - __bfloat162float(h1.y));
                    __nv_bfloat162 e2 = __floats2bfloat162_rn(
                        sc[n1t][0] - __bfloat162float(h2.x), sc[n1t][1] - __bfloat162float(h2.y));
                    __nv_bfloat162 e3 = __floats2bfloat162_rn(
                        sc[n1t][2] - __bfloat162float(h3.x), sc[n1t][3] - __bfloat162float(h3.y));
                    pal[0] = b2u(e0); pal[1] = b2u(e1); pal[2] = b2u(e2); pal[3] = b2u(e3);
                }
                #pragma unroll
                for (int bt = 0; bt < 4; bt++) {
                    uint32_t roff = (uint32_t)(bt*16 + lr + ((lg & 2) ? 8 : 0)) * APITCH
                                  + (uint32_t)(kh2*16 + ((lg & 1) << 3)) * 2u;
                    uint32_t vfh[4], vfl[4];
                    ldmat4(vfh, VHs + roff);
                    ldmat4(vfl, VLs + roff);
                    mma16816(o[2*bt+0], pah, vfh[0], vfh[1]);
                    mma16816(o[2*bt+0], pal, vfh[0], vfh[1]);
                    mma16816(o[2*bt+0], pah, vfl[0], vfl[1]);
                    mma16816(o[2*bt+1], pah, vfh[2], vfh[3]);
                    mma16816(o[2*bt+1], pal, vfh[2], vfh[3]);
                    mma16816(o[2*bt+1], pah, vfl[2], vfl[3]);
                }
            }
        }
        __syncthreads();
    }

    // ---- normalize + store ----
    const float inv0 = 1.f / l0r, inv1 = 1.f / l1r;
    const int row0 = q0 + mw + qr, row1 = row0 + 8;
    float* c0 = ctx + (size_t)(b*TSEQ + row0) * DMODEL + h*64;
    float* c1 = ctx + (size_t)(b*TSEQ + row1) * DMODEL + h*64;
    #pragma unroll
    for (int nt = 0; nt < 8; nt++) {
        int col = nt*8 + qc;
        float2 u0, u1;
        u0.x = o[nt][0] * inv0; u0.y = o[nt][1] * inv0;
        u1.x = o[nt][2] * inv1; u1.y = o[nt][3] * inv1;
        *reinterpret_cast<float2*>(c0 + col) = u0;
        *reinterpret_cast<float2*>(c1 + col) = u1;
    }
}

// ---------------- launch ------------------------------------------------------
extern "C" void kernel_launch(void* const* d_in, const int* in_sizes, int n_in,
                              void* d_out, int out_size)
{
    (void)in_sizes; (void)n_in; (void)out_size;
    const float* X     = (const float*)d_in[0];
    const float* Wqkv  = (const float*)d_in[1];
    const float* bqkv  = (const float*)d_in[2];
    const float* Wo    = (const float*)d_in[3];
    const float* bo    = (const float*)d_in[4];
    const float* W1    = (const float*)d_in[5];
    const float* b1    = (const float*)d_in[6];
    const float* W2    = (const float*)d_in[7];
    const float* b2    = (const float*)d_in[8];
    const float* ln1g  = (const float*)d_in[9];
    const float* ln1b  = (const float*)d_in[10];
    const float* ln2g  = (const float*)d_in[11];
    const float* ln2b  = (const float*)d_in[12];
    float* out = (float*)d_out;

    float *xn, *qkv, *ctx, *x1, *xn2, *hbuf;
    cudaGetSymbolAddress((void**)&xn,   g_xn);
    cudaGetSymbolAddress((void**)&qkv,  g_qkv);
    cudaGetSymbolAddress((void**)&ctx,  g_ctx);
    cudaGetSymbolAddress((void**)&x1,   g_x1);
    cudaGetSymbolAddress((void**)&xn2,  g_xn2);
    cudaGetSymbolAddress((void**)&hbuf, g_h);

    __nv_bfloat16 *wqkv_hi, *wqkv_lo, *wo_hi, *wo_lo, *w1_hi, *w1_lo, *w2_hi, *w2_lo;
    __nv_bfloat16 *qkh, *qkl, *vth, *vtl;
    cudaGetSymbolAddress((void**)&wqkv_hi, g_wqkv_hi);
    cudaGetSymbolAddress((void**)&wqkv_lo, g_wqkv_lo);
    cudaGetSymbolAddress((void**)&wo_hi,   g_wo_hi);
    cudaGetSymbolAddress((void**)&wo_lo,   g_wo_lo);
    cudaGetSymbolAddress((void**)&w1_hi,   g_w1_hi);
    cudaGetSymbolAddress((void**)&w1_lo,   g_w1_lo);
    cudaGetSymbolAddress((void**)&w2_hi,   g_w2_hi);
    cudaGetSymbolAddress((void**)&w2_lo,   g_w2_lo);
    cudaGetSymbolAddress((void**)&qkh,     g_qkh);
    cudaGetSymbolAddress((void**)&qkl,     g_qkl);
    cudaGetSymbolAddress((void**)&vth,     g_vth);
    cudaGetSymbolAddress((void**)&vtl,     g_vtl);

    cudaFuncSetAttribute(gemm_mma<false,false>, cudaFuncAttributeMaxDynamicSharedMemorySize, SMEM_TOT);
    cudaFuncSetAttribute(gemm_mma<false,true>,  cudaFuncAttributeMaxDynamicSharedMemorySize, SMEM_TOT);
    cudaFuncSetAttribute(gemm_mma<true,false>,  cudaFuncAttributeMaxDynamicSharedMemorySize, SMEM_TOT);
    cudaFuncSetAttribute(flash_mma,             cudaFuncAttributeMaxDynamicSharedMemorySize, ASMEM);

    // weight transpose + split
    wconv<<<dim3(QKVROW/32, DMODEL/32), 256>>>(Wqkv, wqkv_hi, wqkv_lo, DMODEL, QKVROW);
    wconv<<<dim3(DMODEL/32, DMODEL/32), 256>>>(Wo,   wo_hi,   wo_lo,   DMODEL, DMODEL);
    wconv<<<dim3(DFF/32,    DMODEL/32), 256>>>(W1,   w1_hi,   w1_lo,   DMODEL, DFF);
    wconv<<<dim3(DMODEL/32, DFF/32),    256>>>(W2,   w2_hi,   w2_lo,   DFF,    DMODEL);

    // 1. LN1
    ln_kernel<<<NTOK, 256>>>(X, ln1g, ln1b, xn);
    // 2. QKV = LN1(X) @ Wqkv + bqkv
    gemm_mma<false,false><<<dim3(QKVROW/128, NTOK/128), 256, SMEM_TOT>>>(
        xn, wqkv_hi, wqkv_lo, bqkv, nullptr, qkv, QKVROW, DMODEL);
    // 3a. convert Q/K (Q prescaled) + transpose-convert V
    qkconv<<<(NTOK*2048/4)/256, 256>>>(qkv, qkh, qkl);
    vtconv<<<dim3(TSEQ/32, DKEY/32, BATCH*NHEADS), 256>>>(qkv, vth, vtl);
    // 3b. MMA flash attention
    flash_mma<<<dim3(TSEQ/128, BATCH*NHEADS), 256, ASMEM>>>(qkh, qkl, vth, vtl, ctx);
    // 4. x1 = ctx @ Wo + bo + X
    gemm_mma<false,true><<<dim3(DMODEL/128, NTOK/128), 256, SMEM_TOT>>>(
        ctx, wo_hi, wo_lo, bo, X, x1, DMODEL, DMODEL);
    // 5. LN2
    ln_kernel<<<NTOK, 256>>>(x1, ln2g, ln2b, xn2);
    // 6. h = relu(xn2 @ W1 + b1)
    gemm_mma<true,false><<<dim3(DFF/128, NTOK/128), 256, SMEM_TOT>>>(
        xn2, w1_hi, w1_lo, b1, nullptr, hbuf, DFF, DMODEL);
    // 7. out = h @ W2 + b2 + x1
    gemm_mma<false,true><<<dim3(DMODEL/128, NTOK/128), 256, SMEM_TOT>>>(
        hbuf, w2_hi, w2_lo, b2, x1, out, DMODEL, DFF);
}

// round 6
// speedup vs baseline: 3.6353x; 1.1076x over previous
#include <cuda_runtime.h>
#include <cuda_bf16.h>
#include <cstdint>
#include <cstddef>

// Problem constants
#define BATCH   2
#define TSEQ    2048
#define DMODEL  1024
#define NHEADS  16
#define DKEY    64
#define DFF     4096
#define NTOK    (BATCH*TSEQ)          // 4096
#define QKVROW  (3*NHEADS*DKEY)       // 3072

// ---------------- scratch ----------------------------------------------------
__device__ float g_qkv [(size_t)NTOK*QKVROW];
__device__ float g_x1  [(size_t)NTOK*DMODEL];

// pre-split bf16 activations
__device__ __nv_bfloat16 g_xnh [(size_t)NTOK*DMODEL];
__device__ __nv_bfloat16 g_xnl [(size_t)NTOK*DMODEL];
__device__ __nv_bfloat16 g_xn2h[(size_t)NTOK*DMODEL];
__device__ __nv_bfloat16 g_xn2l[(size_t)NTOK*DMODEL];
__device__ __nv_bfloat16 g_ctxh[(size_t)NTOK*DMODEL];
__device__ __nv_bfloat16 g_ctxl[(size_t)NTOK*DMODEL];
__device__ __nv_bfloat16 g_hh  [(size_t)NTOK*DFF];
__device__ __nv_bfloat16 g_hl  [(size_t)NTOK*DFF];

// transposed bf16 hi/lo weights  [N, K] K-major
__device__ __nv_bfloat16 g_wqkv_hi[(size_t)QKVROW*DMODEL];
__device__ __nv_bfloat16 g_wqkv_lo[(size_t)QKVROW*DMODEL];
__device__ __nv_bfloat16 g_wo_hi  [(size_t)DMODEL*DMODEL];
__device__ __nv_bfloat16 g_wo_lo  [(size_t)DMODEL*DMODEL];
__device__ __nv_bfloat16 g_w1_hi  [(size_t)DFF*DMODEL];
__device__ __nv_bfloat16 g_w1_lo  [(size_t)DFF*DMODEL];
__device__ __nv_bfloat16 g_w2_hi  [(size_t)DMODEL*DFF];
__device__ __nv_bfloat16 g_w2_lo  [(size_t)DMODEL*DFF];

// attention bf16 operands
__device__ __nv_bfloat16 g_qkh[(size_t)NTOK*2048];
__device__ __nv_bfloat16 g_qkl[(size_t)NTOK*2048];
__device__ __nv_bfloat16 g_vth[(size_t)BATCH*NHEADS*DKEY*TSEQ];
__device__ __nv_bfloat16 g_vtl[(size_t)BATCH*NHEADS*DKEY*TSEQ];

// ---------------- helpers ----------------------------------------------------
__device__ __forceinline__ uint32_t smem_u32(const void* p) {
    uint32_t a;
    asm("{ .reg .u64 t; cvta.to.shared.u64 t, %1; cvt.u32.u64 %0, t; }"
        : "=r"(a) : "l"(p));
    return a;
}
#define CP_ASYNC16(dst, src) \
    asm volatile("cp.async.cg.shared.global [%0], [%1], 16;" :: "r"(dst), "l"(src) : "memory")
#define CP_COMMIT() asm volatile("cp.async.commit_group;" ::: "memory")
#define CP_WAIT0()  asm volatile("cp.async.wait_group 0;"  ::: "memory")
#define CP_WAIT1()  asm volatile("cp.async.wait_group 1;"  ::: "memory")

__device__ __forceinline__ void ldmat4(uint32_t (&r)[4], uint32_t addr) {
    asm volatile("ldmatrix.sync.aligned.m8n8.x4.shared.b16 {%0,%1,%2,%3}, [%4];"
        : "=r"(r[0]), "=r"(r[1]), "=r"(r[2]), "=r"(r[3]) : "r"(addr));
}
__device__ __forceinline__ void mma16816(float (&d)[4], const uint32_t (&a)[4],
                                         const uint32_t b0, const uint32_t b1) {
    asm volatile("mma.sync.aligned.m16n8k16.row.col.f32.bf16.bf16.f32 "
        "{%0,%1,%2,%3}, {%4,%5,%6,%7}, {%8,%9}, {%0,%1,%2,%3};"
        : "+f"(d[0]), "+f"(d[1]), "+f"(d[2]), "+f"(d[3])
        : "r"(a[0]), "r"(a[1]), "r"(a[2]), "r"(a[3]), "r"(b0), "r"(b1));
}
__device__ __forceinline__ uint32_t b2u(__nv_bfloat162 v) {
    union { __nv_bfloat162 h; uint32_t u; } c; c.h = v; return c.u;
}
__device__ __forceinline__ __nv_bfloat162 splitpair(float x, float y,
                                                    __nv_bfloat162& lo) {
    __nv_bfloat16 hx = __float2bfloat16_rn(x);
    __nv_bfloat16 hy = __float2bfloat16_rn(y);
    lo = __floats2bfloat162_rn(x - __bfloat162float(hx), y - __bfloat162float(hy));
    __nv_bfloat162 hi; hi.x = hx; hi.y = hy;
    return hi;
}

// ---------------- LayerNorm with split-bf16 output ---------------------------
__inline__ __device__ float warp_sum(float v) {
    #pragma unroll
    for (int o = 16; o > 0; o >>= 1) v += __shfl_xor_sync(0xffffffffu, v, o);
    return v;
}

__global__ __launch_bounds__(256) void ln_split(
    const float* __restrict__ x, const float* __restrict__ g,
    const float* __restrict__ b,
    __nv_bfloat16* __restrict__ yh, __nv_bfloat16* __restrict__ yl)
{
    const int row = blockIdx.x;
    const int tid = threadIdx.x;
    const float* xr = x + (size_t)row * DMODEL;

    float4 v = reinterpret_cast<const float4*>(xr)[tid];
    float s  = v.x + v.y + v.z + v.w;
    float sq = v.x*v.x + v.y*v.y + v.z*v.z + v.w*v.w;

    __shared__ float sh_s[8], sh_q[8];
    float ws = warp_sum(s), wq = warp_sum(sq);
    int warp = tid >> 5, lane = tid & 31;
    if (lane == 0) { sh_s[warp] = ws; sh_q[warp] = wq; }
    __syncthreads();
    __shared__ float sh_mean, sh_rstd;
    if (tid == 0) {
        float ts = 0.f, tq = 0.f;
        #pragma unroll
        for (int i = 0; i < 8; i++) { ts += sh_s[i]; tq += sh_q[i]; }
        float mean = ts * (1.0f / DMODEL);
        float var  = tq * (1.0f / DMODEL) - mean * mean;
        sh_mean = mean; sh_rstd = rsqrtf(var + 1e-5f);
    }
    __syncthreads();
    float mean = sh_mean, rstd = sh_rstd;

    float4 gv = reinterpret_cast<const float4*>(g)[tid];
    float4 bv = reinterpret_cast<const float4*>(b)[tid];
    float ox = (v.x - mean) * rstd * gv.x + bv.x;
    float oy = (v.y - mean) * rstd * gv.y + bv.y;
    float oz = (v.z - mean) * rstd * gv.z + bv.z;
    float ow = (v.w - mean) * rstd * gv.w + bv.w;

    __nv_bfloat162 l01, l23;
    __nv_bfloat162 h01 = splitpair(ox, oy, l01);
    __nv_bfloat162 h23 = splitpair(oz, ow, l23);
    size_t o = (size_t)row * DMODEL + tid * 4;
    *reinterpret_cast<__nv_bfloat162*>(yh + o)     = h01;
    *reinterpret_cast<__nv_bfloat162*>(yh + o + 2) = h23;
    *reinterpret_cast<__nv_bfloat162*>(yl + o)     = l01;
    *reinterpret_cast<__nv_bfloat162*>(yl + o + 2) = l23;
}

// ---------------- weight transpose + bf16 split: W[K,N] -> hi/lo[N,K] --------
__global__ __launch_bounds__(256) void wconv(
    const float* __restrict__ W, __nv_bfloat16* __restrict__ hi,
    __nv_bfloat16* __restrict__ lo, int K, int N)
{
    __shared__ float t[32][33];
    const int n0 = blockIdx.x * 32, k0 = blockIdx.y * 32;
    const int tx = threadIdx.x & 31, ty = threadIdx.x >> 5;
    #pragma unroll
    for (int j = 0; j < 4; j++)
        t[ty + j*8][tx] = W[(size_t)(k0 + ty + j*8) * N + n0 + tx];
    __syncthreads();
    #pragma unroll
    for (int j = 0; j < 4; j++) {
        int n = ty + j*8;
        float x = t[tx][n];
        __nv_bfloat16 h = __float2bfloat16_rn(x);
        float l = x - __bfloat162float(h);
        hi[(size_t)(n0 + n) * K + k0 + tx] = h;
        lo[(size_t)(n0 + n) * K + k0 + tx] = __float2bfloat16_rn(l);
    }
}

// ---------------- QK convert (Q scaled by 1/8) -------------------------------
__global__ __launch_bounds__(256) void qkconv(
    const float* __restrict__ qkv,
    __nv_bfloat16* __restrict__ hi, __nv_bfloat16* __restrict__ lo)
{
    const int idx = blockIdx.x * 256 + threadIdx.x;
    const int tok = idx >> 9;
    const int c4  = (idx & 511) << 2;
    const float sc = (c4 < 1024) ? 0.125f : 1.0f;
    float4 v = *reinterpret_cast<const float4*>(qkv + (size_t)tok * QKVROW + c4);
    v.x *= sc; v.y *= sc; v.z *= sc; v.w *= sc;
    __nv_bfloat162 l01, l23;
    __nv_bfloat162 h01 = splitpair(v.x, v.y, l01);
    __nv_bfloat162 h23 = splitpair(v.z, v.w, l23);
    size_t o = (size_t)tok * 2048 + c4;
    *reinterpret_cast<__nv_bfloat162*>(hi + o)     = h01;
    *reinterpret_cast<__nv_bfloat162*>(hi + o + 2) = h23;
    *reinterpret_cast<__nv_bfloat162*>(lo + o)     = l01;
    *reinterpret_cast<__nv_bfloat162*>(lo + o + 2) = l23;
}

// ---------------- V transpose-convert ----------------------------------------
__global__ __launch_bounds__(256) void vtconv(
    const float* __restrict__ qkv,
    __nv_bfloat16* __restrict__ vh, __nv_bfloat16* __restrict__ vl)
{
    __shared__ float t[32][33];
    const int t0 = blockIdx.x * 32, d0 = blockIdx.y * 32;
    const int bh = blockIdx.z, b = bh >> 4, h = bh & 15;
    const int tx = threadIdx.x & 31, ty = threadIdx.x >> 5;
    #pragma unroll
    for (int j = 0; j < 4; j++) {
        int tt = ty + j*8;
        t[tt][tx] = qkv[(size_t)(b*TSEQ + t0 + tt) * QKVROW + 2048 + h*64 + d0 + tx];
    }
    __syncthreads();
    #pragma unroll
    for (int j = 0; j < 4; j++) {
        int d = ty + j*8;
        float x = t[tx][d];
        __nv_bfloat16 hh = __float2bfloat16_rn(x);
        float ll = x - __bfloat162float(hh);
        size_t o = ((size_t)bh * 64 + d0 + d) * TSEQ + t0 + tx;
        vh[o] = hh;
        vl[o] = __float2bfloat16_rn(ll);
    }
}

// ---------------- pure-bf16 HMMA GEMM ---------------------------------------
// C[M,N](+res,+relu) = (Ahi+Alo)[M,K] @ (Bhi+Blo)[N,K]^T  (3-product split)
// CTA 128x128, 8 warps (32x64), K_chunk=64, 2-stage cp.async pipeline.
// Pitch 144B: ldmatrix row banks 4r mod 32 distinct.
#define GPITCH 144u
#define GTILE  (128u * GPITCH)     // 18432
#define GSTG   (4u * GTILE)        // 73728: Ah, Al, Bh, Bl
#define GSMEM  (2u * GSTG)         // 147456

template<bool RELU, bool RES, bool OSPLIT>
__global__ __launch_bounds__(256, 1) void gemm_b16(
    const __nv_bfloat16* __restrict__ Ahi, const __nv_bfloat16* __restrict__ Alo,
    const __nv_bfloat16* __restrict__ Bhi, const __nv_bfloat16* __restrict__ Blo,
    const float* __restrict__ bias, const float* __restrict__ res,
    float* __restrict__ C, __nv_bfloat16* __restrict__ Chi,
    __nv_bfloat16* __restrict__ Clo, int N, int K)
{
    extern __shared__ char sm[];
    const int tid = threadIdx.x, wid = tid >> 5, lane = tid & 31;
    const int m0 = blockIdx.y * 128, n0 = blockIdx.x * 128;
    const uint32_t sb = smem_u32(sm);

    const int mw = (wid & 3) * 32;
    const int nw = (wid >> 2) * 64;
    const int lg = lane >> 3, lr = lane & 7;

    float d[2][8][4];
    #pragma unroll
    for (int mt = 0; mt < 2; mt++)
        #pragma unroll
        for (int nt = 0; nt < 8; nt++)
            #pragma unroll
            for (int i = 0; i < 4; i++) d[mt][nt][i] = 0.f;

    const int nkt = K >> 6;    // K_chunk = 64

    auto loadStage = [&](int s, int k0) {
        const uint32_t st = sb + (uint32_t)s * GSTG;
        const __nv_bfloat16* base0 = Ahi + (size_t)m0 * K + k0;
        const __nv_bfloat16* base1 = Alo + (size_t)m0 * K + k0;
        const __nv_bfloat16* base2 = Bhi + (size_t)n0 * K + k0;
        const __nv_bfloat16* base3 = Blo + (size_t)n0 * K + k0;
        #pragma unroll
        for (int i = 0; i < 4; i++) {          // 128 rows x 8 segs / 256 thr
            int lin = i * 256 + tid;
            int row = lin >> 3, seg = lin & 7;
            uint32_t off = (uint32_t)row * GPITCH + (uint32_t)seg * 16u;
            const size_t go = (size_t)row * K + seg * 8;
            CP_ASYNC16(st + off,              (const char*)(base0 + go));
            CP_ASYNC16(st + GTILE + off,      (const char*)(base1 + go));
            CP_ASYNC16(st + 2u*GTILE + off,   (const char*)(base2 + go));
            CP_ASYNC16(st + 3u*GTILE + off,   (const char*)(base3 + go));
        }
        CP_COMMIT();
    };

    auto mmaStage = [&](int s) {
        const uint32_t AhS = sb + (uint32_t)s * GSTG;
        const uint32_t AlS = AhS + GTILE;
        const uint32_t BhS = AhS + 2u * GTILE;
        const uint32_t BlS = AhS + 3u * GTILE;
        #pragma unroll
        for (int kh = 0; kh < 4; kh++) {
            uint32_t ah[2][4], al[2][4];
            #pragma unroll
            for (int mt = 0; mt < 2; mt++) {
                uint32_t roff = (uint32_t)(mw + mt*16 + lr + ((lg & 1) << 3)) * GPITCH
                              + (uint32_t)(kh*16 + ((lg >> 1) << 3)) * 2u;
                ldmat4(ah[mt], AhS + roff);
                ldmat4(al[mt], AlS + roff);
            }
            #pragma unroll
            for (int bt = 0; bt < 4; bt++) {
                uint32_t roff = (uint32_t)(nw + bt*16 + lr + ((lg & 2) ? 8 : 0)) * GPITCH
                              + (uint32_t)(kh*16 + ((lg & 1) << 3)) * 2u;
                uint32_t bh[4], bl[4];
                ldmat4(bh, BhS + roff);
                ldmat4(bl, BlS + roff);
                #pragma unroll
                for (int mt = 0; mt < 2; mt++) {
                    mma16816(d[mt][2*bt+0], ah[mt], bh[0], bh[1]);
                    mma16816(d[mt][2*bt+0], ah[mt], bl[0], bl[1]);
                    mma16816(d[mt][2*bt+0], al[mt], bh[0], bh[1]);
                    mma16816(d[mt][2*bt+1], ah[mt], bh[2], bh[3]);
                    mma16816(d[mt][2*bt+1], ah[mt], bl[2], bl[3]);
                    mma16816(d[mt][2*bt+1], al[mt], bh[2], bh[3]);
                }
            }
        }
    };

    loadStage(0, 0);
    for (int kt = 0; kt < nkt; kt++) {
        const int s = kt & 1;
        const bool more = (kt + 1) < nkt;
        if (more) loadStage(s ^ 1, (kt + 1) << 6);
        if (more) { CP_WAIT1(); } else { CP_WAIT0(); }
        __syncthreads();
        mmaStage(s);
        __syncthreads();
    }

    // ---- epilogue ----
    const int qr = lane >> 2;
    const int qc = (lane & 3) * 2;
    #pragma unroll
    for (int mt = 0; mt < 2; mt++) {
        const int r0 = m0 + mw + mt * 16 + qr;
        const int r1 = r0 + 8;
        #pragma unroll
        for (int nt = 0; nt < 8; nt++) {
            const int c = n0 + nw + nt * 8 + qc;
            float2 bb = *reinterpret_cast<const float2*>(bias + c);
            float2 o0, o1;
            o0.x = d[mt][nt][0] + bb.x; o0.y = d[mt][nt][1] + bb.y;
            o1.x = d[mt][nt][2] + bb.x; o1.y = d[mt][nt][3] + bb.y;
            if (RELU) {
                o0.x = fmaxf(o0.x, 0.f); o0.y = fmaxf(o0.y, 0.f);
                o1.x = fmaxf(o1.x, 0.f); o1.y = fmaxf(o1.y, 0.f);
            }
            if (RES) {
                float2 u0 = *reinterpret_cast<const float2*>(res + (size_t)r0 * N + c);
                float2 u1 = *reinterpret_cast<const float2*>(res + (size_t)r1 * N + c);
                o0.x += u0.x; o0.y += u0.y; o1.x += u1.x; o1.y += u1.y;
            }
            if (OSPLIT) {
                __nv_bfloat162 l0, l1;
                __nv_bfloat162 h0 = splitpair(o0.x, o0.y, l0);
                __nv_bfloat162 h1 = splitpair(o1.x, o1.y, l1);
                *reinterpret_cast<__nv_bfloat162*>(Chi + (size_t)r0 * N + c) = h0;
                *reinterpret_cast<__nv_bfloat162*>(Chi + (size_t)r1 * N + c) = h1;
                *reinterpret_cast<__nv_bfloat162*>(Clo + (size_t)r0 * N + c) = l0;
                *reinterpret_cast<__nv_bfloat162*>(Clo + (size_t)r1 * N + c) = l1;
            } else {
                *reinterpret_cast<float2*>(C + (size_t)r0 * N + c) = o0;
                *reinterpret_cast<float2*>(C + (size_t)r1 * N + c) = o1;
            }
        }
    }
}

// ---------------- MMA flash attention (causal) -------------------------------
#define APITCH 144u
#define AQ_B   (128u * APITCH)
#define AKV_B  (64u * APITCH)
#define ASTG_B (4u * AKV_B)
#define ASMEM  (2u * AQ_B + 2u * ASTG_B)   // 110592

__global__ __launch_bounds__(256, 1) void flash_mma(
    const __nv_bfloat16* __restrict__ qkh, const __nv_bfloat16* __restrict__ qkl,
    const __nv_bfloat16* __restrict__ vth, const __nv_bfloat16* __restrict__ vtl,
    __nv_bfloat16* __restrict__ ctxh, __nv_bfloat16* __restrict__ ctxl)
{
    extern __shared__ char sm[];
    const int tid = threadIdx.x, wid = tid >> 5, lane = tid & 31;
    const int q0 = (15 - blockIdx.x) * 128;
    const int bh = blockIdx.y, b = bh >> 4, h = bh & 15;
    const int mw = wid * 16;
    const int lg = lane >> 3, lr = lane & 7;
    const int qr = lane >> 2, qc = (lane & 3) * 2;

    const uint32_t sb = smem_u32(sm);
    const uint32_t QH = sb, QL = sb + AQ_B;
    const uint32_t ST = sb + 2u * AQ_B;

    {
        const __nv_bfloat16* qb_h = qkh + (size_t)(b*TSEQ + q0) * 2048 + h*64;
        const __nv_bfloat16* qb_l = qkl + (size_t)(b*TSEQ + q0) * 2048 + h*64;
        #pragma unroll
        for (int i = 0; i < 4; i++) {
            int lin = i * 256 + tid;
            int row = lin >> 3, seg = lin & 7;
            uint32_t off = (uint32_t)row * APITCH + (uint32_t)seg * 16u;
            CP_ASYNC16(QH + off, (const char*)(qb_h + (size_t)row * 2048) + seg * 16);
            CP_ASYNC16(QL + off, (const char*)(qb_l + (size_t)row * 2048) + seg * 16);
        }
        CP_COMMIT();
    }

    auto loadKV = [&](int s, int key0) {
        const uint32_t KHs = ST + (uint32_t)s * ASTG_B;
        const uint32_t KLs = KHs + AKV_B;
        const uint32_t VHs = KHs + 2u * AKV_B;
        const uint32_t VLs = KHs + 3u * AKV_B;
        const __nv_bfloat16* kb_h = qkh + (size_t)(b*TSEQ + key0) * 2048 + 1024 + h*64;
        const __nv_bfloat16* kb_l = qkl + (size_t)(b*TSEQ + key0) * 2048 + 1024 + h*64;
        const __nv_bfloat16* vb_h = vth + (size_t)bh * 64 * TSEQ + key0;
        const __nv_bfloat16* vb_l = vtl + (size_t)bh * 64 * TSEQ + key0;
        #pragma unroll
        for (int i = 0; i < 2; i++) {
            int lin = i * 256 + tid;
            int row = lin >> 3, seg = lin & 7;
            uint32_t off = (uint32_t)row * APITCH + (uint32_t)seg * 16u;
            CP_ASYNC16(KHs + off, (const char*)(kb_h + (size_t)row * 2048) + seg * 16);
            CP_ASYNC16(KLs + off, (const char*)(kb_l + (size_t)row * 2048) + seg * 16);
            CP_ASYNC16(VHs + off, (const char*)(vb_h + (size_t)row * TSEQ) + seg * 16);
            CP_ASYNC16(VLs + off, (const char*)(vb_l + (size_t)row * TSEQ) + seg * 16);
        }
        CP_COMMIT();
    };

    const int nkt = q0 / 64 + 2;
    loadKV(0, 0);
    CP_WAIT0();
    __syncthreads();

    uint32_t qfh[4][4], qfl[4][4];
    #pragma unroll
    for (int kh = 0; kh < 4; kh++) {
        uint32_t roff = (uint32_t)(mw + lr + ((lg & 1) << 3)) * APITCH
                      + (uint32_t)(kh*16 + ((lg >> 1) << 3)) * 2u;
        ldmat4(qfh[kh], QH + roff);
        ldmat4(qfl[kh], QL + roff);
    }

    float o[8][4];
    #pragma unroll
    for (int nt = 0; nt < 8; nt++)
        #pragma unroll
        for (int i = 0; i < 4; i++) o[nt][i] = 0.f;
    float m0r = -1e30f, m1r = -1e30f, l0r = 0.f, l1r = 0.f;

    for (int kt = 0; kt < nkt; kt++) {
        const int s = kt & 1;
        const int key0 = kt * 64;
        const bool more = (kt + 1) < nkt;
        if (more) loadKV(s ^ 1, key0 + 64);
        if (more) { CP_WAIT1(); } else { CP_WAIT0(); }
        __syncthreads();

        if (key0 <= q0 + mw + 15) {
            const uint32_t KHs = ST + (uint32_t)s * ASTG_B;
            const uint32_t KLs = KHs + AKV_B;
            const uint32_t VHs = KHs + 2u * AKV_B;
            const uint32_t VLs = KHs + 3u * AKV_B;

            float sc[8][4];
            #pragma unroll
            for (int nt = 0; nt < 8; nt++)
                #pragma unroll
                for (int i = 0; i < 4; i++) sc[nt][i] = 0.f;

            #pragma unroll
            for (int kh = 0; kh < 4; kh++) {
                #pragma unroll
                for (int bt = 0; bt < 4; bt++) {
                    uint32_t roff = (uint32_t)(bt*16 + lr + ((lg & 2) ? 8 : 0)) * APITCH
                                  + (uint32_t)(kh*16 + ((lg & 1) << 3)) * 2u;
                    uint32_t kfh[4], kfl[4];
                    ldmat4(kfh, KHs + roff);
                    ldmat4(kfl, KLs + roff);
                    mma16816(sc[2*bt+0], qfh[kh], kfh[0], kfh[1]);
                    mma16816(sc[2*bt+0], qfh[kh], kfl[0], kfl[1]);
                    mma16816(sc[2*bt+0], qfl[kh], kfh[0], kfh[1]);
                    mma16816(sc[2*bt+1], qfh[kh], kfh[2], kfh[3]);
                    mma16816(sc[2*bt+1], qfh[kh], kfl[2], kfl[3]);
                    mma16816(sc[2*bt+1], qfl[kh], kfh[2], kfh[3]);
                }
            }

            const int row0 = q0 + mw + qr, row1 = row0 + 8;
            if (key0 + 63 > q0 + mw) {
                #pragma unroll
                for (int nt = 0; nt < 8; nt++) {
                    int c0 = key0 + nt*8 + qc;
                    if (c0     > row0) sc[nt][0] = -1e30f;
                    if (c0 + 1 > row0) sc[nt][1] = -1e30f;
                    if (c0     > row1) sc[nt][2] = -1e30f;
                    if (c0 + 1 > row1) sc[nt][3] = -1e30f;
                }
            }

            float mx0 = -1e30f, mx1 = -1e30f;
            #pragma unroll
            for (int nt = 0; nt < 8; nt++) {
                mx0 = fmaxf(mx0, fmaxf(sc[nt][0], sc[nt][1]));
                mx1 = fmaxf(mx1, fmaxf(sc[nt][2], sc[nt][3]));
            }
            mx0 = fmaxf(mx0, __shfl_xor_sync(0xffffffffu, mx0, 1));
            mx0 = fmaxf(mx0, __shfl_xor_sync(0xffffffffu, mx0, 2));
            mx1 = fmaxf(mx1, __shfl_xor_sync(0xffffffffu, mx1, 1));
            mx1 = fmaxf(mx1, __shfl_xor_sync(0xffffffffu, mx1, 2));
            float mn0 = fmaxf(m0r, mx0), mn1 = fmaxf(m1r, mx1);
            float a0 = __expf(m0r - mn0), a1 = __expf(m1r - mn1);
            float sum0 = 0.f, sum1 = 0.f;
            #pragma unroll
            for (int nt = 0; nt < 8; nt++) {
                sc[nt][0] = __expf(sc[nt][0] - mn0);
                sc[nt][1] = __expf(sc[nt][1] - mn0);
                sc[nt][2] = __expf(sc[nt][2] - mn1);
                sc[nt][3] = __expf(sc[nt][3] - mn1);
                sum0 += sc[nt][0] + sc[nt][1];
                sum1 += sc[nt][2] + sc[nt][3];
            }
            sum0 += __shfl_xor_sync(0xffffffffu, sum0, 1);
            sum0 += __shfl_xor_sync(0xffffffffu, sum0, 2);
            sum1 += __shfl_xor_sync(0xffffffffu, sum1, 1);
            sum1 += __shfl_xor_sync(0xffffffffu, sum1, 2);
            l0r = l0r * a0 + sum0;
            l1r = l1r * a1 + sum1;
            m0r = mn0; m1r = mn1;
            #pragma unroll
            for (int nt = 0; nt < 8; nt++) {
                o[nt][0] *= a0; o[nt][1] *= a0;
                o[nt][2] *= a1; o[nt][3] *= a1;
            }

            #pragma unroll
            for (int kh2 = 0; kh2 < 4; kh2++) {
                const int n0t = 2 * kh2, n1t = 2 * kh2 + 1;
                uint32_t pah[4], pal[4];
                {
                    __nv_bfloat162 e0, e1, e2, e3;
                    __nv_bfloat162 h0 = splitpair(sc[n0t][0], sc[n0t][1], e0);
                    __nv_bfloat162 h1 = splitpair(sc[n0t][2], sc[n0t][3], e1);
                    __nv_bfloat162 h2 = splitpair(sc[n1t][0], sc[n1t][1], e2);
                    __nv_bfloat162 h3 = splitpair(sc[n1t][2], sc[n1t][3], e3);
                    pah[0] = b2u(h0); pah[1] = b2u(h1); pah[2] = b2u(h2); pah[3] = b2u(h3);
                    pal[0] = b2u(e0); pal[1] = b2u(e1); pal[2] = b2u(e2); pal[3] = b2u(e3);
                }
                #pragma unroll
                for (int bt = 0; bt < 4; bt++) {
                    uint32_t roff = (uint32_t)(bt*16 + lr + ((lg & 2) ? 8 : 0)) * APITCH
                                  + (uint32_t)(kh2*16 + ((lg & 1) << 3)) * 2u;
                    uint32_t vfh[4], vfl[4];
                    ldmat4(vfh, VHs + roff);
                    ldmat4(vfl, VLs + roff);
                    mma16816(o[2*bt+0], pah, vfh[0], vfh[1]);
                    mma16816(o[2*bt+0], pal, vfh[0], vfh[1]);
                    mma16816(o[2*bt+0], pah, vfl[0], vfl[1]);
                    mma16816(o[2*bt+1], pah, vfh[2], vfh[3]);
                    mma16816(o[2*bt+1], pal, vfh[2], vfh[3]);
                    mma16816(o[2*bt+1], pah, vfl[2], vfl[3]);
                }
            }
        }
        __syncthreads();
    }

    // ---- normalize + split-store ----
    const float inv0 = 1.f / l0r, inv1 = 1.f / l1r;
    const int row0 = q0 + mw + qr, row1 = row0 + 8;
    const size_t o0 = (size_t)(b*TSEQ + row0) * DMODEL + h*64;
    const size_t o1 = (size_t)(b*TSEQ + row1) * DMODEL + h*64;
    #pragma unroll
    for (int nt = 0; nt < 8; nt++) {
        int col = nt*8 + qc;
        __nv_bfloat162 l0, l1;
        __nv_bfloat162 h0 = splitpair(o[nt][0] * inv0, o[nt][1] * inv0, l0);
        __nv_bfloat162 h1 = splitpair(o[nt][2] * inv1, o[nt][3] * inv1, l1);
        *reinterpret_cast<__nv_bfloat162*>(ctxh + o0 + col) = h0;
        *reinterpret_cast<__nv_bfloat162*>(ctxh + o1 + col) = h1;
        *reinterpret_cast<__nv_bfloat162*>(ctxl + o0 + col) = l0;
        *reinterpret_cast<__nv_bfloat162*>(ctxl + o1 + col) = l1;
    }
}

// ---------------- launch ------------------------------------------------------
extern "C" void kernel_launch(void* const* d_in, const int* in_sizes, int n_in,
                              void* d_out, int out_size)
{
    (void)in_sizes; (void)n_in; (void)out_size;
    const float* X     = (const float*)d_in[0];
    const float* Wqkv  = (const float*)d_in[1];
    const float* bqkv  = (const float*)d_in[2];
    const float* Wo    = (const float*)d_in[3];
    const float* bo    = (const float*)d_in[4];
    const float* W1    = (const float*)d_in[5];
    const float* b1    = (const float*)d_in[6];
    const float* W2    = (const float*)d_in[7];
    const float* b2    = (const float*)d_in[8];
    const float* ln1g  = (const float*)d_in[9];
    const float* ln1b  = (const float*)d_in[10];
    const float* ln2g  = (const float*)d_in[11];
    const float* ln2b  = (const float*)d_in[12];
    float* out = (float*)d_out;

    float *qkv, *x1;
    cudaGetSymbolAddress((void**)&qkv,  g_qkv);
    cudaGetSymbolAddress((void**)&x1,   g_x1);

    __nv_bfloat16 *xnh, *xnl, *xn2h, *xn2l, *ctxh, *ctxl, *hh, *hl;
    cudaGetSymbolAddress((void**)&xnh,  g_xnh);
    cudaGetSymbolAddress((void**)&xnl,  g_xnl);
    cudaGetSymbolAddress((void**)&xn2h, g_xn2h);
    cudaGetSymbolAddress((void**)&xn2l, g_xn2l);
    cudaGetSymbolAddress((void**)&ctxh, g_ctxh);
    cudaGetSymbolAddress((void**)&ctxl, g_ctxl);
    cudaGetSymbolAddress((void**)&hh,   g_hh);
    cudaGetSymbolAddress((void**)&hl,   g_hl);

    __nv_bfloat16 *wqkv_hi, *wqkv_lo, *wo_hi, *wo_lo, *w1_hi, *w1_lo, *w2_hi, *w2_lo;
    __nv_bfloat16 *qkh, *qkl, *vth, *vtl;
    cudaGetSymbolAddress((void**)&wqkv_hi, g_wqkv_hi);
    cudaGetSymbolAddress((void**)&wqkv_lo, g_wqkv_lo);
    cudaGetSymbolAddress((void**)&wo_hi,   g_wo_hi);
    cudaGetSymbolAddress((void**)&wo_lo,   g_wo_lo);
    cudaGetSymbolAddress((void**)&w1_hi,   g_w1_hi);
    cudaGetSymbolAddress((void**)&w1_lo,   g_w1_lo);
    cudaGetSymbolAddress((void**)&w2_hi,   g_w2_hi);
    cudaGetSymbolAddress((void**)&w2_lo,   g_w2_lo);
    cudaGetSymbolAddress((void**)&qkh,     g_qkh);
    cudaGetSymbolAddress((void**)&qkl,     g_qkl);
    cudaGetSymbolAddress((void**)&vth,     g_vth);
    cudaGetSymbolAddress((void**)&vtl,     g_vtl);

    cudaFuncSetAttribute(gemm_b16<false,false,false>, cudaFuncAttributeMaxDynamicSharedMemorySize, GSMEM);
    cudaFuncSetAttribute(gemm_b16<false,true,false>,  cudaFuncAttributeMaxDynamicSharedMemorySize, GSMEM);
    cudaFuncSetAttribute(gemm_b16<true,false,true>,   cudaFuncAttributeMaxDynamicSharedMemorySize, GSMEM);
    cudaFuncSetAttribute(flash_mma,                   cudaFuncAttributeMaxDynamicSharedMemorySize, ASMEM);

    // weight transpose + split
    wconv<<<dim3(QKVROW/32, DMODEL/32), 256>>>(Wqkv, wqkv_hi, wqkv_lo, DMODEL, QKVROW);
    wconv<<<dim3(DMODEL/32, DMODEL/32), 256>>>(Wo,   wo_hi,   wo_lo,   DMODEL, DMODEL);
    wconv<<<dim3(DFF/32,    DMODEL/32), 256>>>(W1,   w1_hi,   w1_lo,   DMODEL, DFF);
    wconv<<<dim3(DMODEL/32, DFF/32),    256>>>(W2,   w2_hi,   w2_lo,   DFF,    DMODEL);

    // 1. LN1 -> split bf16
    ln_split<<<NTOK, 256>>>(X, ln1g, ln1b, xnh, xnl);
    // 2. QKV = LN1(X) @ Wqkv + bqkv  (fp32 out)
    gemm_b16<false,false,false><<<dim3(QKVROW/128, NTOK/128), 256, GSMEM>>>(
        xnh, xnl, wqkv_hi, wqkv_lo, bqkv, nullptr, qkv, nullptr, nullptr, QKVROW, DMODEL);
    // 3a. convert Q/K + transpose-convert V
    qkconv<<<(NTOK*2048/4)/256, 256>>>(qkv, qkh, qkl);
    vtconv<<<dim3(TSEQ/32, DKEY/32, BATCH*NHEADS), 256>>>(qkv, vth, vtl);
    // 3b. MMA flash attention -> split bf16 ctx
    flash_mma<<<dim3(TSEQ/128, BATCH*NHEADS), 256, ASMEM>>>(qkh, qkl, vth, vtl, ctxh, ctxl);
    // 4. x1 = ctx @ Wo + bo + X  (fp32 out)
    gemm_b16<false,true,false><<<dim3(DMODEL/128, NTOK/128), 256, GSMEM>>>(
        ctxh, ctxl, wo_hi, wo_lo, bo, X, x1, nullptr, nullptr, DMODEL, DMODEL);
    // 5. LN2 -> split bf16
    ln_split<<<NTOK, 256>>>(x1, ln2g, ln2b, xn2h, xn2l);
    // 6. h = relu(xn2 @ W1 + b1)  (split bf16 out)
    gemm_b16<true,false,true><<<dim3(DFF/128, NTOK/128), 256, GSMEM>>>(
        xn2h, xn2l, w1_hi, w1_lo, b1, nullptr, nullptr, hh, hl, DFF, DMODEL);
    // 7. out = h @ W2 + b2 + x1  (fp32 out)
    gemm_b16<false,true,false><<<dim3(DMODEL/128, NTOK/128), 256, GSMEM>>>(
        hh, hl, w2_hi, w2_lo, b2, x1, out, nullptr, nullptr, DMODEL, DFF);
}

// round 7
// speedup vs baseline: 3.6557x; 1.0056x over previous
#include <cuda_runtime.h>
#include <cuda_bf16.h>
#include <cstdint>
#include <cstddef>

// Problem constants
#define BATCH   2
#define TSEQ    2048
#define DMODEL  1024
#define NHEADS  16
#define DKEY    64
#define DFF     4096
#define NTOK    (BATCH*TSEQ)          // 4096
#define QKVROW  (3*NHEADS*DKEY)       // 3072

// ---------------- scratch ----------------------------------------------------
__device__ float g_x1  [(size_t)NTOK*DMODEL];

// pre-split bf16 activations
__device__ __nv_bfloat16 g_xnh [(size_t)NTOK*DMODEL];
__device__ __nv_bfloat16 g_xnl [(size_t)NTOK*DMODEL];
__device__ __nv_bfloat16 g_xn2h[(size_t)NTOK*DMODEL];
__device__ __nv_bfloat16 g_xn2l[(size_t)NTOK*DMODEL];
__device__ __nv_bfloat16 g_ctxh[(size_t)NTOK*DMODEL];
__device__ __nv_bfloat16 g_ctxl[(size_t)NTOK*DMODEL];
__device__ __nv_bfloat16 g_hh  [(size_t)NTOK*DFF];
__device__ __nv_bfloat16 g_hl  [(size_t)NTOK*DFF];

// qkv split output: [tok][3072] (Q scaled by 1/8 in cols 0..1023)
__device__ __nv_bfloat16 g_qsph[(size_t)NTOK*QKVROW];
__device__ __nv_bfloat16 g_qspl[(size_t)NTOK*QKVROW];

// transposed bf16 hi/lo weights  [N, K] K-major
__device__ __nv_bfloat16 g_wqkv_hi[(size_t)QKVROW*DMODEL];
__device__ __nv_bfloat16 g_wqkv_lo[(size_t)QKVROW*DMODEL];
__device__ __nv_bfloat16 g_wo_hi  [(size_t)DMODEL*DMODEL];
__device__ __nv_bfloat16 g_wo_lo  [(size_t)DMODEL*DMODEL];
__device__ __nv_bfloat16 g_w1_hi  [(size_t)DFF*DMODEL];
__device__ __nv_bfloat16 g_w1_lo  [(size_t)DFF*DMODEL];
__device__ __nv_bfloat16 g_w2_hi  [(size_t)DMODEL*DFF];
__device__ __nv_bfloat16 g_w2_lo  [(size_t)DMODEL*DFF];

// V transposed per (b,h): [bh][d][t]
__device__ __nv_bfloat16 g_vth[(size_t)BATCH*NHEADS*DKEY*TSEQ];
__device__ __nv_bfloat16 g_vtl[(size_t)BATCH*NHEADS*DKEY*TSEQ];

// ---------------- helpers ----------------------------------------------------
__device__ __forceinline__ uint32_t smem_u32(const void* p) {
    uint32_t a;
    asm("{ .reg .u64 t; cvta.to.shared.u64 t, %1; cvt.u32.u64 %0, t; }"
        : "=r"(a) : "l"(p));
    return a;
}
#define CP_ASYNC16(dst, src) \
    asm volatile("cp.async.cg.shared.global [%0], [%1], 16;" :: "r"(dst), "l"(src) : "memory")
#define CP_COMMIT() asm volatile("cp.async.commit_group;" ::: "memory")
#define CP_WAIT0()  asm volatile("cp.async.wait_group 0;"  ::: "memory")
#define CP_WAIT1()  asm volatile("cp.async.wait_group 1;"  ::: "memory")

__device__ __forceinline__ void ldmat4(uint32_t (&r)[4], uint32_t addr) {
    asm volatile("ldmatrix.sync.aligned.m8n8.x4.shared.b16 {%0,%1,%2,%3}, [%4];"
        : "=r"(r[0]), "=r"(r[1]), "=r"(r[2]), "=r"(r[3]) : "r"(addr));
}
__device__ __forceinline__ void mma16816(float (&d)[4], const uint32_t (&a)[4],
                                         const uint32_t b0, const uint32_t b1) {
    asm volatile("mma.sync.aligned.m16n8k16.row.col.f32.bf16.bf16.f32 "
        "{%0,%1,%2,%3}, {%4,%5,%6,%7}, {%8,%9}, {%0,%1,%2,%3};"
        : "+f"(d[0]), "+f"(d[1]), "+f"(d[2]), "+f"(d[3])
        : "r"(a[0]), "r"(a[1]), "r"(a[2]), "r"(a[3]), "r"(b0), "r"(b1));
}
__device__ __forceinline__ uint32_t b2u(__nv_bfloat162 v) {
    union { __nv_bfloat162 h; uint32_t u; } c; c.h = v; return c.u;
}
__device__ __forceinline__ __nv_bfloat162 splitpair(float x, float y,
                                                    __nv_bfloat162& lo) {
    __nv_bfloat16 hx = __float2bfloat16_rn(x);
    __nv_bfloat16 hy = __float2bfloat16_rn(y);
    lo = __floats2bfloat162_rn(x - __bfloat162float(hx), y - __bfloat162float(hy));
    __nv_bfloat162 hi; hi.x = hx; hi.y = hy;
    return hi;
}

// ---------------- LayerNorm with split-bf16 output ---------------------------
__inline__ __device__ float warp_sum(float v) {
    #pragma unroll
    for (int o = 16; o > 0; o >>= 1) v += __shfl_xor_sync(0xffffffffu, v, o);
    return v;
}

__global__ __launch_bounds__(256) void ln_split(
    const float* __restrict__ x, const float* __restrict__ g,
    const float* __restrict__ b,
    __nv_bfloat16* __restrict__ yh, __nv_bfloat16* __restrict__ yl)
{
    const int row = blockIdx.x;
    const int tid = threadIdx.x;
    const float* xr = x + (size_t)row * DMODEL;

    float4 v = reinterpret_cast<const float4*>(xr)[tid];
    float s  = v.x + v.y + v.z + v.w;
    float sq = v.x*v.x + v.y*v.y + v.z*v.z + v.w*v.w;

    __shared__ float sh_s[8], sh_q[8];
    float ws = warp_sum(s), wq = warp_sum(sq);
    int warp = tid >> 5, lane = tid & 31;
    if (lane == 0) { sh_s[warp] = ws; sh_q[warp] = wq; }
    __syncthreads();
    __shared__ float sh_mean, sh_rstd;
    if (tid == 0) {
        float ts = 0.f, tq = 0.f;
        #pragma unroll
        for (int i = 0; i < 8; i++) { ts += sh_s[i]; tq += sh_q[i]; }
        float mean = ts * (1.0f / DMODEL);
        float var  = tq * (1.0f / DMODEL) - mean * mean;
        sh_mean = mean; sh_rstd = rsqrtf(var + 1e-5f);
    }
    __syncthreads();
    float mean = sh_mean, rstd = sh_rstd;

    float4 gv = reinterpret_cast<const float4*>(g)[tid];
    float4 bv = reinterpret_cast<const float4*>(b)[tid];
    float ox = (v.x - mean) * rstd * gv.x + bv.x;
    float oy = (v.y - mean) * rstd * gv.y + bv.y;
    float oz = (v.z - mean) * rstd * gv.z + bv.z;
    float ow = (v.w - mean) * rstd * gv.w + bv.w;

    __nv_bfloat162 l01, l23;
    __nv_bfloat162 h01 = splitpair(ox, oy, l01);
    __nv_bfloat162 h23 = splitpair(oz, ow, l23);
    size_t o = (size_t)row * DMODEL + tid * 4;
    *reinterpret_cast<__nv_bfloat162*>(yh + o)     = h01;
    *reinterpret_cast<__nv_bfloat162*>(yh + o + 2) = h23;
    *reinterpret_cast<__nv_bfloat162*>(yl + o)     = l01;
    *reinterpret_cast<__nv_bfloat162*>(yl + o + 2) = l23;
}

// ---------------- weight transpose + bf16 split: W[K,N] -> hi/lo[N,K] --------
__global__ __launch_bounds__(256) void wconv(
    const float* __restrict__ W, __nv_bfloat16* __restrict__ hi,
    __nv_bfloat16* __restrict__ lo, int K, int N)
{
    __shared__ float t[32][33];
    const int n0 = blockIdx.x * 32, k0 = blockIdx.y * 32;
    const int tx = threadIdx.x & 31, ty = threadIdx.x >> 5;
    #pragma unroll
    for (int j = 0; j < 4; j++)
        t[ty + j*8][tx] = W[(size_t)(k0 + ty + j*8) * N + n0 + tx];
    __syncthreads();
    #pragma unroll
    for (int j = 0; j < 4; j++) {
        int n = ty + j*8;
        float x = t[tx][n];
        __nv_bfloat16 h = __float2bfloat16_rn(x);
        float l = x - __bfloat162float(h);
        hi[(size_t)(n0 + n) * K + k0 + tx] = h;
        lo[(size_t)(n0 + n) * K + k0 + tx] = __float2bfloat16_rn(l);
    }
}

// ---------------- V transpose (bf16 hi/lo, split-preserving) -----------------
__global__ __launch_bounds__(256) void vtrans(
    const __nv_bfloat16* __restrict__ qsph, const __nv_bfloat16* __restrict__ qspl,
    __nv_bfloat16* __restrict__ vh, __nv_bfloat16* __restrict__ vl)
{
    __shared__ __nv_bfloat16 th[32][40], tl[32][40];
    const int t0 = blockIdx.x * 32, d0 = blockIdx.y * 32;
    const int bh = blockIdx.z, b = bh >> 4, h = bh & 15;
    const int tx = threadIdx.x & 31, ty = threadIdx.x >> 5;
    #pragma unroll
    for (int j = 0; j < 4; j++) {
        int tt = ty + j*8;
        size_t src = (size_t)(b*TSEQ + t0 + tt) * QKVROW + 2048 + h*64 + d0 + tx;
        th[tt][tx] = qsph[src];
        tl[tt][tx] = qspl[src];
    }
    __syncthreads();
    #pragma unroll
    for (int j = 0; j < 4; j++) {
        int d = ty + j*8;
        size_t o = ((size_t)bh * 64 + d0 + d) * TSEQ + t0 + tx;
        vh[o] = th[tx][d];
        vl[o] = tl[tx][d];
    }
}

// ---------------- pure-bf16 HMMA GEMM, 3-stage pipeline ----------------------
// C[M,N](+res,+relu,+qkscale) = (Ahi+Alo)[M,K] @ (Bhi+Blo)[N,K]^T
// CTA 128x128, 8 warps (32x64), K_chunk=64, 3-stage cp.async, 1 sync/stage.
#define GPITCH 144u
#define GTILE  (128u * GPITCH)     // 18432
#define GSTG   (4u * GTILE)        // 73728: Ah, Al, Bh, Bl
#define GSMEM  (3u * GSTG)         // 221184

template<bool RELU, bool RES, bool OSPLIT, bool QKSCALE>
__global__ __launch_bounds__(256, 1) void gemm_b16(
    const __nv_bfloat16* __restrict__ Ahi, const __nv_bfloat16* __restrict__ Alo,
    const __nv_bfloat16* __restrict__ Bhi, const __nv_bfloat16* __restrict__ Blo,
    const float* __restrict__ bias, const float* __restrict__ res,
    float* __restrict__ C, __nv_bfloat16* __restrict__ Chi,
    __nv_bfloat16* __restrict__ Clo, int N, int K)
{
    extern __shared__ char sm[];
    const int tid = threadIdx.x, wid = tid >> 5, lane = tid & 31;
    const int m0 = blockIdx.y * 128, n0 = blockIdx.x * 128;
    const uint32_t sb = smem_u32(sm);

    const int mw = (wid & 3) * 32;
    const int nw = (wid >> 2) * 64;
    const int lg = lane >> 3, lr = lane & 7;

    float d[2][8][4];
    #pragma unroll
    for (int mt = 0; mt < 2; mt++)
        #pragma unroll
        for (int nt = 0; nt < 8; nt++)
            #pragma unroll
            for (int i = 0; i < 4; i++) d[mt][nt][i] = 0.f;

    const int nkt = K >> 6;    // K_chunk = 64, nkt >= 2 always here

    auto loadStage = [&](int s, int k0) {
        const uint32_t st = sb + (uint32_t)s * GSTG;
        const __nv_bfloat16* base0 = Ahi + (size_t)m0 * K + k0;
        const __nv_bfloat16* base1 = Alo + (size_t)m0 * K + k0;
        const __nv_bfloat16* base2 = Bhi + (size_t)n0 * K + k0;
        const __nv_bfloat16* base3 = Blo + (size_t)n0 * K + k0;
        #pragma unroll
        for (int i = 0; i < 4; i++) {
            int lin = i * 256 + tid;
            int row = lin >> 3, seg = lin & 7;
            uint32_t off = (uint32_t)row * GPITCH + (uint32_t)seg * 16u;
            const size_t go = (size_t)row * K + seg * 8;
            CP_ASYNC16(st + off,              (const char*)(base0 + go));
            CP_ASYNC16(st + GTILE + off,      (const char*)(base1 + go));
            CP_ASYNC16(st + 2u*GTILE + off,   (const char*)(base2 + go));
            CP_ASYNC16(st + 3u*GTILE + off,   (const char*)(base3 + go));
        }
        CP_COMMIT();
    };

    auto mmaStage = [&](int s) {
        const uint32_t AhS = sb + (uint32_t)s * GSTG;
        const uint32_t AlS = AhS + GTILE;
        const uint32_t BhS = AhS + 2u * GTILE;
        const uint32_t BlS = AhS + 3u * GTILE;
        #pragma unroll
        for (int kh = 0; kh < 4; kh++) {
            uint32_t ah[2][4], al[2][4];
            #pragma unroll
            for (int mt = 0; mt < 2; mt++) {
                uint32_t roff = (uint32_t)(mw + mt*16 + lr + ((lg & 1) << 3)) * GPITCH
                              + (uint32_t)(kh*16 + ((lg >> 1) << 3)) * 2u;
                ldmat4(ah[mt], AhS + roff);
                ldmat4(al[mt], AlS + roff);
            }
            #pragma unroll
            for (int bt = 0; bt < 4; bt++) {
                uint32_t roff = (uint32_t)(nw + bt*16 + lr + ((lg & 2) ? 8 : 0)) * GPITCH
                              + (uint32_t)(kh*16 + ((lg & 1) << 3)) * 2u;
                uint32_t bh[4], bl[4];
                ldmat4(bh, BhS + roff);
                ldmat4(bl, BlS + roff);
                #pragma unroll
                for (int mt = 0; mt < 2; mt++) {
                    mma16816(d[mt][2*bt+0], ah[mt], bh[0], bh[1]);
                    mma16816(d[mt][2*bt+0], ah[mt], bl[0], bl[1]);
                    mma16816(d[mt][2*bt+0], al[mt], bh[0], bh[1]);
                    mma16816(d[mt][2*bt+1], ah[mt], bh[2], bh[3]);
                    mma16816(d[mt][2*bt+1], ah[mt], bl[2], bl[3]);
                    mma16816(d[mt][2*bt+1], al[mt], bh[2], bh[3]);
                }
            }
        }
    };

    // 3-stage pipeline, one barrier per stage
    loadStage(0, 0);
    loadStage(1, 64);
    for (int kt = 0; kt < nkt; kt++) {
        if (kt + 1 < nkt) { CP_WAIT1(); } else { CP_WAIT0(); }
        __syncthreads();
        if (kt + 2 < nkt) loadStage((kt + 2) % 3, (kt + 2) << 6);
        mmaStage(kt % 3);
    }

    // ---- epilogue ----
    const int qr = lane >> 2;
    const int qc = (lane & 3) * 2;
    #pragma unroll
    for (int mt = 0; mt < 2; mt++) {
        const int r0 = m0 + mw + mt * 16 + qr;
        const int r1 = r0 + 8;
        #pragma unroll
        for (int nt = 0; nt < 8; nt++) {
            const int c = n0 + nw + nt * 8 + qc;
            float2 bb = *reinterpret_cast<const float2*>(bias + c);
            float2 o0, o1;
            o0.x = d[mt][nt][0] + bb.x; o0.y = d[mt][nt][1] + bb.y;
            o1.x = d[mt][nt][2] + bb.x; o1.y = d[mt][nt][3] + bb.y;
            if (QKSCALE) {
                const float sc = (c < 1024) ? 0.125f : 1.0f;
                o0.x *= sc; o0.y *= sc; o1.x *= sc; o1.y *= sc;
            }
            if (RELU) {
                o0.x = fmaxf(o0.x, 0.f); o0.y = fmaxf(o0.y, 0.f);
                o1.x = fmaxf(o1.x, 0.f); o1.y = fmaxf(o1.y, 0.f);
            }
            if (RES) {
                float2 u0 = *reinterpret_cast<const float2*>(res + (size_t)r0 * N + c);
                float2 u1 = *reinterpret_cast<const float2*>(res + (size_t)r1 * N + c);
                o0.x += u0.x; o0.y += u0.y; o1.x += u1.x; o1.y += u1.y;
            }
            if (OSPLIT) {
                __nv_bfloat162 l0, l1;
                __nv_bfloat162 h0 = splitpair(o0.x, o0.y, l0);
                __nv_bfloat162 h1 = splitpair(o1.x, o1.y, l1);
                *reinterpret_cast<__nv_bfloat162*>(Chi + (size_t)r0 * N + c) = h0;
                *reinterpret_cast<__nv_bfloat162*>(Chi + (size_t)r1 * N + c) = h1;
                *reinterpret_cast<__nv_bfloat162*>(Clo + (size_t)r0 * N + c) = l0;
                *reinterpret_cast<__nv_bfloat162*>(Clo + (size_t)r1 * N + c) = l1;
            } else {
                *reinterpret_cast<float2*>(C + (size_t)r0 * N + c) = o0;
                *reinterpret_cast<float2*>(C + (size_t)r1 * N + c) = o1;
            }
        }
    }
}

// ---------------- MMA flash attention (causal), 3-stage KV pipeline ----------
#define APITCH 144u
#define AQ_B   (128u * APITCH)
#define AKV_B  (64u * APITCH)
#define ASTG_B (4u * AKV_B)
#define ASMEM  (2u * AQ_B + 3u * ASTG_B)   // 147456

__global__ __launch_bounds__(256, 1) void flash_mma(
    const __nv_bfloat16* __restrict__ qsph, const __nv_bfloat16* __restrict__ qspl,
    const __nv_bfloat16* __restrict__ vth, const __nv_bfloat16* __restrict__ vtl,
    __nv_bfloat16* __restrict__ ctxh, __nv_bfloat16* __restrict__ ctxl)
{
    extern __shared__ char sm[];
    const int tid = threadIdx.x, wid = tid >> 5, lane = tid & 31;
    const int q0 = (15 - blockIdx.x) * 128;
    const int bh = blockIdx.y, b = bh >> 4, h = bh & 15;
    const int mw = wid * 16;
    const int lg = lane >> 3, lr = lane & 7;
    const int qr = lane >> 2, qc = (lane & 3) * 2;

    const uint32_t sb = smem_u32(sm);
    const uint32_t QH = sb, QL = sb + AQ_B;
    const uint32_t ST = sb + 2u * AQ_B;

    {
        const __nv_bfloat16* qb_h = qsph + (size_t)(b*TSEQ + q0) * QKVROW + h*64;
        const __nv_bfloat16* qb_l = qspl + (size_t)(b*TSEQ + q0) * QKVROW + h*64;
        #pragma unroll
        for (int i = 0; i < 4; i++) {
            int lin = i * 256 + tid;
            int row = lin >> 3, seg = lin & 7;
            uint32_t off = (uint32_t)row * APITCH + (uint32_t)seg * 16u;
            CP_ASYNC16(QH + off, (const char*)(qb_h + (size_t)row * QKVROW) + seg * 16);
            CP_ASYNC16(QL + off, (const char*)(qb_l + (size_t)row * QKVROW) + seg * 16);
        }
        CP_COMMIT();
    }

    auto loadKV = [&](int s, int key0) {
        const uint32_t KHs = ST + (uint32_t)s * ASTG_B;
        const uint32_t KLs = KHs + AKV_B;
        const uint32_t VHs = KHs + 2u * AKV_B;
        const uint32_t VLs = KHs + 3u * AKV_B;
        const __nv_bfloat16* kb_h = qsph + (size_t)(b*TSEQ + key0) * QKVROW + 1024 + h*64;
        const __nv_bfloat16* kb_l = qspl + (size_t)(b*TSEQ + key0) * QKVROW + 1024 + h*64;
        const __nv_bfloat16* vb_h = vth + (size_t)bh * 64 * TSEQ + key0;
        const __nv_bfloat16* vb_l = vtl + (size_t)bh * 64 * TSEQ + key0;
        #pragma unroll
        for (int i = 0; i < 2; i++) {
            int lin = i * 256 + tid;
            int row = lin >> 3, seg = lin & 7;
            uint32_t off = (uint32_t)row * APITCH + (uint32_t)seg * 16u;
            CP_ASYNC16(KHs + off, (const char*)(kb_h + (size_t)row * QKVROW) + seg * 16);
            CP_ASYNC16(KLs + off, (const char*)(kb_l + (size_t)row * QKVROW) + seg * 16);
            CP_ASYNC16(VHs + off, (const char*)(vb_h + (size_t)row * TSEQ) + seg * 16);
            CP_ASYNC16(VLs + off, (const char*)(vb_l + (size_t)row * TSEQ) + seg * 16);
        }
        CP_COMMIT();
    };

    const int nkt = q0 / 64 + 2;     // >= 2 always
    loadKV(0, 0);
    loadKV(1, 64);
    CP_WAIT1();                       // Q + KV0 complete
    __syncthreads();

    uint32_t qfh[4][4], qfl[4][4];
    #pragma unroll
    for (int kh = 0; kh < 4; kh++) {
        uint32_t roff = (uint32_t)(mw + lr + ((lg & 1) << 3)) * APITCH
                      + (uint32_t)(kh*16 + ((lg >> 1) << 3)) * 2u;
        ldmat4(qfh[kh], QH + roff);
        ldmat4(qfl[kh], QL + roff);
    }

    float o[8][4];
    #pragma unroll
    for (int nt = 0; nt < 8; nt++)
        #pragma unroll
        for (int i = 0; i < 4; i++) o[nt][i] = 0.f;
    float m0r = -1e30f, m1r = -1e30f, l0r = 0.f, l1r = 0.f;

    for (int kt = 0; kt < nkt; kt++) {
        const int key0 = kt * 64;
        if (kt > 0) {
            if (kt + 1 < nkt) { CP_WAIT1(); } else { CP_WAIT0(); }
            __syncthreads();
        }
        if (kt + 2 < nkt) loadKV((kt + 2) % 3, (kt + 2) * 64);

        if (key0 <= q0 + mw + 15) {
            const int s = kt % 3;
            const uint32_t KHs = ST + (uint32_t)s * ASTG_B;
            const uint32_t KLs = KHs + AKV_B;
            const uint32_t VHs = KHs + 2u * AKV_B;
            const uint32_t VLs = KHs + 3u * AKV_B;

            float sc[8][4];
            #pragma unroll
            for (int nt = 0; nt < 8; nt++)
                #pragma unroll
                for (int i = 0; i < 4; i++) sc[nt][i] = 0.f;

            #pragma unroll
            for (int kh = 0; kh < 4; kh++) {
                #pragma unroll
                for (int bt = 0; bt < 4; bt++) {
                    uint32_t roff = (uint32_t)(bt*16 + lr + ((lg & 2) ? 8 : 0)) * APITCH
                                  + (uint32_t)(kh*16 + ((lg & 1) << 3)) * 2u;
                    uint32_t kfh[4], kfl[4];
                    ldmat4(kfh, KHs + roff);
                    ldmat4(kfl, KLs + roff);
                    mma16816(sc[2*bt+0], qfh[kh], kfh[0], kfh[1]);
                    mma16816(sc[2*bt+0], qfh[kh], kfl[0], kfl[1]);
                    mma16816(sc[2*bt+0], qfl[kh], kfh[0], kfh[1]);
                    mma16816(sc[2*bt+1], qfh[kh], kfh[2], kfh[3]);
                    mma16816(sc[2*bt+1], qfh[kh], kfl[2], kfl[3]);
                    mma16816(sc[2*bt+1], qfl[kh], kfh[2], kfh[3]);
                }
            }

            const int row0 = q0 + mw + qr, row1 = row0 + 8;
            if (key0 + 63 > q0 + mw) {
                #pragma unroll
                for (int nt = 0; nt < 8; nt++) {
                    int c0 = key0 + nt*8 + qc;
                    if (c0     > row0) sc[nt][0] = -1e30f;
                    if (c0 + 1 > row0) sc[nt][1] = -1e30f;
                    if (c0     > row1) sc[nt][2] = -1e30f;
                    if (c0 + 1 > row1) sc[nt][3] = -1e30f;
                }
            }

            float mx0 = -1e30f, mx1 = -1e30f;
            #pragma unroll
            for (int nt = 0; nt < 8; nt++) {
                mx0 = fmaxf(mx0, fmaxf(sc[nt][0], sc[nt][1]));
                mx1 = fmaxf(mx1, fmaxf(sc[nt][2], sc[nt][3]));
            }
            mx0 = fmaxf(mx0, __shfl_xor_sync(0xffffffffu, mx0, 1));
            mx0 = fmaxf(mx0, __shfl_xor_sync(0xffffffffu, mx0, 2));
            mx1 = fmaxf(mx1, __shfl_xor_sync(0xffffffffu, mx1, 1));
            mx1 = fmaxf(mx1, __shfl_xor_sync(0xffffffffu, mx1, 2));
            float mn0 = fmaxf(m0r, mx0), mn1 = fmaxf(m1r, mx1);
            float a0 = __expf(m0r - mn0), a1 = __expf(m1r - mn1);
            float sum0 = 0.f, sum1 = 0.f;
            #pragma unroll
            for (int nt = 0; nt < 8; nt++) {
                sc[nt][0] = __expf(sc[nt][0] - mn0);
                sc[nt][1] = __expf(sc[nt][1] - mn0);
                sc[nt][2] = __expf(sc[nt][2] - mn1);
                sc[nt][3] = __expf(sc[nt][3] - mn1);
                sum0 += sc[nt][0] + sc[nt][1];
                sum1 += sc[nt][2] + sc[nt][3];
            }
            sum0 += __shfl_xor_sync(0xffffffffu, sum0, 1);
            sum0 += __shfl_xor_sync(0xffffffffu, sum0, 2);
            sum1 += __shfl_xor_sync(0xffffffffu, sum1, 1);
            sum1 += __shfl_xor_sync(0xffffffffu, sum1, 2);
            l0r = l0r * a0 + sum0;
            l1r = l1r * a1 + sum1;
            m0r = mn0; m1r = mn1;
            #pragma unroll
            for (int nt = 0; nt < 8; nt++) {
                o[nt][0] *= a0; o[nt][1] *= a0;
                o[nt][2] *= a1; o[nt][3] *= a1;
            }

            #pragma unroll
            for (int kh2 = 0; kh2 < 4; kh2++) {
                const int n0t = 2 * kh2, n1t = 2 * kh2 + 1;
                uint32_t pah[4], pal[4];
                {
                    __nv_bfloat162 e0, e1, e2, e3;
                    __nv_bfloat162 h0 = splitpair(sc[n0t][0], sc[n0t][1], e0);
                    __nv_bfloat162 h1 = splitpair(sc[n0t][2], sc[n0t][3], e1);
                    __nv_bfloat162 h2 = splitpair(sc[n1t][0], sc[n1t][1], e2);
                    __nv_bfloat162 h3 = splitpair(sc[n1t][2], sc[n1t][3], e3);
                    pah[0] = b2u(h0); pah[1] = b2u(h1); pah[2] = b2u(h2); pah[3] = b2u(h3);
                    pal[0] = b2u(e0); pal[1] = b2u(e1); pal[2] = b2u(e2); pal[3] = b2u(e3);
                }
                #pragma unroll
                for (int bt = 0; bt < 4; bt++) {
                    uint32_t roff = (uint32_t)(bt*16 + lr + ((lg & 2) ? 8 : 0)) * APITCH
                                  + (uint32_t)(kh2*16 + ((lg & 1) << 3)) * 2u;
                    uint32_t vfh[4], vfl[4];
                    ldmat4(vfh, VHs + roff);
                    ldmat4(vfl, VLs + roff);
                    mma16816(o[2*bt+0], pah, vfh[0], vfh[1]);
                    mma16816(o[2*bt+0], pal, vfh[0], vfh[1]);
                    mma16816(o[2*bt+0], pah, vfl[0], vfl[1]);
                    mma16816(o[2*bt+1], pah, vfh[2], vfh[3]);
                    mma16816(o[2*bt+1], pal, vfh[2], vfh[3]);
                    mma16816(o[2*bt+1], pah, vfl[2], vfl[3]);
                }
            }
        }
    }

    // ---- normalize + split-store ----
    const float inv0 = 1.f / l0r, inv1 = 1.f / l1r;
    const int row0 = q0 + mw + qr, row1 = row0 + 8;
    const size_t o0 = (size_t)(b*TSEQ + row0) * DMODEL + h*64;
    const size_t o1 = (size_t)(b*TSEQ + row1) * DMODEL + h*64;
    #pragma unroll
    for (int nt = 0; nt < 8; nt++) {
        int col = nt*8 + qc;
        __nv_bfloat162 l0, l1;
        __nv_bfloat162 h0 = splitpair(o[nt][0] * inv0, o[nt][1] * inv0, l0);
        __nv_bfloat162 h1 = splitpair(o[nt][2] * inv1, o[nt][3] * inv1, l1);
        *reinterpret_cast<__nv_bfloat162*>(ctxh + o0 + col) = h0;
        *reinterpret_cast<__nv_bfloat162*>(ctxh + o1 + col) = h1;
        *reinterpret_cast<__nv_bfloat162*>(ctxl + o0 + col) = l0;
        *reinterpret_cast<__nv_bfloat162*>(ctxl + o1 + col) = l1;
    }
}

// ---------------- launch ------------------------------------------------------
extern "C" void kernel_launch(void* const* d_in, const int* in_sizes, int n_in,
                              void* d_out, int out_size)
{
    (void)in_sizes; (void)n_in; (void)out_size;
    const float* X     = (const float*)d_in[0];
    const float* Wqkv  = (const float*)d_in[1];
    const float* bqkv  = (const float*)d_in[2];
    const float* Wo    = (const float*)d_in[3];
    const float* bo    = (const float*)d_in[4];
    const float* W1    = (const float*)d_in[5];
    const float* b1    = (const float*)d_in[6];
    const float* W2    = (const float*)d_in[7];
    const float* b2    = (const float*)d_in[8];
    const float* ln1g  = (const float*)d_in[9];
    const float* ln1b  = (const float*)d_in[10];
    const float* ln2g  = (const float*)d_in[11];
    const float* ln2b  = (const float*)d_in[12];
    float* out = (float*)d_out;

    float* x1;
    cudaGetSymbolAddress((void**)&x1, g_x1);

    __nv_bfloat16 *xnh, *xnl, *xn2h, *xn2l, *ctxh, *ctxl, *hh, *hl, *qsph, *qspl;
    cudaGetSymbolAddress((void**)&xnh,  g_xnh);
    cudaGetSymbolAddress((void**)&xnl,  g_xnl);
    cudaGetSymbolAddress((void**)&xn2h, g_xn2h);
    cudaGetSymbolAddress((void**)&xn2l, g_xn2l);
    cudaGetSymbolAddress((void**)&ctxh, g_ctxh);
    cudaGetSymbolAddress((void**)&ctxl, g_ctxl);
    cudaGetSymbolAddress((void**)&hh,   g_hh);
    cudaGetSymbolAddress((void**)&hl,   g_hl);
    cudaGetSymbolAddress((void**)&qsph, g_qsph);
    cudaGetSymbolAddress((void**)&qspl, g_qspl);

    __nv_bfloat16 *wqkv_hi, *wqkv_lo, *wo_hi, *wo_lo, *w1_hi, *w1_lo, *w2_hi, *w2_lo;
    __nv_bfloat16 *vth, *vtl;
    cudaGetSymbolAddress((void**)&wqkv_hi, g_wqkv_hi);
    cudaGetSymbolAddress((void**)&wqkv_lo, g_wqkv_lo);
    cudaGetSymbolAddress((void**)&wo_hi,   g_wo_hi);
    cudaGetSymbolAddress((void**)&wo_lo,   g_wo_lo);
    cudaGetSymbolAddress((void**)&w1_hi,   g_w1_hi);
    cudaGetSymbolAddress((void**)&w1_lo,   g_w1_lo);
    cudaGetSymbolAddress((void**)&w2_hi,   g_w2_hi);
    cudaGetSymbolAddress((void**)&w2_lo,   g_w2_lo);
    cudaGetSymbolAddress((void**)&vth,     g_vth);
    cudaGetSymbolAddress((void**)&vtl,     g_vtl);

    cudaFuncSetAttribute(gemm_b16<false,false,true,true>, cudaFuncAttributeMaxDynamicSharedMemorySize, GSMEM);
    cudaFuncSetAttribute(gemm_b16<false,true,false,false>, cudaFuncAttributeMaxDynamicSharedMemorySize, GSMEM);
    cudaFuncSetAttribute(gemm_b16<true,false,true,false>,  cudaFuncAttributeMaxDynamicSharedMemorySize, GSMEM);
    cudaFuncSetAttribute(flash_mma, cudaFuncAttributeMaxDynamicSharedMemorySize, ASMEM);

    // weight transpose + split
    wconv<<<dim3(QKVROW/32, DMODEL/32), 256>>>(Wqkv, wqkv_hi, wqkv_lo, DMODEL, QKVROW);
    wconv<<<dim3(DMODEL/32, DMODEL/32), 256>>>(Wo,   wo_hi,   wo_lo,   DMODEL, DMODEL);
    wconv<<<dim3(DFF/32,    DMODEL/32), 256>>>(W1,   w1_hi,   w1_lo,   DMODEL, DFF);
    wconv<<<dim3(DMODEL/32, DFF/32),    256>>>(W2,   w2_hi,   w2_lo,   DFF,    DMODEL);

    // 1. LN1 -> split bf16
    ln_split<<<NTOK, 256>>>(X, ln1g, ln1b, xnh, xnl);
    // 2. QKV = LN1(X) @ Wqkv + bqkv  -> split bf16, Q cols pre-scaled by 1/8
    gemm_b16<false,false,true,true><<<dim3(QKVROW/128, NTOK/128), 256, GSMEM>>>(
        xnh, xnl, wqkv_hi, wqkv_lo, bqkv, nullptr, nullptr, qsph, qspl, QKVROW, DMODEL);
    // 3a. V transpose (split-preserving)
    vtrans<<<dim3(TSEQ/32, DKEY/32, BATCH*NHEADS), 256>>>(qsph, qspl, vth, vtl);
    // 3b. MMA flash attention -> split bf16 ctx
    flash_mma<<<dim3(TSEQ/128, BATCH*NHEADS), 256, ASMEM>>>(qsph, qspl, vth, vtl, ctxh, ctxl);
    // 4. x1 = ctx @ Wo + bo + X  (fp32 out)
    gemm_b16<false,true,false,false><<<dim3(DMODEL/128, NTOK/128), 256, GSMEM>>>(
        ctxh, ctxl, wo_hi, wo_lo, bo, X, x1, nullptr, nullptr, DMODEL, DMODEL);
    // 5. LN2 -> split bf16
    ln_split<<<NTOK, 256>>>(x1, ln2g, ln2b, xn2h, xn2l);
    // 6. h = relu(xn2 @ W1 + b1)  (split bf16 out)
    gemm_b16<true,false,true,false><<<dim3(DFF/128, NTOK/128), 256, GSMEM>>>(
        xn2h, xn2l, w1_hi, w1_lo, b1, nullptr, nullptr, hh, hl, DFF, DMODEL);
    // 7. out = h @ W2 + b2 + x1  (fp32 out)
    gemm_b16<false,true,false,false><<<dim3(DMODEL/128, NTOK/128), 256, GSMEM>>>(
        hh, hl, w2_hi, w2_lo, b2, x1, out, nullptr, nullptr, DMODEL, DFF);
}

// round 8
// speedup vs baseline: 4.2858x; 1.1724x over previous
#include <cuda_runtime.h>
#include <cuda_bf16.h>
#include <cuda_fp16.h>
#include <cstdint>
#include <cstddef>

// Problem constants
#define BATCH   2
#define TSEQ    2048
#define DMODEL  1024
#define NHEADS  16
#define DKEY    64
#define DFF     4096
#define NTOK    (BATCH*TSEQ)          // 4096
#define QKVROW  (3*NHEADS*DKEY)       // 3072

// ---------------- scratch ----------------------------------------------------
__device__ float g_x1  [(size_t)NTOK*DMODEL];

// bf16 split activations (attention path)
__device__ __nv_bfloat16 g_xnh [(size_t)NTOK*DMODEL];
__device__ __nv_bfloat16 g_xnl [(size_t)NTOK*DMODEL];
__device__ __nv_bfloat16 g_ctxh[(size_t)NTOK*DMODEL];
__device__ __nv_bfloat16 g_ctxl[(size_t)NTOK*DMODEL];

// fp16 split activations (FFN path)
__device__ __half g_xn2h[(size_t)NTOK*DMODEL];
__device__ __half g_xn2l[(size_t)NTOK*DMODEL];
__device__ __half g_hh  [(size_t)NTOK*DFF];
__device__ __half g_hl  [(size_t)NTOK*DFF];

// qkv split output: [tok][3072] (Q scaled by 1/8 in cols 0..1023)
__device__ __nv_bfloat16 g_qsph[(size_t)NTOK*QKVROW];
__device__ __nv_bfloat16 g_qspl[(size_t)NTOK*QKVROW];

// transposed weights [N, K] K-major
__device__ __nv_bfloat16 g_wqkv_hi[(size_t)QKVROW*DMODEL];
__device__ __nv_bfloat16 g_wqkv_lo[(size_t)QKVROW*DMODEL];
__device__ __nv_bfloat16 g_wo_hi  [(size_t)DMODEL*DMODEL];
__device__ __nv_bfloat16 g_wo_lo  [(size_t)DMODEL*DMODEL];
__device__ __half        g_w1f    [(size_t)DFF*DMODEL];     // single fp16
__device__ __half        g_w2f    [(size_t)DMODEL*DFF];     // single fp16

// V transposed per (b,h): [bh][d][t]
__device__ __nv_bfloat16 g_vth[(size_t)BATCH*NHEADS*DKEY*TSEQ];
__device__ __nv_bfloat16 g_vtl[(size_t)BATCH*NHEADS*DKEY*TSEQ];

// ---------------- helpers ----------------------------------------------------
__device__ __forceinline__ uint32_t smem_u32(const void* p) {
    uint32_t a;
    asm("{ .reg .u64 t; cvta.to.shared.u64 t, %1; cvt.u32.u64 %0, t; }"
        : "=r"(a) : "l"(p));
    return a;
}
#define CP_ASYNC16(dst, src) \
    asm volatile("cp.async.cg.shared.global [%0], [%1], 16;" :: "r"(dst), "l"(src) : "memory")
#define CP_COMMIT() asm volatile("cp.async.commit_group;" ::: "memory")
#define CP_WAIT0()  asm volatile("cp.async.wait_group 0;"  ::: "memory")
#define CP_WAIT1()  asm volatile("cp.async.wait_group 1;"  ::: "memory")

__device__ __forceinline__ void ldmat4(uint32_t (&r)[4], uint32_t addr) {
    asm volatile("ldmatrix.sync.aligned.m8n8.x4.shared.b16 {%0,%1,%2,%3}, [%4];"
        : "=r"(r[0]), "=r"(r[1]), "=r"(r[2]), "=r"(r[3]) : "r"(addr));
}
__device__ __forceinline__ void mma16816(float (&d)[4], const uint32_t (&a)[4],
                                         const uint32_t b0, const uint32_t b1) {
    asm volatile("mma.sync.aligned.m16n8k16.row.col.f32.bf16.bf16.f32 "
        "{%0,%1,%2,%3}, {%4,%5,%6,%7}, {%8,%9}, {%0,%1,%2,%3};"
        : "+f"(d[0]), "+f"(d[1]), "+f"(d[2]), "+f"(d[3])
        : "r"(a[0]), "r"(a[1]), "r"(a[2]), "r"(a[3]), "r"(b0), "r"(b1));
}
__device__ __forceinline__ void mma16816h(float (&d)[4], const uint32_t (&a)[4],
                                          const uint32_t b0, const uint32_t b1) {
    asm volatile("mma.sync.aligned.m16n8k16.row.col.f32.f16.f16.f32 "
        "{%0,%1,%2,%3}, {%4,%5,%6,%7}, {%8,%9}, {%0,%1,%2,%3};"
        : "+f"(d[0]), "+f"(d[1]), "+f"(d[2]), "+f"(d[3])
        : "r"(a[0]), "r"(a[1]), "r"(a[2]), "r"(a[3]), "r"(b0), "r"(b1));
}
__device__ __forceinline__ uint32_t b2u(__nv_bfloat162 v) {
    union { __nv_bfloat162 h; uint32_t u; } c; c.h = v; return c.u;
}
__device__ __forceinline__ __nv_bfloat162 splitpair(float x, float y,
                                                    __nv_bfloat162& lo) {
    __nv_bfloat16 hx = __float2bfloat16_rn(x);
    __nv_bfloat16 hy = __float2bfloat16_rn(y);
    lo = __floats2bfloat162_rn(x - __bfloat162float(hx), y - __bfloat162float(hy));
    __nv_bfloat162 hi; hi.x = hx; hi.y = hy;
    return hi;
}
__device__ __forceinline__ __half2 splitpair_h(float x, float y, __half2& lo) {
    __half hx = __float2half_rn(x);
    __half hy = __float2half_rn(y);
    lo = __floats2half2_rn(x - __half2float(hx), y - __half2float(hy));
    __half2 hi; hi.x = hx; hi.y = hy;
    return hi;
}

// ---------------- LayerNorm with split output --------------------------------
__inline__ __device__ float warp_sum(float v) {
    #pragma unroll
    for (int o = 16; o > 0; o >>= 1) v += __shfl_xor_sync(0xffffffffu, v, o);
    return v;
}

template<bool FP16OUT>
__global__ __launch_bounds__(256) void ln_split(
    const float* __restrict__ x, const float* __restrict__ g,
    const float* __restrict__ b,
    void* __restrict__ yh_, void* __restrict__ yl_)
{
    const int row = blockIdx.x;
    const int tid = threadIdx.x;
    const float* xr = x + (size_t)row * DMODEL;

    float4 v = reinterpret_cast<const float4*>(xr)[tid];
    float s  = v.x + v.y + v.z + v.w;
    float sq = v.x*v.x + v.y*v.y + v.z*v.z + v.w*v.w;

    __shared__ float sh_s[8], sh_q[8];
    float ws = warp_sum(s), wq = warp_sum(sq);
    int warp = tid >> 5, lane = tid & 31;
    if (lane == 0) { sh_s[warp] = ws; sh_q[warp] = wq; }
    __syncthreads();
    __shared__ float sh_mean, sh_rstd;
    if (tid == 0) {
        float ts = 0.f, tq = 0.f;
        #pragma unroll
        for (int i = 0; i < 8; i++) { ts += sh_s[i]; tq += sh_q[i]; }
        float mean = ts * (1.0f / DMODEL);
        float var  = tq * (1.0f / DMODEL) - mean * mean;
        sh_mean = mean; sh_rstd = rsqrtf(var + 1e-5f);
    }
    __syncthreads();
    float mean = sh_mean, rstd = sh_rstd;

    float4 gv = reinterpret_cast<const float4*>(g)[tid];
    float4 bv = reinterpret_cast<const float4*>(b)[tid];
    float ox = (v.x - mean) * rstd * gv.x + bv.x;
    float oy = (v.y - mean) * rstd * gv.y + bv.y;
    float oz = (v.z - mean) * rstd * gv.z + bv.z;
    float ow = (v.w - mean) * rstd * gv.w + bv.w;

    size_t o = (size_t)row * DMODEL + tid * 4;
    if (FP16OUT) {
        __half2 l01, l23;
        __half2 h01 = splitpair_h(ox, oy, l01);
        __half2 h23 = splitpair_h(oz, ow, l23);
        __half* yh = (__half*)yh_; __half* yl = (__half*)yl_;
        *reinterpret_cast<__half2*>(yh + o)     = h01;
        *reinterpret_cast<__half2*>(yh + o + 2) = h23;
        *reinterpret_cast<__half2*>(yl + o)     = l01;
        *reinterpret_cast<__half2*>(yl + o + 2) = l23;
    } else {
        __nv_bfloat162 l01, l23;
        __nv_bfloat162 h01 = splitpair(ox, oy, l01);
        __nv_bfloat162 h23 = splitpair(oz, ow, l23);
        __nv_bfloat16* yh = (__nv_bfloat16*)yh_; __nv_bfloat16* yl = (__nv_bfloat16*)yl_;
        *reinterpret_cast<__nv_bfloat162*>(yh + o)     = h01;
        *reinterpret_cast<__nv_bfloat162*>(yh + o + 2) = h23;
        *reinterpret_cast<__nv_bfloat162*>(yl + o)     = l01;
        *reinterpret_cast<__nv_bfloat162*>(yl + o + 2) = l23;
    }
}

// ---------------- weight transpose kernels -----------------------------------
__global__ __launch_bounds__(256) void wconv(
    const float* __restrict__ W, __nv_bfloat16* __restrict__ hi,
    __nv_bfloat16* __restrict__ lo, int K, int N)
{
    __shared__ float t[32][33];
    const int n0 = blockIdx.x * 32, k0 = blockIdx.y * 32;
    const int tx = threadIdx.x & 31, ty = threadIdx.x >> 5;
    #pragma unroll
    for (int j = 0; j < 4; j++)
        t[ty + j*8][tx] = W[(size_t)(k0 + ty + j*8) * N + n0 + tx];
    __syncthreads();
    #pragma unroll
    for (int j = 0; j < 4; j++) {
        int n = ty + j*8;
        float x = t[tx][n];
        __nv_bfloat16 h = __float2bfloat16_rn(x);
        float l = x - __bfloat162float(h);
        hi[(size_t)(n0 + n) * K + k0 + tx] = h;
        lo[(size_t)(n0 + n) * K + k0 + tx] = __float2bfloat16_rn(l);
    }
}

__global__ __launch_bounds__(256) void wconv_f16(
    const float* __restrict__ W, __half* __restrict__ out, int K, int N)
{
    __shared__ float t[32][33];
    const int n0 = blockIdx.x * 32, k0 = blockIdx.y * 32;
    const int tx = threadIdx.x & 31, ty = threadIdx.x >> 5;
    #pragma unroll
    for (int j = 0; j < 4; j++)
        t[ty + j*8][tx] = W[(size_t)(k0 + ty + j*8) * N + n0 + tx];
    __syncthreads();
    #pragma unroll
    for (int j = 0; j < 4; j++) {
        int n = ty + j*8;
        out[(size_t)(n0 + n) * K + k0 + tx] = __float2half_rn(t[tx][n]);
    }
}

// ---------------- V transpose (bf16 hi/lo, split-preserving) -----------------
__global__ __launch_bounds__(256) void vtrans(
    const __nv_bfloat16* __restrict__ qsph, const __nv_bfloat16* __restrict__ qspl,
    __nv_bfloat16* __restrict__ vh, __nv_bfloat16* __restrict__ vl)
{
    __shared__ __nv_bfloat16 th[32][40], tl[32][40];
    const int t0 = blockIdx.x * 32, d0 = blockIdx.y * 32;
    const int bh = blockIdx.z, b = bh >> 4, h = bh & 15;
    const int tx = threadIdx.x & 31, ty = threadIdx.x >> 5;
    #pragma unroll
    for (int j = 0; j < 4; j++) {
        int tt = ty + j*8;
        size_t src = (size_t)(b*TSEQ + t0 + tt) * QKVROW + 2048 + h*64 + d0 + tx;
        th[tt][tx] = qsph[src];
        tl[tt][tx] = qspl[src];
    }
    __syncthreads();
    #pragma unroll
    for (int j = 0; j < 4; j++) {
        int d = ty + j*8;
        size_t o = ((size_t)bh * 64 + d0 + d) * TSEQ + t0 + tx;
        vh[o] = th[tx][d];
        vl[o] = tl[tx][d];
    }
}

// ---------------- 3-product bf16 HMMA GEMM (QKV, Wo) -------------------------
#define GPITCH 144u
#define GTILE  (128u * GPITCH)     // 18432
#define GSTG   (4u * GTILE)        // Ah, Al, Bh, Bl
#define GSMEM  (3u * GSTG)         // 221184

template<bool RES, bool OSPLIT, bool QKSCALE>
__global__ __launch_bounds__(256, 1) void gemm_b16(
    const __nv_bfloat16* __restrict__ Ahi, const __nv_bfloat16* __restrict__ Alo,
    const __nv_bfloat16* __restrict__ Bhi, const __nv_bfloat16* __restrict__ Blo,
    const float* __restrict__ bias, const float* __restrict__ res,
    float* __restrict__ C, __nv_bfloat16* __restrict__ Chi,
    __nv_bfloat16* __restrict__ Clo, int N, int K)
{
    extern __shared__ char sm[];
    const int tid = threadIdx.x, wid = tid >> 5, lane = tid & 31;
    const int m0 = blockIdx.y * 128, n0 = blockIdx.x * 128;
    const uint32_t sb = smem_u32(sm);

    const int mw = (wid & 3) * 32;
    const int nw = (wid >> 2) * 64;
    const int lg = lane >> 3, lr = lane & 7;

    float d[2][8][4];
    #pragma unroll
    for (int mt = 0; mt < 2; mt++)
        #pragma unroll
        for (int nt = 0; nt < 8; nt++)
            #pragma unroll
            for (int i = 0; i < 4; i++) d[mt][nt][i] = 0.f;

    const int nkt = K >> 6;

    auto loadStage = [&](int s, int k0) {
        const uint32_t st = sb + (uint32_t)s * GSTG;
        const __nv_bfloat16* base0 = Ahi + (size_t)m0 * K + k0;
        const __nv_bfloat16* base1 = Alo + (size_t)m0 * K + k0;
        const __nv_bfloat16* base2 = Bhi + (size_t)n0 * K + k0;
        const __nv_bfloat16* base3 = Blo + (size_t)n0 * K + k0;
        #pragma unroll
        for (int i = 0; i < 4; i++) {
            int lin = i * 256 + tid;
            int row = lin >> 3, seg = lin & 7;
            uint32_t off = (uint32_t)row * GPITCH + (uint32_t)seg * 16u;
            const size_t go = (size_t)row * K + seg * 8;
            CP_ASYNC16(st + off,              (const char*)(base0 + go));
            CP_ASYNC16(st + GTILE + off,      (const char*)(base1 + go));
            CP_ASYNC16(st + 2u*GTILE + off,   (const char*)(base2 + go));
            CP_ASYNC16(st + 3u*GTILE + off,   (const char*)(base3 + go));
        }
        CP_COMMIT();
    };

    auto mmaStage = [&](int s) {
        const uint32_t AhS = sb + (uint32_t)s * GSTG;
        const uint32_t AlS = AhS + GTILE;
        const uint32_t BhS = AhS + 2u * GTILE;
        const uint32_t BlS = AhS + 3u * GTILE;
        #pragma unroll
        for (int kh = 0; kh < 4; kh++) {
            uint32_t ah[2][4], al[2][4];
            #pragma unroll
            for (int mt = 0; mt < 2; mt++) {
                uint32_t roff = (uint32_t)(mw + mt*16 + lr + ((lg & 1) << 3)) * GPITCH
                              + (uint32_t)(kh*16 + ((lg >> 1) << 3)) * 2u;
                ldmat4(ah[mt], AhS + roff);
                ldmat4(al[mt], AlS + roff);
            }
            #pragma unroll
            for (int bt = 0; bt < 4; bt++) {
                uint32_t roff = (uint32_t)(nw + bt*16 + lr + ((lg & 2) ? 8 : 0)) * GPITCH
                              + (uint32_t)(kh*16 + ((lg & 1) << 3)) * 2u;
                uint32_t bh[4], bl[4];
                ldmat4(bh, BhS + roff);
                ldmat4(bl, BlS + roff);
                #pragma unroll
                for (int mt = 0; mt < 2; mt++) {
                    mma16816(d[mt][2*bt+0], ah[mt], bh[0], bh[1]);
                    mma16816(d[mt][2*bt+0], ah[mt], bl[0], bl[1]);
                    mma16816(d[mt][2*bt+0], al[mt], bh[0], bh[1]);
                    mma16816(d[mt][2*bt+1], ah[mt], bh[2], bh[3]);
                    mma16816(d[mt][2*bt+1], ah[mt], bl[2], bl[3]);
                    mma16816(d[mt][2*bt+1], al[mt], bh[2], bh[3]);
                }
            }
        }
    };

    loadStage(0, 0);
    loadStage(1, 64);
    for (int kt = 0; kt < nkt; kt++) {
        if (kt + 1 < nkt) { CP_WAIT1(); } else { CP_WAIT0(); }
        __syncthreads();
        if (kt + 2 < nkt) loadStage((kt + 2) % 3, (kt + 2) << 6);
        mmaStage(kt % 3);
    }

    const int qr = lane >> 2;
    const int qc = (lane & 3) * 2;
    #pragma unroll
    for (int mt = 0; mt < 2; mt++) {
        const int r0 = m0 + mw + mt * 16 + qr;
        const int r1 = r0 + 8;
        #pragma unroll
        for (int nt = 0; nt < 8; nt++) {
            const int c = n0 + nw + nt * 8 + qc;
            float2 bb = *reinterpret_cast<const float2*>(bias + c);
            float2 o0, o1;
            o0.x = d[mt][nt][0] + bb.x; o0.y = d[mt][nt][1] + bb.y;
            o1.x = d[mt][nt][2] + bb.x; o1.y = d[mt][nt][3] + bb.y;
            if (QKSCALE) {
                const float sc = (c < 1024) ? 0.125f : 1.0f;
                o0.x *= sc; o0.y *= sc; o1.x *= sc; o1.y *= sc;
            }
            if (RES) {
                float2 u0 = *reinterpret_cast<const float2*>(res + (size_t)r0 * N + c);
                float2 u1 = *reinterpret_cast<const float2*>(res + (size_t)r1 * N + c);
                o0.x += u0.x; o0.y += u0.y; o1.x += u1.x; o1.y += u1.y;
            }
            if (OSPLIT) {
                __nv_bfloat162 l0, l1;
                __nv_bfloat162 h0 = splitpair(o0.x, o0.y, l0);
                __nv_bfloat162 h1 = splitpair(o1.x, o1.y, l1);
                *reinterpret_cast<__nv_bfloat162*>(Chi + (size_t)r0 * N + c) = h0;
                *reinterpret_cast<__nv_bfloat162*>(Chi + (size_t)r1 * N + c) = h1;
                *reinterpret_cast<__nv_bfloat162*>(Clo + (size_t)r0 * N + c) = l0;
                *reinterpret_cast<__nv_bfloat162*>(Clo + (size_t)r1 * N + c) = l1;
            } else {
                *reinterpret_cast<float2*>(C + (size_t)r0 * N + c) = o0;
                *reinterpret_cast<float2*>(C + (size_t)r1 * N + c) = o1;
            }
        }
    }
}

// ---------------- 2-product fp16 GEMM (FFN): C = (Ah+Al) @ Bh^T --------------
// A split fp16 (exact), B single-rounded fp16.  2 MMAs + 8 LDSM per warp-K16.
#define G2STG  (3u * GTILE)        // Ah, Al, Bh = 55296
#define G2SMEM (3u * G2STG)        // 165888

template<bool RELU, bool RES, bool OSPLIT>
__global__ __launch_bounds__(256, 1) void gemm_f16_2p(
    const __half* __restrict__ Ahi, const __half* __restrict__ Alo,
    const __half* __restrict__ Bf,
    const float* __restrict__ bias, const float* __restrict__ res,
    float* __restrict__ C, __half* __restrict__ Chi,
    __half* __restrict__ Clo, int N, int K)
{
    extern __shared__ char sm[];
    const int tid = threadIdx.x, wid = tid >> 5, lane = tid & 31;
    const int m0 = blockIdx.y * 128, n0 = blockIdx.x * 128;
    const uint32_t sb = smem_u32(sm);

    const int mw = (wid & 3) * 32;
    const int nw = (wid >> 2) * 64;
    const int lg = lane >> 3, lr = lane & 7;

    float d[2][8][4];
    #pragma unroll
    for (int mt = 0; mt < 2; mt++)
        #pragma unroll
        for (int nt = 0; nt < 8; nt++)
            #pragma unroll
            for (int i = 0; i < 4; i++) d[mt][nt][i] = 0.f;

    const int nkt = K >> 6;

    auto loadStage = [&](int s, int k0) {
        const uint32_t st = sb + (uint32_t)s * G2STG;
        const __half* base0 = Ahi + (size_t)m0 * K + k0;
        const __half* base1 = Alo + (size_t)m0 * K + k0;
        const __half* base2 = Bf  + (size_t)n0 * K + k0;
        #pragma unroll
        for (int i = 0; i < 4; i++) {
            int lin = i * 256 + tid;
            int row = lin >> 3, seg = lin & 7;
            uint32_t off = (uint32_t)row * GPITCH + (uint32_t)seg * 16u;
            const size_t go = (size_t)row * K + seg * 8;
            CP_ASYNC16(st + off,            (const char*)(base0 + go));
            CP_ASYNC16(st + GTILE + off,    (const char*)(base1 + go));
            CP_ASYNC16(st + 2u*GTILE + off, (const char*)(base2 + go));
        }
        CP_COMMIT();
    };

    auto mmaStage = [&](int s) {
        const uint32_t AhS = sb + (uint32_t)s * G2STG;
        const uint32_t AlS = AhS + GTILE;
        const uint32_t BhS = AhS + 2u * GTILE;
        #pragma unroll
        for (int kh = 0; kh < 4; kh++) {
            uint32_t ah[2][4], al[2][4];
            #pragma unroll
            for (int mt = 0; mt < 2; mt++) {
                uint32_t roff = (uint32_t)(mw + mt*16 + lr + ((lg & 1) << 3)) * GPITCH
                              + (uint32_t)(kh*16 + ((lg >> 1) << 3)) * 2u;
                ldmat4(ah[mt], AhS + roff);
                ldmat4(al[mt], AlS + roff);
            }
            #pragma unroll
            for (int bt = 0; bt < 4; bt++) {
                uint32_t roff = (uint32_t)(nw + bt*16 + lr + ((lg & 2) ? 8 : 0)) * GPITCH
                              + (uint32_t)(kh*16 + ((lg & 1) << 3)) * 2u;
                uint32_t bh[4];
                ldmat4(bh, BhS + roff);
                #pragma unroll
                for (int mt = 0; mt < 2; mt++) {
                    mma16816h(d[mt][2*bt+0], ah[mt], bh[0], bh[1]);
                    mma16816h(d[mt][2*bt+0], al[mt], bh[0], bh[1]);
                    mma16816h(d[mt][2*bt+1], ah[mt], bh[2], bh[3]);
                    mma16816h(d[mt][2*bt+1], al[mt], bh[2], bh[3]);
                }
            }
        }
    };

    loadStage(0, 0);
    loadStage(1, 64);
    for (int kt = 0; kt < nkt; kt++) {
        if (kt + 1 < nkt) { CP_WAIT1(); } else { CP_WAIT0(); }
        __syncthreads();
        if (kt + 2 < nkt) loadStage((kt + 2) % 3, (kt + 2) << 6);
        mmaStage(kt % 3);
    }

    const int qr = lane >> 2;
    const int qc = (lane & 3) * 2;
    #pragma unroll
    for (int mt = 0; mt < 2; mt++) {
        const int r0 = m0 + mw + mt * 16 + qr;
        const int r1 = r0 + 8;
        #pragma unroll
        for (int nt = 0; nt < 8; nt++) {
            const int c = n0 + nw + nt * 8 + qc;
            float2 bb = *reinterpret_cast<const float2*>(bias + c);
            float2 o0, o1;
            o0.x = d[mt][nt][0] + bb.x; o0.y = d[mt][nt][1] + bb.y;
            o1.x = d[mt][nt][2] + bb.x; o1.y = d[mt][nt][3] + bb.y;
            if (RELU) {
                o0.x = fmaxf(o0.x, 0.f); o0.y = fmaxf(o0.y, 0.f);
                o1.x = fmaxf(o1.x, 0.f); o1.y = fmaxf(o1.y, 0.f);
            }
            if (RES) {
                float2 u0 = *reinterpret_cast<const float2*>(res + (size_t)r0 * N + c);
                float2 u1 = *reinterpret_cast<const float2*>(res + (size_t)r1 * N + c);
                o0.x += u0.x; o0.y += u0.y; o1.x += u1.x; o1.y += u1.y;
            }
            if (OSPLIT) {
                __half2 l0, l1;
                __half2 h0 = splitpair_h(o0.x, o0.y, l0);
                __half2 h1 = splitpair_h(o1.x, o1.y, l1);
                *reinterpret_cast<__half2*>(Chi + (size_t)r0 * N + c) = h0;
                *reinterpret_cast<__half2*>(Chi + (size_t)r1 * N + c) = h1;
                *reinterpret_cast<__half2*>(Clo + (size_t)r0 * N + c) = l0;
                *reinterpret_cast<__half2*>(Clo + (size_t)r1 * N + c) = l1;
            } else {
                *reinterpret_cast<float2*>(C + (size_t)r0 * N + c) = o0;
                *reinterpret_cast<float2*>(C + (size_t)r1 * N + c) = o1;
            }
        }
    }
}

// ---------------- MMA flash attention (causal), 3-stage KV pipeline ----------
#define APITCH 144u
#define AQ_B   (128u * APITCH)
#define AKV_B  (64u * APITCH)
#define ASTG_B (4u * AKV_B)
#define ASMEM  (2u * AQ_B + 3u * ASTG_B)   // 147456

__global__ __launch_bounds__(256, 1) void flash_mma(
    const __nv_bfloat16* __restrict__ qsph, const __nv_bfloat16* __restrict__ qspl,
    const __nv_bfloat16* __restrict__ vth, const __nv_bfloat16* __restrict__ vtl,
    __nv_bfloat16* __restrict__ ctxh, __nv_bfloat16* __restrict__ ctxl)
{
    extern __shared__ char sm[];
    const int tid = threadIdx.x, wid = tid >> 5, lane = tid & 31;
    const int q0 = (15 - blockIdx.x) * 128;
    const int bh = blockIdx.y, b = bh >> 4, h = bh & 15;
    const int mw = wid * 16;
    const int lg = lane >> 3, lr = lane & 7;
    const int qr = lane >> 2, qc = (lane & 3) * 2;

    const uint32_t sb = smem_u32(sm);
    const uint32_t QH = sb, QL = sb + AQ_B;
    const uint32_t ST = sb + 2u * AQ_B;

    {
        const __nv_bfloat16* qb_h = qsph + (size_t)(b*TSEQ + q0) * QKVROW + h*64;
        const __nv_bfloat16* qb_l = qspl + (size_t)(b*TSEQ + q0) * QKVROW + h*64;
        #pragma unroll
        for (int i = 0; i < 4; i++) {
            int lin = i * 256 + tid;
            int row = lin >> 3, seg = lin & 7;
            uint32_t off = (uint32_t)row * APITCH + (uint32_t)seg * 16u;
            CP_ASYNC16(QH + off, (const char*)(qb_h + (size_t)row * QKVROW) + seg * 16);
            CP_ASYNC16(QL + off, (const char*)(qb_l + (size_t)row * QKVROW) + seg * 16);
        }
        CP_COMMIT();
    }

    auto loadKV = [&](int s, int key0) {
        const uint32_t KHs = ST + (uint32_t)s * ASTG_B;
        const uint32_t KLs = KHs + AKV_B;
        const uint32_t VHs = KHs + 2u * AKV_B;
        const uint32_t VLs = KHs + 3u * AKV_B;
        const __nv_bfloat16* kb_h = qsph + (size_t)(b*TSEQ + key0) * QKVROW + 1024 + h*64;
        const __nv_bfloat16* kb_l = qspl + (size_t)(b*TSEQ + key0) * QKVROW + 1024 + h*64;
        const __nv_bfloat16* vb_h = vth + (size_t)bh * 64 * TSEQ + key0;
        const __nv_bfloat16* vb_l = vtl + (size_t)bh * 64 * TSEQ + key0;
        #pragma unroll
        for (int i = 0; i < 2; i++) {
            int lin = i * 256 + tid;
            int row = lin >> 3, seg = lin & 7;
            uint32_t off = (uint32_t)row * APITCH + (uint32_t)seg * 16u;
            CP_ASYNC16(KHs + off, (const char*)(kb_h + (size_t)row * QKVROW) + seg * 16);
            CP_ASYNC16(KLs + off, (const char*)(kb_l + (size_t)row * QKVROW) + seg * 16);
            CP_ASYNC16(VHs + off, (const char*)(vb_h + (size_t)row * TSEQ) + seg * 16);
            CP_ASYNC16(VLs + off, (const char*)(vb_l + (size_t)row * TSEQ) + seg * 16);
        }
        CP_COMMIT();
    };

    const int nkt = q0 / 64 + 2;
    loadKV(0, 0);
    loadKV(1, 64);
    CP_WAIT1();
    __syncthreads();

    uint32_t qfh[4][4], qfl[4][4];
    #pragma unroll
    for (int kh = 0; kh < 4; kh++) {
        uint32_t roff = (uint32_t)(mw + lr + ((lg & 1) << 3)) * APITCH
                      + (uint32_t)(kh*16 + ((lg >> 1) << 3)) * 2u;
        ldmat4(qfh[kh], QH + roff);
        ldmat4(qfl[kh], QL + roff);
    }

    float o[8][4];
    #pragma unroll
    for (int nt = 0; nt < 8; nt++)
        #pragma unroll
        for (int i = 0; i < 4; i++) o[nt][i] = 0.f;
    float m0r = -1e30f, m1r = -1e30f, l0r = 0.f, l1r = 0.f;

    for (int kt = 0; kt < nkt; kt++) {
        const int key0 = kt * 64;
        if (kt > 0) {
            if (kt + 1 < nkt) { CP_WAIT1(); } else { CP_WAIT0(); }
            __syncthreads();
        }
        if (kt + 2 < nkt) loadKV((kt + 2) % 3, (kt + 2) * 64);

        if (key0 <= q0 + mw + 15) {
            const int s = kt % 3;
            const uint32_t KHs = ST + (uint32_t)s * ASTG_B;
            const uint32_t KLs = KHs + AKV_B;
            const uint32_t VHs = KHs + 2u * AKV_B;
            const uint32_t VLs = KHs + 3u * AKV_B;

            float sc[8][4];
            #pragma unroll
            for (int nt = 0; nt < 8; nt++)
                #pragma unroll
                for (int i = 0; i < 4; i++) sc[nt][i] = 0.f;

            #pragma unroll
            for (int kh = 0; kh < 4; kh++) {
                #pragma unroll
                for (int bt = 0; bt < 4; bt++) {
                    uint32_t roff = (uint32_t)(bt*16 + lr + ((lg & 2) ? 8 : 0)) * APITCH
                                  + (uint32_t)(kh*16 + ((lg & 1) << 3)) * 2u;
                    uint32_t kfh[4], kfl[4];
                    ldmat4(kfh, KHs + roff);
                    ldmat4(kfl, KLs + roff);
                    mma16816(sc[2*bt+0], qfh[kh], kfh[0], kfh[1]);
                    mma16816(sc[2*bt+0], qfh[kh], kfl[0], kfl[1]);
                    mma16816(sc[2*bt+0], qfl[kh], kfh[0], kfh[1]);
                    mma16816(sc[2*bt+1], qfh[kh], kfh[2], kfh[3]);
                    mma16816(sc[2*bt+1], qfh[kh], kfl[2], kfl[3]);
                    mma16816(sc[2*bt+1], qfl[kh], kfh[2], kfh[3]);
                }
            }

            const int row0 = q0 + mw + qr, row1 = row0 + 8;
            if (key0 + 63 > q0 + mw) {
                #pragma unroll
                for (int nt = 0; nt < 8; nt++) {
                    int c0 = key0 + nt*8 + qc;
                    if (c0     > row0) sc[nt][0] = -1e30f;
                    if (c0 + 1 > row0) sc[nt][1] = -1e30f;
                    if (c0     > row1) sc[nt][2] = -1e30f;
                    if (c0 + 1 > row1) sc[nt][3] = -1e30f;
                }
            }

            float mx0 = -1e30f, mx1 = -1e30f;
            #pragma unroll
            for (int nt = 0; nt < 8; nt++) {
                mx0 = fmaxf(mx0, fmaxf(sc[nt][0], sc[nt][1]));
                mx1 = fmaxf(mx1, fmaxf(sc[nt][2], sc[nt][3]));
            }
            mx0 = fmaxf(mx0, __shfl_xor_sync(0xffffffffu, mx0, 1));
            mx0 = fmaxf(mx0, __shfl_xor_sync(0xffffffffu, mx0, 2));
            mx1 = fmaxf(mx1, __shfl_xor_sync(0xffffffffu, mx1, 1));
            mx1 = fmaxf(mx1, __shfl_xor_sync(0xffffffffu, mx1, 2));
            float mn0 = fmaxf(m0r, mx0), mn1 = fmaxf(m1r, mx1);
            float a0 = __expf(m0r - mn0), a1 = __expf(m1r - mn1);
            float sum0 = 0.f, sum1 = 0.f;
            #pragma unroll
            for (int nt = 0; nt < 8; nt++) {
                sc[nt][0] = __expf(sc[nt][0] - mn0);
                sc[nt][1] = __expf(sc[nt][1] - mn0);
                sc[nt][2] = __expf(sc[nt][2] - mn1);
                sc[nt][3] = __expf(sc[nt][3] - mn1);
                sum0 += sc[nt][0] + sc[nt][1];
                sum1 += sc[nt][2] + sc[nt][3];
            }
            sum0 += __shfl_xor_sync(0xffffffffu, sum0, 1);
            sum0 += __shfl_xor_sync(0xffffffffu, sum0, 2);
            sum1 += __shfl_xor_sync(0xffffffffu, sum1, 1);
            sum1 += __shfl_xor_sync(0xffffffffu, sum1, 2);
            l0r = l0r * a0 + sum0;
            l1r = l1r * a1 + sum1;
            m0r = mn0; m1r = mn1;
            #pragma unroll
            for (int nt = 0; nt < 8; nt++) {
                o[nt][0] *= a0; o[nt][1] *= a0;
                o[nt][2] *= a1; o[nt][3] *= a1;
            }

            #pragma unroll
            for (int kh2 = 0; kh2 < 4; kh2++) {
                const int n0t = 2 * kh2, n1t = 2 * kh2 + 1;
                uint32_t pah[4], pal[4];
                {
                    __nv_bfloat162 e0, e1, e2, e3;
                    __nv_bfloat162 h0 = splitpair(sc[n0t][0], sc[n0t][1], e0);
                    __nv_bfloat162 h1 = splitpair(sc[n0t][2], sc[n0t][3], e1);
                    __nv_bfloat162 h2 = splitpair(sc[n1t][0], sc[n1t][1], e2);
                    __nv_bfloat162 h3 = splitpair(sc[n1t][2], sc[n1t][3], e3);
                    pah[0] = b2u(h0); pah[1] = b2u(h1); pah[2] = b2u(h2); pah[3] = b2u(h3);
                    pal[0] = b2u(e0); pal[1] = b2u(e1); pal[2] = b2u(e2); pal[3] = b2u(e3);
                }
                #pragma unroll
                for (int bt = 0; bt < 4; bt++) {
                    uint32_t roff = (uint32_t)(bt*16 + lr + ((lg & 2) ? 8 : 0)) * APITCH
                                  + (uint32_t)(kh2*16 + ((lg & 1) << 3)) * 2u;
                    uint32_t vfh[4], vfl[4];
                    ldmat4(vfh, VHs + roff);
                    ldmat4(vfl, VLs + roff);
                    mma16816(o[2*bt+0], pah, vfh[0], vfh[1]);
                    mma16816(o[2*bt+0], pal, vfh[0], vfh[1]);
                    mma16816(o[2*bt+0], pah, vfl[0], vfl[1]);
                    mma16816(o[2*bt+1], pah, vfh[2], vfh[3]);
                    mma16816(o[2*bt+1], pal, vfh[2], vfh[3]);
                    mma16816(o[2*bt+1], pah, vfl[2], vfl[3]);
                }
            }
        }
    }

    const float inv0 = 1.f / l0r, inv1 = 1.f / l1r;
    const int row0 = q0 + mw + qr, row1 = row0 + 8;
    const size_t o0 = (size_t)(b*TSEQ + row0) * DMODEL + h*64;
    const size_t o1 = (size_t)(b*TSEQ + row1) * DMODEL + h*64;
    #pragma unroll
    for (int nt = 0; nt < 8; nt++) {
        int col = nt*8 + qc;
        __nv_bfloat162 l0, l1;
        __nv_bfloat162 h0 = splitpair(o[nt][0] * inv0, o[nt][1] * inv0, l0);
        __nv_bfloat162 h1 = splitpair(o[nt][2] * inv1, o[nt][3] * inv1, l1);
        *reinterpret_cast<__nv_bfloat162*>(ctxh + o0 + col) = h0;
        *reinterpret_cast<__nv_bfloat162*>(ctxh + o1 + col) = h1;
        *reinterpret_cast<__nv_bfloat162*>(ctxl + o0 + col) = l0;
        *reinterpret_cast<__nv_bfloat162*>(ctxl + o1 + col) = l1;
    }
}

// ---------------- launch ------------------------------------------------------
extern "C" void kernel_launch(void* const* d_in, const int* in_sizes, int n_in,
                              void* d_out, int out_size)
{
    (void)in_sizes; (void)n_in; (void)out_size;
    const float* X     = (const float*)d_in[0];
    const float* Wqkv  = (const float*)d_in[1];
    const float* bqkv  = (const float*)d_in[2];
    const float* Wo    = (const float*)d_in[3];
    const float* bo    = (const float*)d_in[4];
    const float* W1    = (const float*)d_in[5];
    const float* b1    = (const float*)d_in[6];
    const float* W2    = (const float*)d_in[7];
    const float* b2    = (const float*)d_in[8];
    const float* ln1g  = (const float*)d_in[9];
    const float* ln1b  = (const float*)d_in[10];
    const float* ln2g  = (const float*)d_in[11];
    const float* ln2b  = (const float*)d_in[12];
    float* out = (float*)d_out;

    float* x1;
    cudaGetSymbolAddress((void**)&x1, g_x1);

    __nv_bfloat16 *xnh, *xnl, *ctxh, *ctxl, *qsph, *qspl;
    cudaGetSymbolAddress((void**)&xnh,  g_xnh);
    cudaGetSymbolAddress((void**)&xnl,  g_xnl);
    cudaGetSymbolAddress((void**)&ctxh, g_ctxh);
    cudaGetSymbolAddress((void**)&ctxl, g_ctxl);
    cudaGetSymbolAddress((void**)&qsph, g_qsph);
    cudaGetSymbolAddress((void**)&qspl, g_qspl);

    __half *xn2h, *xn2l, *hh, *hl, *w1f, *w2f;
    cudaGetSymbolAddress((void**)&xn2h, g_xn2h);
    cudaGetSymbolAddress((void**)&xn2l, g_xn2l);
    cudaGetSymbolAddress((void**)&hh,   g_hh);
    cudaGetSymbolAddress((void**)&hl,   g_hl);
    cudaGetSymbolAddress((void**)&w1f,  g_w1f);
    cudaGetSymbolAddress((void**)&w2f,  g_w2f);

    __nv_bfloat16 *wqkv_hi, *wqkv_lo, *wo_hi, *wo_lo, *vth, *vtl;
    cudaGetSymbolAddress((void**)&wqkv_hi, g_wqkv_hi);
    cudaGetSymbolAddress((void**)&wqkv_lo, g_wqkv_lo);
    cudaGetSymbolAddress((void**)&wo_hi,   g_wo_hi);
    cudaGetSymbolAddress((void**)&wo_lo,   g_wo_lo);
    cudaGetSymbolAddress((void**)&vth,     g_vth);
    cudaGetSymbolAddress((void**)&vtl,     g_vtl);

    cudaFuncSetAttribute(gemm_b16<false,true,true>,  cudaFuncAttributeMaxDynamicSharedMemorySize, GSMEM);
    cudaFuncSetAttribute(gemm_b16<true,false,false>, cudaFuncAttributeMaxDynamicSharedMemorySize, GSMEM);
    cudaFuncSetAttribute(gemm_f16_2p<true,false,true>,  cudaFuncAttributeMaxDynamicSharedMemorySize, G2SMEM);
    cudaFuncSetAttribute(gemm_f16_2p<false,true,false>, cudaFuncAttributeMaxDynamicSharedMemorySize, G2SMEM);
    cudaFuncSetAttribute(flash_mma, cudaFuncAttributeMaxDynamicSharedMemorySize, ASMEM);

    // weight transpose + convert
    wconv<<<dim3(QKVROW/32, DMODEL/32), 256>>>(Wqkv, wqkv_hi, wqkv_lo, DMODEL, QKVROW);
    wconv<<<dim3(DMODEL/32, DMODEL/32), 256>>>(Wo,   wo_hi,   wo_lo,   DMODEL, DMODEL);
    wconv_f16<<<dim3(DFF/32,    DMODEL/32), 256>>>(W1, w1f, DMODEL, DFF);
    wconv_f16<<<dim3(DMODEL/32, DFF/32),    256>>>(W2, w2f, DFF,    DMODEL);

    // 1. LN1 -> split bf16
    ln_split<false><<<NTOK, 256>>>(X, ln1g, ln1b, xnh, xnl);
    // 2. QKV -> split bf16, Q cols pre-scaled by 1/8
    gemm_b16<false,true,true><<<dim3(QKVROW/128, NTOK/128), 256, GSMEM>>>(
        xnh, xnl, wqkv_hi, wqkv_lo, bqkv, nullptr, nullptr, qsph, qspl, QKVROW, DMODEL);
    // 3a. V transpose (split-preserving)
    vtrans<<<dim3(TSEQ/32, DKEY/32, BATCH*NHEADS), 256>>>(qsph, qspl, vth, vtl);
    // 3b. MMA flash attention -> split bf16 ctx
    flash_mma<<<dim3(TSEQ/128, BATCH*NHEADS), 256, ASMEM>>>(qsph, qspl, vth, vtl, ctxh, ctxl);
    // 4. x1 = ctx @ Wo + bo + X  (fp32 out)
    gemm_b16<true,false,false><<<dim3(DMODEL/128, NTOK/128), 256, GSMEM>>>(
        ctxh, ctxl, wo_hi, wo_lo, bo, X, x1, nullptr, nullptr, DMODEL, DMODEL);
    // 5. LN2 -> split fp16
    ln_split<true><<<NTOK, 256>>>(x1, ln2g, ln2b, xn2h, xn2l);
    // 6. h = relu(xn2 @ W1 + b1)  (2-product fp16, split fp16 out)
    gemm_f16_2p<true,false,true><<<dim3(DFF/128, NTOK/128), 256, G2SMEM>>>(
        xn2h, xn2l, w1f, b1, nullptr, nullptr, hh, hl, DFF, DMODEL);
    // 7. out = h @ W2 + b2 + x1  (2-product fp16, fp32 out)
    gemm_f16_2p<false,true,false><<<dim3(DMODEL/128, NTOK/128), 256, G2SMEM>>>(
        hh, hl, w2f, b2, x1, out, nullptr, nullptr, DMODEL, DFF);
}

// round 9
// speedup vs baseline: 5.0290x; 1.1734x over previous
#include <cuda_runtime.h>
#include <cuda_fp16.h>
#include <cstdint>
#include <cstddef>

// Problem constants
#define BATCH   2
#define TSEQ    2048
#define DMODEL  1024
#define NHEADS  16
#define DKEY    64
#define DFF     4096
#define NTOK    (BATCH*TSEQ)          // 4096
#define QKVROW  (3*NHEADS*DKEY)       // 3072

// ---------------- scratch ----------------------------------------------------
__device__ float g_x1  [(size_t)NTOK*DMODEL];

// fp16 split activations
__device__ __half g_xnh [(size_t)NTOK*DMODEL];
__device__ __half g_xnl [(size_t)NTOK*DMODEL];
__device__ __half g_xn2h[(size_t)NTOK*DMODEL];
__device__ __half g_xn2l[(size_t)NTOK*DMODEL];
__device__ __half g_ctxh[(size_t)NTOK*DMODEL];
__device__ __half g_ctxl[(size_t)NTOK*DMODEL];
__device__ __half g_hh  [(size_t)NTOK*DFF];
__device__ __half g_hl  [(size_t)NTOK*DFF];

// qkv split output: [tok][3072] (Q scaled by 1/8 in cols 0..1023)
__device__ __half g_qsph[(size_t)NTOK*QKVROW];
__device__ __half g_qspl[(size_t)NTOK*QKVROW];

// single-fp16 transposed weights [N, K] K-major
__device__ __half g_wqkvf[(size_t)QKVROW*DMODEL];
__device__ __half g_wof  [(size_t)DMODEL*DMODEL];
__device__ __half g_w1f  [(size_t)DFF*DMODEL];
__device__ __half g_w2f  [(size_t)DMODEL*DFF];

// V transposed per (b,h): [bh][d][t], single fp16
__device__ __half g_vtf[(size_t)BATCH*NHEADS*DKEY*TSEQ];

// ---------------- helpers ----------------------------------------------------
__device__ __forceinline__ uint32_t smem_u32(const void* p) {
    uint32_t a;
    asm("{ .reg .u64 t; cvta.to.shared.u64 t, %1; cvt.u32.u64 %0, t; }"
        : "=r"(a) : "l"(p));
    return a;
}
#define CP_ASYNC16(dst, src) \
    asm volatile("cp.async.cg.shared.global [%0], [%1], 16;" :: "r"(dst), "l"(src) : "memory")
#define CP_COMMIT() asm volatile("cp.async.commit_group;" ::: "memory")
#define CP_WAIT0()  asm volatile("cp.async.wait_group 0;"  ::: "memory")
#define CP_WAIT1()  asm volatile("cp.async.wait_group 1;"  ::: "memory")

__device__ __forceinline__ void ldmat4(uint32_t (&r)[4], uint32_t addr) {
    asm volatile("ldmatrix.sync.aligned.m8n8.x4.shared.b16 {%0,%1,%2,%3}, [%4];"
        : "=r"(r[0]), "=r"(r[1]), "=r"(r[2]), "=r"(r[3]) : "r"(addr));
}
__device__ __forceinline__ void mma16816h(float (&d)[4], const uint32_t (&a)[4],
                                          const uint32_t b0, const uint32_t b1) {
    asm volatile("mma.sync.aligned.m16n8k16.row.col.f32.f16.f16.f32 "
        "{%0,%1,%2,%3}, {%4,%5,%6,%7}, {%8,%9}, {%0,%1,%2,%3};"
        : "+f"(d[0]), "+f"(d[1]), "+f"(d[2]), "+f"(d[3])
        : "r"(a[0]), "r"(a[1]), "r"(a[2]), "r"(a[3]), "r"(b0), "r"(b1));
}
__device__ __forceinline__ uint32_t h2u(__half2 v) {
    union { __half2 h; uint32_t u; } c; c.h = v; return c.u;
}
__device__ __forceinline__ __half2 splitpair_h(float x, float y, __half2& lo) {
    __half hx = __float2half_rn(x);
    __half hy = __float2half_rn(y);
    lo = __floats2half2_rn(x - __half2float(hx), y - __half2float(hy));
    __half2 hi; hi.x = hx; hi.y = hy;
    return hi;
}

// ---------------- LayerNorm with split-fp16 output ---------------------------
__inline__ __device__ float warp_sum(float v) {
    #pragma unroll
    for (int o = 16; o > 0; o >>= 1) v += __shfl_xor_sync(0xffffffffu, v, o);
    return v;
}

__global__ __launch_bounds__(256) void ln_split(
    const float* __restrict__ x, const float* __restrict__ g,
    const float* __restrict__ b,
    __half* __restrict__ yh, __half* __restrict__ yl)
{
    const int row = blockIdx.x;
    const int tid = threadIdx.x;
    const float* xr = x + (size_t)row * DMODEL;

    float4 v = reinterpret_cast<const float4*>(xr)[tid];
    float s  = v.x + v.y + v.z + v.w;
    float sq = v.x*v.x + v.y*v.y + v.z*v.z + v.w*v.w;

    __shared__ float sh_s[8], sh_q[8];
    float ws = warp_sum(s), wq = warp_sum(sq);
    int warp = tid >> 5, lane = tid & 31;
    if (lane == 0) { sh_s[warp] = ws; sh_q[warp] = wq; }
    __syncthreads();
    __shared__ float sh_mean, sh_rstd;
    if (tid == 0) {
        float ts = 0.f, tq = 0.f;
        #pragma unroll
        for (int i = 0; i < 8; i++) { ts += sh_s[i]; tq += sh_q[i]; }
        float mean = ts * (1.0f / DMODEL);
        float var  = tq * (1.0f / DMODEL) - mean * mean;
        sh_mean = mean; sh_rstd = rsqrtf(var + 1e-5f);
    }
    __syncthreads();
    float mean = sh_mean, rstd = sh_rstd;

    float4 gv = reinterpret_cast<const float4*>(g)[tid];
    float4 bv = reinterpret_cast<const float4*>(b)[tid];
    float ox = (v.x - mean) * rstd * gv.x + bv.x;
    float oy = (v.y - mean) * rstd * gv.y + bv.y;
    float oz = (v.z - mean) * rstd * gv.z + bv.z;
    float ow = (v.w - mean) * rstd * gv.w + bv.w;

    __half2 l01, l23;
    __half2 h01 = splitpair_h(ox, oy, l01);
    __half2 h23 = splitpair_h(oz, ow, l23);
    size_t o = (size_t)row * DMODEL + tid * 4;
    *reinterpret_cast<__half2*>(yh + o)     = h01;
    *reinterpret_cast<__half2*>(yh + o + 2) = h23;
    *reinterpret_cast<__half2*>(yl + o)     = l01;
    *reinterpret_cast<__half2*>(yl + o + 2) = l23;
}

// ---------------- weight transpose: W[K,N] -> fp16 [N,K] ---------------------
__global__ __launch_bounds__(256) void wconv_f16(
    const float* __restrict__ W, __half* __restrict__ out, int K, int N)
{
    __shared__ float t[32][33];
    const int n0 = blockIdx.x * 32, k0 = blockIdx.y * 32;
    const int tx = threadIdx.x & 31, ty = threadIdx.x >> 5;
    #pragma unroll
    for (int j = 0; j < 4; j++)
        t[ty + j*8][tx] = W[(size_t)(k0 + ty + j*8) * N + n0 + tx];
    __syncthreads();
    #pragma unroll
    for (int j = 0; j < 4; j++) {
        int n = ty + j*8;
        out[(size_t)(n0 + n) * K + k0 + tx] = __float2half_rn(t[tx][n]);
    }
}

// ---------------- V transpose (single fp16) ----------------------------------
__global__ __launch_bounds__(256) void vtrans(
    const __half* __restrict__ qsph, __half* __restrict__ vt)
{
    __shared__ __half t[32][40];
    const int t0 = blockIdx.x * 32, d0 = blockIdx.y * 32;
    const int bh = blockIdx.z, b = bh >> 4, h = bh & 15;
    const int tx = threadIdx.x & 31, ty = threadIdx.x >> 5;
    #pragma unroll
    for (int j = 0; j < 4; j++) {
        int tt = ty + j*8;
        t[tt][tx] = qsph[(size_t)(b*TSEQ + t0 + tt) * QKVROW + 2048 + h*64 + d0 + tx];
    }
    __syncthreads();
    #pragma unroll
    for (int j = 0; j < 4; j++) {
        int d = ty + j*8;
        vt[((size_t)bh * 64 + d0 + d) * TSEQ + t0 + tx] = t[tx][d];
    }
}

// ---------------- 2-product fp16 GEMM: C = (Ah+Al) @ B^T ---------------------
// A split fp16 (exact), B single-rounded fp16.
#define GPITCH 144u
#define GTILE  (128u * GPITCH)     // 18432
#define G2STG  (3u * GTILE)        // Ah, Al, B = 55296
#define G2SMEM (3u * G2STG)        // 165888

template<bool RELU, bool RES, bool OSPLIT, bool QKSCALE>
__global__ __launch_bounds__(256, 1) void gemm_f16_2p(
    const __half* __restrict__ Ahi, const __half* __restrict__ Alo,
    const __half* __restrict__ Bf,
    const float* __restrict__ bias, const float* __restrict__ res,
    float* __restrict__ C, __half* __restrict__ Chi,
    __half* __restrict__ Clo, int N, int K)
{
    extern __shared__ char sm[];
    const int tid = threadIdx.x, wid = tid >> 5, lane = tid & 31;
    const int m0 = blockIdx.y * 128, n0 = blockIdx.x * 128;
    const uint32_t sb = smem_u32(sm);

    const int mw = (wid & 3) * 32;
    const int nw = (wid >> 2) * 64;
    const int lg = lane >> 3, lr = lane & 7;

    float d[2][8][4];
    #pragma unroll
    for (int mt = 0; mt < 2; mt++)
        #pragma unroll
        for (int nt = 0; nt < 8; nt++)
            #pragma unroll
            for (int i = 0; i < 4; i++) d[mt][nt][i] = 0.f;

    const int nkt = K >> 6;

    auto loadStage = [&](int s, int k0) {
        const uint32_t st = sb + (uint32_t)s * G2STG;
        const __half* base0 = Ahi + (size_t)m0 * K + k0;
        const __half* base1 = Alo + (size_t)m0 * K + k0;
        const __half* base2 = Bf  + (size_t)n0 * K + k0;
        #pragma unroll
        for (int i = 0; i < 4; i++) {
            int lin = i * 256 + tid;
            int row = lin >> 3, seg = lin & 7;
            uint32_t off = (uint32_t)row * GPITCH + (uint32_t)seg * 16u;
            const size_t go = (size_t)row * K + seg * 8;
            CP_ASYNC16(st + off,            (const char*)(base0 + go));
            CP_ASYNC16(st + GTILE + off,    (const char*)(base1 + go));
            CP_ASYNC16(st + 2u*GTILE + off, (const char*)(base2 + go));
        }
        CP_COMMIT();
    };

    auto mmaStage = [&](int s) {
        const uint32_t AhS = sb + (uint32_t)s * G2STG;
        const uint32_t AlS = AhS + GTILE;
        const uint32_t BhS = AhS + 2u * GTILE;
        #pragma unroll
        for (int kh = 0; kh < 4; kh++) {
            uint32_t ah[2][4], al[2][4];
            #pragma unroll
            for (int mt = 0; mt < 2; mt++) {
                uint32_t roff = (uint32_t)(mw + mt*16 + lr + ((lg & 1) << 3)) * GPITCH
                              + (uint32_t)(kh*16 + ((lg >> 1) << 3)) * 2u;
                ldmat4(ah[mt], AhS + roff);
                ldmat4(al[mt], AlS + roff);
            }
            #pragma unroll
            for (int bt = 0; bt < 4; bt++) {
                uint32_t roff = (uint32_t)(nw + bt*16 + lr + ((lg & 2) ? 8 : 0)) * GPITCH
                              + (uint32_t)(kh*16 + ((lg & 1) << 3)) * 2u;
                uint32_t bh[4];
                ldmat4(bh, BhS + roff);
                #pragma unroll
                for (int mt = 0; mt < 2; mt++) {
                    mma16816h(d[mt][2*bt+0], ah[mt], bh[0], bh[1]);
                    mma16816h(d[mt][2*bt+0], al[mt], bh[0], bh[1]);
                    mma16816h(d[mt][2*bt+1], ah[mt], bh[2], bh[3]);
                    mma16816h(d[mt][2*bt+1], al[mt], bh[2], bh[3]);
                }
            }
        }
    };

    loadStage(0, 0);
    loadStage(1, 64);
    for (int kt = 0; kt < nkt; kt++) {
        if (kt + 1 < nkt) { CP_WAIT1(); } else { CP_WAIT0(); }
        __syncthreads();
        if (kt + 2 < nkt) loadStage((kt + 2) % 3, (kt + 2) << 6);
        mmaStage(kt % 3);
    }

    const int qr = lane >> 2;
    const int qc = (lane & 3) * 2;
    #pragma unroll
    for (int mt = 0; mt < 2; mt++) {
        const int r0 = m0 + mw + mt * 16 + qr;
        const int r1 = r0 + 8;
        #pragma unroll
        for (int nt = 0; nt < 8; nt++) {
            const int c = n0 + nw + nt * 8 + qc;
            float2 bb = *reinterpret_cast<const float2*>(bias + c);
            float2 o0, o1;
            o0.x = d[mt][nt][0] + bb.x; o0.y = d[mt][nt][1] + bb.y;
            o1.x = d[mt][nt][2] + bb.x; o1.y = d[mt][nt][3] + bb.y;
            if (QKSCALE) {
                const float sc = (c < 1024) ? 0.125f : 1.0f;
                o0.x *= sc; o0.y *= sc; o1.x *= sc; o1.y *= sc;
            }
            if (RELU) {
                o0.x = fmaxf(o0.x, 0.f); o0.y = fmaxf(o0.y, 0.f);
                o1.x = fmaxf(o1.x, 0.f); o1.y = fmaxf(o1.y, 0.f);
            }
            if (RES) {
                float2 u0 = *reinterpret_cast<const float2*>(res + (size_t)r0 * N + c);
                float2 u1 = *reinterpret_cast<const float2*>(res + (size_t)r1 * N + c);
                o0.x += u0.x; o0.y += u0.y; o1.x += u1.x; o1.y += u1.y;
            }
            if (OSPLIT) {
                __half2 l0, l1;
                __half2 h0 = splitpair_h(o0.x, o0.y, l0);
                __half2 h1 = splitpair_h(o1.x, o1.y, l1);
                *reinterpret_cast<__half2*>(Chi + (size_t)r0 * N + c) = h0;
                *reinterpret_cast<__half2*>(Chi + (size_t)r1 * N + c) = h1;
                *reinterpret_cast<__half2*>(Clo + (size_t)r0 * N + c) = l0;
                *reinterpret_cast<__half2*>(Clo + (size_t)r1 * N + c) = l1;
            } else {
                *reinterpret_cast<float2*>(C + (size_t)r0 * N + c) = o0;
                *reinterpret_cast<float2*>(C + (size_t)r1 * N + c) = o1;
            }
        }
    }
}

// ---------------- MMA flash attention (causal), 2-product fp16 ---------------
// Q split fp16 (regs), K single, V single. 3-stage KV pipeline.
#define APITCH 144u
#define AQ_B   (128u * APITCH)
#define AKV_B  (64u * APITCH)
#define ASTG_B (2u * AKV_B)                // K, V
#define ASMEM  (2u * AQ_B + 3u * ASTG_B)   // 92160

__global__ __launch_bounds__(256, 1) void flash_mma(
    const __half* __restrict__ qsph, const __half* __restrict__ qspl,
    const __half* __restrict__ vtf,
    __half* __restrict__ ctxh, __half* __restrict__ ctxl)
{
    extern __shared__ char sm[];
    const int tid = threadIdx.x, wid = tid >> 5, lane = tid & 31;
    const int q0 = (15 - blockIdx.x) * 128;
    const int bh = blockIdx.y, b = bh >> 4, h = bh & 15;
    const int mw = wid * 16;
    const int lg = lane >> 3, lr = lane & 7;
    const int qr = lane >> 2, qc = (lane & 3) * 2;

    const uint32_t sb = smem_u32(sm);
    const uint32_t QH = sb, QL = sb + AQ_B;
    const uint32_t ST = sb + 2u * AQ_B;

    {
        const __half* qb_h = qsph + (size_t)(b*TSEQ + q0) * QKVROW + h*64;
        const __half* qb_l = qspl + (size_t)(b*TSEQ + q0) * QKVROW + h*64;
        #pragma unroll
        for (int i = 0; i < 4; i++) {
            int lin = i * 256 + tid;
            int row = lin >> 3, seg = lin & 7;
            uint32_t off = (uint32_t)row * APITCH + (uint32_t)seg * 16u;
            CP_ASYNC16(QH + off, (const char*)(qb_h + (size_t)row * QKVROW) + seg * 16);
            CP_ASYNC16(QL + off, (const char*)(qb_l + (size_t)row * QKVROW) + seg * 16);
        }
        CP_COMMIT();
    }

    auto loadKV = [&](int s, int key0) {
        const uint32_t Ks = ST + (uint32_t)s * ASTG_B;
        const uint32_t Vs = Ks + AKV_B;
        const __half* kb = qsph + (size_t)(b*TSEQ + key0) * QKVROW + 1024 + h*64;
        const __half* vb = vtf + (size_t)bh * 64 * TSEQ + key0;
        #pragma unroll
        for (int i = 0; i < 2; i++) {
            int lin = i * 256 + tid;
            int row = lin >> 3, seg = lin & 7;
            uint32_t off = (uint32_t)row * APITCH + (uint32_t)seg * 16u;
            CP_ASYNC16(Ks + off, (const char*)(kb + (size_t)row * QKVROW) + seg * 16);
            CP_ASYNC16(Vs + off, (const char*)(vb + (size_t)row * TSEQ) + seg * 16);
        }
        CP_COMMIT();
    };

    const int nkt = q0 / 64 + 2;
    loadKV(0, 0);
    loadKV(1, 64);
    CP_WAIT1();
    __syncthreads();

    uint32_t qfh[4][4], qfl[4][4];
    #pragma unroll
    for (int kh = 0; kh < 4; kh++) {
        uint32_t roff = (uint32_t)(mw + lr + ((lg & 1) << 3)) * APITCH
                      + (uint32_t)(kh*16 + ((lg >> 1) << 3)) * 2u;
        ldmat4(qfh[kh], QH + roff);
        ldmat4(qfl[kh], QL + roff);
    }

    float o[8][4];
    #pragma unroll
    for (int nt = 0; nt < 8; nt++)
        #pragma unroll
        for (int i = 0; i < 4; i++) o[nt][i] = 0.f;
    float m0r = -1e30f, m1r = -1e30f, l0r = 0.f, l1r = 0.f;

    for (int kt = 0; kt < nkt; kt++) {
        const int key0 = kt * 64;
        if (kt > 0) {
            if (kt + 1 < nkt) { CP_WAIT1(); } else { CP_WAIT0(); }
            __syncthreads();
        }
        if (kt + 2 < nkt) loadKV((kt + 2) % 3, (kt + 2) * 64);

        if (key0 <= q0 + mw + 15) {
            const int s = kt % 3;
            const uint32_t Ks = ST + (uint32_t)s * ASTG_B;
            const uint32_t Vs = Ks + AKV_B;

            float sc[8][4];
            #pragma unroll
            for (int nt = 0; nt < 8; nt++)
                #pragma unroll
                for (int i = 0; i < 4; i++) sc[nt][i] = 0.f;

            #pragma unroll
            for (int kh = 0; kh < 4; kh++) {
                #pragma unroll
                for (int bt = 0; bt < 4; bt++) {
                    uint32_t roff = (uint32_t)(bt*16 + lr + ((lg & 2) ? 8 : 0)) * APITCH
                                  + (uint32_t)(kh*16 + ((lg & 1) << 3)) * 2u;
                    uint32_t kf[4];
                    ldmat4(kf, Ks + roff);
                    mma16816h(sc[2*bt+0], qfh[kh], kf[0], kf[1]);
                    mma16816h(sc[2*bt+0], qfl[kh], kf[0], kf[1]);
                    mma16816h(sc[2*bt+1], qfh[kh], kf[2], kf[3]);
                    mma16816h(sc[2*bt+1], qfl[kh], kf[2], kf[3]);
                }
            }

            const int row0 = q0 + mw + qr, row1 = row0 + 8;
            if (key0 + 63 > q0 + mw) {
                #pragma unroll
                for (int nt = 0; nt < 8; nt++) {
                    int c0 = key0 + nt*8 + qc;
                    if (c0     > row0) sc[nt][0] = -1e30f;
                    if (c0 + 1 > row0) sc[nt][1] = -1e30f;
                    if (c0     > row1) sc[nt][2] = -1e30f;
                    if (c0 + 1 > row1) sc[nt][3] = -1e30f;
                }
            }

            float mx0 = -1e30f, mx1 = -1e30f;
            #pragma unroll
            for (int nt = 0; nt < 8; nt++) {
                mx0 = fmaxf(mx0, fmaxf(sc[nt][0], sc[nt][1]));
                mx1 = fmaxf(mx1, fmaxf(sc[nt][2], sc[nt][3]));
            }
            mx0 = fmaxf(mx0, __shfl_xor_sync(0xffffffffu, mx0, 1));
            mx0 = fmaxf(mx0, __shfl_xor_sync(0xffffffffu, mx0, 2));
            mx1 = fmaxf(mx1, __shfl_xor_sync(0xffffffffu, mx1, 1));
            mx1 = fmaxf(mx1, __shfl_xor_sync(0xffffffffu, mx1, 2));
            float mn0 = fmaxf(m0r, mx0), mn1 = fmaxf(m1r, mx1);
            float a0 = __expf(m0r - mn0), a1 = __expf(m1r - mn1);
            float sum0 = 0.f, sum1 = 0.f;
            #pragma unroll
            for (int nt = 0; nt < 8; nt++) {
                sc[nt][0] = __expf(sc[nt][0] - mn0);
                sc[nt][1] = __expf(sc[nt][1] - mn0);
                sc[nt][2] = __expf(sc[nt][2] - mn1);
                sc[nt][3] = __expf(sc[nt][3] - mn1);
                sum0 += sc[nt][0] + sc[nt][1];
                sum1 += sc[nt][2] + sc[nt][3];
            }
            sum0 += __shfl_xor_sync(0xffffffffu, sum0, 1);
            sum0 += __shfl_xor_sync(0xffffffffu, sum0, 2);
            sum1 += __shfl_xor_sync(0xffffffffu, sum1, 1);
            sum1 += __shfl_xor_sync(0xffffffffu, sum1, 2);
            l0r = l0r * a0 + sum0;
            l1r = l1r * a1 + sum1;
            m0r = mn0; m1r = mn1;
            #pragma unroll
            for (int nt = 0; nt < 8; nt++) {
                o[nt][0] *= a0; o[nt][1] *= a0;
                o[nt][2] *= a1; o[nt][3] *= a1;
            }

            #pragma unroll
            for (int kh2 = 0; kh2 < 4; kh2++) {
                const int n0t = 2 * kh2, n1t = 2 * kh2 + 1;
                uint32_t pah[4], pal[4];
                {
                    __half2 e0, e1, e2, e3;
                    __half2 h0 = splitpair_h(sc[n0t][0], sc[n0t][1], e0);
                    __half2 h1 = splitpair_h(sc[n0t][2], sc[n0t][3], e1);
                    __half2 h2 = splitpair_h(sc[n1t][0], sc[n1t][1], e2);
                    __half2 h3 = splitpair_h(sc[n1t][2], sc[n1t][3], e3);
                    pah[0] = h2u(h0); pah[1] = h2u(h1); pah[2] = h2u(h2); pah[3] = h2u(h3);
                    pal[0] = h2u(e0); pal[1] = h2u(e1); pal[2] = h2u(e2); pal[3] = h2u(e3);
                }
                #pragma unroll
                for (int bt = 0; bt < 4; bt++) {
                    uint32_t roff = (uint32_t)(bt*16 + lr + ((lg & 2) ? 8 : 0)) * APITCH
                                  + (uint32_t)(kh2*16 + ((lg & 1) << 3)) * 2u;
                    uint32_t vf[4];
                    ldmat4(vf, Vs + roff);
                    mma16816h(o[2*bt+0], pah, vf[0], vf[1]);
                    mma16816h(o[2*bt+0], pal, vf[0], vf[1]);
                    mma16816h(o[2*bt+1], pah, vf[2], vf[3]);
                    mma16816h(o[2*bt+1], pal, vf[2], vf[3]);
                }
            }
        }
    }

    // ---- normalize + split-store ----
    const float inv0 = 1.f / l0r, inv1 = 1.f / l1r;
    const int row0 = q0 + mw + qr, row1 = row0 + 8;
    const size_t o0 = (size_t)(b*TSEQ + row0) * DMODEL + h*64;
    const size_t o1 = (size_t)(b*TSEQ + row1) * DMODEL + h*64;
    #pragma unroll
    for (int nt = 0; nt < 8; nt++) {
        int col = nt*8 + qc;
        __half2 l0, l1;
        __half2 h0 = splitpair_h(o[nt][0] * inv0, o[nt][1] * inv0, l0);
        __half2 h1 = splitpair_h(o[nt][2] * inv1, o[nt][3] * inv1, l1);
        *reinterpret_cast<__half2*>(ctxh + o0 + col) = h0;
        *reinterpret_cast<__half2*>(ctxh + o1 + col) = h1;
        *reinterpret_cast<__half2*>(ctxl + o0 + col) = l0;
        *reinterpret_cast<__half2*>(ctxl + o1 + col) = l1;
    }
}

// ---------------- launch ------------------------------------------------------
extern "C" void kernel_launch(void* const* d_in, const int* in_sizes, int n_in,
                              void* d_out, int out_size)
{
    (void)in_sizes; (void)n_in; (void)out_size;
    const float* X     = (const float*)d_in[0];
    const float* Wqkv  = (const float*)d_in[1];
    const float* bqkv  = (const float*)d_in[2];
    const float* Wo    = (const float*)d_in[3];
    const float* bo    = (const float*)d_in[4];
    const float* W1    = (const float*)d_in[5];
    const float* b1    = (const float*)d_in[6];
    const float* W2    = (const float*)d_in[7];
    const float* b2    = (const float*)d_in[8];
    const float* ln1g  = (const float*)d_in[9];
    const float* ln1b  = (const float*)d_in[10];
    const float* ln2g  = (const float*)d_in[11];
    const float* ln2b  = (const float*)d_in[12];
    float* out = (float*)d_out;

    float* x1;
    cudaGetSymbolAddress((void**)&x1, g_x1);

    __half *xnh, *xnl, *xn2h, *xn2l, *ctxh, *ctxl, *hh, *hl, *qsph, *qspl;
    __half *wqkvf, *wof, *w1f, *w2f, *vtf;
    cudaGetSymbolAddress((void**)&xnh,   g_xnh);
    cudaGetSymbolAddress((void**)&xnl,   g_xnl);
    cudaGetSymbolAddress((void**)&xn2h,  g_xn2h);
    cudaGetSymbolAddress((void**)&xn2l,  g_xn2l);
    cudaGetSymbolAddress((void**)&ctxh,  g_ctxh);
    cudaGetSymbolAddress((void**)&ctxl,  g_ctxl);
    cudaGetSymbolAddress((void**)&hh,    g_hh);
    cudaGetSymbolAddress((void**)&hl,    g_hl);
    cudaGetSymbolAddress((void**)&qsph,  g_qsph);
    cudaGetSymbolAddress((void**)&qspl,  g_qspl);
    cudaGetSymbolAddress((void**)&wqkvf, g_wqkvf);
    cudaGetSymbolAddress((void**)&wof,   g_wof);
    cudaGetSymbolAddress((void**)&w1f,   g_w1f);
    cudaGetSymbolAddress((void**)&w2f,   g_w2f);
    cudaGetSymbolAddress((void**)&vtf,   g_vtf);

    cudaFuncSetAttribute(gemm_f16_2p<false,false,true,true>, cudaFuncAttributeMaxDynamicSharedMemorySize, G2SMEM);
    cudaFuncSetAttribute(gemm_f16_2p<false,true,false,false>, cudaFuncAttributeMaxDynamicSharedMemorySize, G2SMEM);
    cudaFuncSetAttribute(gemm_f16_2p<true,false,true,false>,  cudaFuncAttributeMaxDynamicSharedMemorySize, G2SMEM);
    cudaFuncSetAttribute(flash_mma, cudaFuncAttributeMaxDynamicSharedMemorySize, ASMEM);

    // weight transpose + convert to fp16
    wconv_f16<<<dim3(QKVROW/32, DMODEL/32), 256>>>(Wqkv, wqkvf, DMODEL, QKVROW);
    wconv_f16<<<dim3(DMODEL/32, DMODEL/32), 256>>>(Wo,   wof,   DMODEL, DMODEL);
    wconv_f16<<<dim3(DFF/32,    DMODEL/32), 256>>>(W1,   w1f,   DMODEL, DFF);
    wconv_f16<<<dim3(DMODEL/32, DFF/32),    256>>>(W2,   w2f,   DFF,    DMODEL);

    // 1. LN1 -> split fp16
    ln_split<<<NTOK, 256>>>(X, ln1g, ln1b, xnh, xnl);
    // 2. QKV -> split fp16, Q cols pre-scaled by 1/8
    gemm_f16_2p<false,false,true,true><<<dim3(QKVROW/128, NTOK/128), 256, G2SMEM>>>(
        xnh, xnl, wqkvf, bqkv, nullptr, nullptr, qsph, qspl, QKVROW, DMODEL);
    // 3a. V transpose (single fp16)
    vtrans<<<dim3(TSEQ/32, DKEY/32, BATCH*NHEADS), 256>>>(qsph, vtf);
    // 3b. MMA flash attention -> split fp16 ctx
    flash_mma<<<dim3(TSEQ/128, BATCH*NHEADS), 256, ASMEM>>>(qsph, qspl, vtf, ctxh, ctxl);
    // 4. x1 = ctx @ Wo + bo + X  (fp32 out)
    gemm_f16_2p<false,true,false,false><<<dim3(DMODEL/128, NTOK/128), 256, G2SMEM>>>(
        ctxh, ctxl, wof, bo, X, x1, nullptr, nullptr, DMODEL, DMODEL);
    // 5. LN2 -> split fp16
    ln_split<<<NTOK, 256>>>(x1, ln2g, ln2b, xn2h, xn2l);
    // 6. h = relu(xn2 @ W1 + b1)  (split fp16 out)
    gemm_f16_2p<true,false,true,false><<<dim3(DFF/128, NTOK/128), 256, G2SMEM>>>(
        xn2h, xn2l, w1f, b1, nullptr, nullptr, hh, hl, DFF, DMODEL);
    // 7. out = h @ W2 + b2 + x1  (fp32 out)
    gemm_f16_2p<false,true,false,false><<<dim3(DMODEL/128, NTOK/128), 256, G2SMEM>>>(
        hh, hl, w2f, b2, x1, out, nullptr, nullptr, DMODEL, DFF);
}

// round 10
// speedup vs baseline: 7.8478x; 1.5605x over previous
#include <cuda_runtime.h>
#include <cuda_fp16.h>
#include <cstdint>
#include <cstddef>

// Problem constants
#define BATCH   2
#define TSEQ    2048
#define DMODEL  1024
#define NHEADS  16
#define DKEY    64
#define DFF     4096
#define NTOK    (BATCH*TSEQ)          // 4096
#define QKVROW  (3*NHEADS*DKEY)       // 3072

// ---------------- scratch ----------------------------------------------------
__device__ float g_x1  [(size_t)NTOK*DMODEL];

// single fp16 activations
__device__ __half g_xn  [(size_t)NTOK*DMODEL];
__device__ __half g_xn2 [(size_t)NTOK*DMODEL];
__device__ __half g_ctx [(size_t)NTOK*DMODEL];
__device__ __half g_h   [(size_t)NTOK*DFF];

// qkv output: [tok][3072] (Q scaled by 1/8 in cols 0..1023)
__device__ __half g_qsp [(size_t)NTOK*QKVROW];

// single-fp16 transposed weights [N, K] K-major
__device__ __half g_wqkvf[(size_t)QKVROW*DMODEL];
__device__ __half g_wof  [(size_t)DMODEL*DMODEL];
__device__ __half g_w1f  [(size_t)DFF*DMODEL];
__device__ __half g_w2f  [(size_t)DMODEL*DFF];

// V transposed per (b,h): [bh][d][t]
__device__ __half g_vtf[(size_t)BATCH*NHEADS*DKEY*TSEQ];

// ---------------- helpers ----------------------------------------------------
__device__ __forceinline__ uint32_t smem_u32(const void* p) {
    uint32_t a;
    asm("{ .reg .u64 t; cvta.to.shared.u64 t, %1; cvt.u32.u64 %0, t; }"
        : "=r"(a) : "l"(p));
    return a;
}
#define CP_ASYNC16(dst, src) \
    asm volatile("cp.async.cg.shared.global [%0], [%1], 16;" :: "r"(dst), "l"(src) : "memory")
#define CP_COMMIT() asm volatile("cp.async.commit_group;" ::: "memory")
#define CP_WAIT0()  asm volatile("cp.async.wait_group 0;"  ::: "memory")
#define CP_WAIT1()  asm volatile("cp.async.wait_group 1;"  ::: "memory")

__device__ __forceinline__ void ldmat4(uint32_t (&r)[4], uint32_t addr) {
    asm volatile("ldmatrix.sync.aligned.m8n8.x4.shared.b16 {%0,%1,%2,%3}, [%4];"
        : "=r"(r[0]), "=r"(r[1]), "=r"(r[2]), "=r"(r[3]) : "r"(addr));
}
__device__ __forceinline__ void mma16816h(float (&d)[4], const uint32_t (&a)[4],
                                          const uint32_t b0, const uint32_t b1) {
    asm volatile("mma.sync.aligned.m16n8k16.row.col.f32.f16.f16.f32 "
        "{%0,%1,%2,%3}, {%4,%5,%6,%7}, {%8,%9}, {%0,%1,%2,%3};"
        : "+f"(d[0]), "+f"(d[1]), "+f"(d[2]), "+f"(d[3])
        : "r"(a[0]), "r"(a[1]), "r"(a[2]), "r"(a[3]), "r"(b0), "r"(b1));
}
__device__ __forceinline__ uint32_t h2u(__half2 v) {
    union { __half2 h; uint32_t u; } c; c.h = v; return c.u;
}

// ---------------- LayerNorm -> single fp16 -----------------------------------
__inline__ __device__ float warp_sum(float v) {
    #pragma unroll
    for (int o = 16; o > 0; o >>= 1) v += __shfl_xor_sync(0xffffffffu, v, o);
    return v;
}

__global__ __launch_bounds__(256) void ln_f16(
    const float* __restrict__ x, const float* __restrict__ g,
    const float* __restrict__ b, __half* __restrict__ y)
{
    const int row = blockIdx.x;
    const int tid = threadIdx.x;
    const float* xr = x + (size_t)row * DMODEL;

    float4 v = reinterpret_cast<const float4*>(xr)[tid];
    float s  = v.x + v.y + v.z + v.w;
    float sq = v.x*v.x + v.y*v.y + v.z*v.z + v.w*v.w;

    __shared__ float sh_s[8], sh_q[8];
    float ws = warp_sum(s), wq = warp_sum(sq);
    int warp = tid >> 5, lane = tid & 31;
    if (lane == 0) { sh_s[warp] = ws; sh_q[warp] = wq; }
    __syncthreads();
    __shared__ float sh_mean, sh_rstd;
    if (tid == 0) {
        float ts = 0.f, tq = 0.f;
        #pragma unroll
        for (int i = 0; i < 8; i++) { ts += sh_s[i]; tq += sh_q[i]; }
        float mean = ts * (1.0f / DMODEL);
        float var  = tq * (1.0f / DMODEL) - mean * mean;
        sh_mean = mean; sh_rstd = rsqrtf(var + 1e-5f);
    }
    __syncthreads();
    float mean = sh_mean, rstd = sh_rstd;

    float4 gv = reinterpret_cast<const float4*>(g)[tid];
    float4 bv = reinterpret_cast<const float4*>(b)[tid];
    float ox = (v.x - mean) * rstd * gv.x + bv.x;
    float oy = (v.y - mean) * rstd * gv.y + bv.y;
    float oz = (v.z - mean) * rstd * gv.z + bv.z;
    float ow = (v.w - mean) * rstd * gv.w + bv.w;

    size_t o = (size_t)row * DMODEL + tid * 4;
    *reinterpret_cast<__half2*>(y + o)     = __floats2half2_rn(ox, oy);
    *reinterpret_cast<__half2*>(y + o + 2) = __floats2half2_rn(oz, ow);
}

// ---------------- weight transpose: W[K,N] -> fp16 [N,K] ---------------------
__global__ __launch_bounds__(256) void wconv_f16(
    const float* __restrict__ W, __half* __restrict__ out, int K, int N)
{
    __shared__ float t[32][33];
    const int n0 = blockIdx.x * 32, k0 = blockIdx.y * 32;
    const int tx = threadIdx.x & 31, ty = threadIdx.x >> 5;
    #pragma unroll
    for (int j = 0; j < 4; j++)
        t[ty + j*8][tx] = W[(size_t)(k0 + ty + j*8) * N + n0 + tx];
    __syncthreads();
    #pragma unroll
    for (int j = 0; j < 4; j++) {
        int n = ty + j*8;
        out[(size_t)(n0 + n) * K + k0 + tx] = __float2half_rn(t[tx][n]);
    }
}

// ---------------- V transpose ------------------------------------------------
__global__ __launch_bounds__(256) void vtrans(
    const __half* __restrict__ qsp, __half* __restrict__ vt)
{
    __shared__ __half t[32][40];
    const int t0 = blockIdx.x * 32, d0 = blockIdx.y * 32;
    const int bh = blockIdx.z, b = bh >> 4, h = bh & 15;
    const int tx = threadIdx.x & 31, ty = threadIdx.x >> 5;
    #pragma unroll
    for (int j = 0; j < 4; j++) {
        int tt = ty + j*8;
        t[tt][tx] = qsp[(size_t)(b*TSEQ + t0 + tt) * QKVROW + 2048 + h*64 + d0 + tx];
    }
    __syncthreads();
    #pragma unroll
    for (int j = 0; j < 4; j++) {
        int d = ty + j*8;
        vt[((size_t)bh * 64 + d0 + d) * TSEQ + t0 + tx] = t[tx][d];
    }
}

// ---------------- 1-product fp16 GEMM: C = A @ B^T ---------------------------
#define GPITCH 144u
#define GTILE  (128u * GPITCH)     // 18432
#define G1STG  (2u * GTILE)        // A, B = 36864
#define G1SMEM (3u * G1STG)        // 110592

template<bool RELU, bool RES, bool OF16, bool QKSCALE>
__global__ __launch_bounds__(256, 1) void gemm_f16(
    const __half* __restrict__ Af, const __half* __restrict__ Bf,
    const float* __restrict__ bias, const float* __restrict__ res,
    float* __restrict__ C, __half* __restrict__ Ch, int N, int K)
{
    extern __shared__ char sm[];
    const int tid = threadIdx.x, wid = tid >> 5, lane = tid & 31;
    const int m0 = blockIdx.y * 128, n0 = blockIdx.x * 128;
    const uint32_t sb = smem_u32(sm);

    const int mw = (wid & 3) * 32;
    const int nw = (wid >> 2) * 64;
    const int lg = lane >> 3, lr = lane & 7;

    float d[2][8][4];
    #pragma unroll
    for (int mt = 0; mt < 2; mt++)
        #pragma unroll
        for (int nt = 0; nt < 8; nt++)
            #pragma unroll
            for (int i = 0; i < 4; i++) d[mt][nt][i] = 0.f;

    const int nkt = K >> 6;

    auto loadStage = [&](int s, int k0) {
        const uint32_t st = sb + (uint32_t)s * G1STG;
        const __half* base0 = Af + (size_t)m0 * K + k0;
        const __half* base1 = Bf + (size_t)n0 * K + k0;
        #pragma unroll
        for (int i = 0; i < 4; i++) {
            int lin = i * 256 + tid;
            int row = lin >> 3, seg = lin & 7;
            uint32_t off = (uint32_t)row * GPITCH + (uint32_t)seg * 16u;
            const size_t go = (size_t)row * K + seg * 8;
            CP_ASYNC16(st + off,         (const char*)(base0 + go));
            CP_ASYNC16(st + GTILE + off, (const char*)(base1 + go));
        }
        CP_COMMIT();
    };

    auto mmaStage = [&](int s) {
        const uint32_t AS = sb + (uint32_t)s * G1STG;
        const uint32_t BS = AS + GTILE;
        #pragma unroll
        for (int kh = 0; kh < 4; kh++) {
            uint32_t af[2][4];
            #pragma unroll
            for (int mt = 0; mt < 2; mt++) {
                uint32_t roff = (uint32_t)(mw + mt*16 + lr + ((lg & 1) << 3)) * GPITCH
                              + (uint32_t)(kh*16 + ((lg >> 1) << 3)) * 2u;
                ldmat4(af[mt], AS + roff);
            }
            #pragma unroll
            for (int bt = 0; bt < 4; bt++) {
                uint32_t roff = (uint32_t)(nw + bt*16 + lr + ((lg & 2) ? 8 : 0)) * GPITCH
                              + (uint32_t)(kh*16 + ((lg & 1) << 3)) * 2u;
                uint32_t bh[4];
                ldmat4(bh, BS + roff);
                #pragma unroll
                for (int mt = 0; mt < 2; mt++) {
                    mma16816h(d[mt][2*bt+0], af[mt], bh[0], bh[1]);
                    mma16816h(d[mt][2*bt+1], af[mt], bh[2], bh[3]);
                }
            }
        }
    };

    loadStage(0, 0);
    loadStage(1, 64);
    for (int kt = 0; kt < nkt; kt++) {
        if (kt + 1 < nkt) { CP_WAIT1(); } else { CP_WAIT0(); }
        __syncthreads();
        if (kt + 2 < nkt) loadStage((kt + 2) % 3, (kt + 2) << 6);
        mmaStage(kt % 3);
    }

    const int qr = lane >> 2;
    const int qc = (lane & 3) * 2;
    #pragma unroll
    for (int mt = 0; mt < 2; mt++) {
        const int r0 = m0 + mw + mt * 16 + qr;
        const int r1 = r0 + 8;
        #pragma unroll
        for (int nt = 0; nt < 8; nt++) {
            const int c = n0 + nw + nt * 8 + qc;
            float2 bb = *reinterpret_cast<const float2*>(bias + c);
            float2 o0, o1;
            o0.x = d[mt][nt][0] + bb.x; o0.y = d[mt][nt][1] + bb.y;
            o1.x = d[mt][nt][2] + bb.x; o1.y = d[mt][nt][3] + bb.y;
            if (QKSCALE) {
                const float sc = (c < 1024) ? 0.125f : 1.0f;
                o0.x *= sc; o0.y *= sc; o1.x *= sc; o1.y *= sc;
            }
            if (RELU) {
                o0.x = fmaxf(o0.x, 0.f); o0.y = fmaxf(o0.y, 0.f);
                o1.x = fmaxf(o1.x, 0.f); o1.y = fmaxf(o1.y, 0.f);
            }
            if (RES) {
                float2 u0 = *reinterpret_cast<const float2*>(res + (size_t)r0 * N + c);
                float2 u1 = *reinterpret_cast<const float2*>(res + (size_t)r1 * N + c);
                o0.x += u0.x; o0.y += u0.y; o1.x += u1.x; o1.y += u1.y;
            }
            if (OF16) {
                *reinterpret_cast<__half2*>(Ch + (size_t)r0 * N + c) = __floats2half2_rn(o0.x, o0.y);
                *reinterpret_cast<__half2*>(Ch + (size_t)r1 * N + c) = __floats2half2_rn(o1.x, o1.y);
            } else {
                *reinterpret_cast<float2*>(C + (size_t)r0 * N + c) = o0;
                *reinterpret_cast<float2*>(C + (size_t)r1 * N + c) = o1;
            }
        }
    }
}

// ---------------- MMA flash attention (causal), 1-product fp16 ---------------
#define APITCH 144u
#define AQ_B   (128u * APITCH)
#define AKV_B  (64u * APITCH)
#define ASTG_B (2u * AKV_B)                // K, V
#define ASMEM  (AQ_B + 3u * ASTG_B)        // 73728

__global__ __launch_bounds__(256, 1) void flash_mma(
    const __half* __restrict__ qsp, const __half* __restrict__ vtf,
    __half* __restrict__ ctx)
{
    extern __shared__ char sm[];
    const int tid = threadIdx.x, wid = tid >> 5, lane = tid & 31;
    const int q0 = (15 - blockIdx.x) * 128;
    const int bh = blockIdx.y, b = bh >> 4, h = bh & 15;
    const int mw = wid * 16;
    const int lg = lane >> 3, lr = lane & 7;
    const int qr = lane >> 2, qc = (lane & 3) * 2;

    const uint32_t sb = smem_u32(sm);
    const uint32_t QS = sb;
    const uint32_t ST = sb + AQ_B;

    {
        const __half* qb = qsp + (size_t)(b*TSEQ + q0) * QKVROW + h*64;
        #pragma unroll
        for (int i = 0; i < 4; i++) {
            int lin = i * 256 + tid;
            int row = lin >> 3, seg = lin & 7;
            uint32_t off = (uint32_t)row * APITCH + (uint32_t)seg * 16u;
            CP_ASYNC16(QS + off, (const char*)(qb + (size_t)row * QKVROW) + seg * 16);
        }
        CP_COMMIT();
    }

    auto loadKV = [&](int s, int key0) {
        const uint32_t Ks = ST + (uint32_t)s * ASTG_B;
        const uint32_t Vs = Ks + AKV_B;
        const __half* kb = qsp + (size_t)(b*TSEQ + key0) * QKVROW + 1024 + h*64;
        const __half* vb = vtf + (size_t)bh * 64 * TSEQ + key0;
        #pragma unroll
        for (int i = 0; i < 2; i++) {
            int lin = i * 256 + tid;
            int row = lin >> 3, seg = lin & 7;
            uint32_t off = (uint32_t)row * APITCH + (uint32_t)seg * 16u;
            CP_ASYNC16(Ks + off, (const char*)(kb + (size_t)row * QKVROW) + seg * 16);
            CP_ASYNC16(Vs + off, (const char*)(vb + (size_t)row * TSEQ) + seg * 16);
        }
        CP_COMMIT();
    };

    const int nkt = q0 / 64 + 2;
    loadKV(0, 0);
    loadKV(1, 64);
    CP_WAIT1();
    __syncthreads();

    uint32_t qf[4][4];
    #pragma unroll
    for (int kh = 0; kh < 4; kh++) {
        uint32_t roff = (uint32_t)(mw + lr + ((lg & 1) << 3)) * APITCH
                      + (uint32_t)(kh*16 + ((lg >> 1) << 3)) * 2u;
        ldmat4(qf[kh], QS + roff);
    }

    float o[8][4];
    #pragma unroll
    for (int nt = 0; nt < 8; nt++)
        #pragma unroll
        for (int i = 0; i < 4; i++) o[nt][i] = 0.f;
    float m0r = -1e30f, m1r = -1e30f, l0r = 0.f, l1r = 0.f;

    for (int kt = 0; kt < nkt; kt++) {
        const int key0 = kt * 64;
        if (kt > 0) {
            if (kt + 1 < nkt) { CP_WAIT1(); } else { CP_WAIT0(); }
            __syncthreads();
        }
        if (kt + 2 < nkt) loadKV((kt + 2) % 3, (kt + 2) * 64);

        if (key0 <= q0 + mw + 15) {
            const int s = kt % 3;
            const uint32_t Ks = ST + (uint32_t)s * ASTG_B;
            const uint32_t Vs = Ks + AKV_B;

            float sc[8][4];
            #pragma unroll
            for (int nt = 0; nt < 8; nt++)
                #pragma unroll
                for (int i = 0; i < 4; i++) sc[nt][i] = 0.f;

            #pragma unroll
            for (int kh = 0; kh < 4; kh++) {
                #pragma unroll
                for (int bt = 0; bt < 4; bt++) {
                    uint32_t roff = (uint32_t)(bt*16 + lr + ((lg & 2) ? 8 : 0)) * APITCH
                                  + (uint32_t)(kh*16 + ((lg & 1) << 3)) * 2u;
                    uint32_t kf[4];
                    ldmat4(kf, Ks + roff);
                    mma16816h(sc[2*bt+0], qf[kh], kf[0], kf[1]);
                    mma16816h(sc[2*bt+1], qf[kh], kf[2], kf[3]);
                }
            }

            const int row0 = q0 + mw + qr, row1 = row0 + 8;
            if (key0 + 63 > q0 + mw) {
                #pragma unroll
                for (int nt = 0; nt < 8; nt++) {
                    int c0 = key0 + nt*8 + qc;
                    if (c0     > row0) sc[nt][0] = -1e30f;
                    if (c0 + 1 > row0) sc[nt][1] = -1e30f;
                    if (c0     > row1) sc[nt][2] = -1e30f;
                    if (c0 + 1 > row1) sc[nt][3] = -1e30f;
                }
            }

            float mx0 = -1e30f, mx1 = -1e30f;
            #pragma unroll
            for (int nt = 0; nt < 8; nt++) {
                mx0 = fmaxf(mx0, fmaxf(sc[nt][0], sc[nt][1]));
                mx1 = fmaxf(mx1, fmaxf(sc[nt][2], sc[nt][3]));
            }
            mx0 = fmaxf(mx0, __shfl_xor_sync(0xffffffffu, mx0, 1));
            mx0 = fmaxf(mx0, __shfl_xor_sync(0xffffffffu, mx0, 2));
            mx1 = fmaxf(mx1, __shfl_xor_sync(0xffffffffu, mx1, 1));
            mx1 = fmaxf(mx1, __shfl_xor_sync(0xffffffffu, mx1, 2));
            float mn0 = fmaxf(m0r, mx0), mn1 = fmaxf(m1r, mx1);
            float a0 = __expf(m0r - mn0), a1 = __expf(m1r - mn1);
            float sum0 = 0.f, sum1 = 0.f;
            #pragma unroll
            for (int nt = 0; nt < 8; nt++) {
                sc[nt][0] = __expf(sc[nt][0] - mn0);
                sc[nt][1] = __expf(sc[nt][1] - mn0);
                sc[nt][2] = __expf(sc[nt][2] - mn1);
                sc[nt][3] = __expf(sc[nt][3] - mn1);
                sum0 += sc[nt][0] + sc[nt][1];
                sum1 += sc[nt][2] + sc[nt][3];
            }
            sum0 += __shfl_xor_sync(0xffffffffu, sum0, 1);
            sum0 += __shfl_xor_sync(0xffffffffu, sum0, 2);
            sum1 += __shfl_xor_sync(0xffffffffu, sum1, 1);
            sum1 += __shfl_xor_sync(0xffffffffu, sum1, 2);
            l0r = l0r * a0 + sum0;
            l1r = l1r * a1 + sum1;
            m0r = mn0; m1r = mn1;
            #pragma unroll
            for (int nt = 0; nt < 8; nt++) {
                o[nt][0] *= a0; o[nt][1] *= a0;
                o[nt][2] *= a1; o[nt][3] *= a1;
            }

            #pragma unroll
            for (int kh2 = 0; kh2 < 4; kh2++) {
                const int n0t = 2 * kh2, n1t = 2 * kh2 + 1;
                uint32_t pa[4];
                pa[0] = h2u(__floats2half2_rn(sc[n0t][0], sc[n0t][1]));
                pa[1] = h2u(__floats2half2_rn(sc[n0t][2], sc[n0t][3]));
                pa[2] = h2u(__floats2half2_rn(sc[n1t][0], sc[n1t][1]));
                pa[3] = h2u(__floats2half2_rn(sc[n1t][2], sc[n1t][3]));
                #pragma unroll
                for (int bt = 0; bt < 4; bt++) {
                    uint32_t roff = (uint32_t)(bt*16 + lr + ((lg & 2) ? 8 : 0)) * APITCH
                                  + (uint32_t)(kh2*16 + ((lg & 1) << 3)) * 2u;
                    uint32_t vf[4];
                    ldmat4(vf, Vs + roff);
                    mma16816h(o[2*bt+0], pa, vf[0], vf[1]);
                    mma16816h(o[2*bt+1], pa, vf[2], vf[3]);
                }
            }
        }
    }

    // ---- normalize + store ----
    const float inv0 = 1.f / l0r, inv1 = 1.f / l1r;
    const int row0 = q0 + mw + qr, row1 = row0 + 8;
    const size_t o0 = (size_t)(b*TSEQ + row0) * DMODEL + h*64;
    const size_t o1 = (size_t)(b*TSEQ + row1) * DMODEL + h*64;
    #pragma unroll
    for (int nt = 0; nt < 8; nt++) {
        int col = nt*8 + qc;
        *reinterpret_cast<__half2*>(ctx + o0 + col) =
            __floats2half2_rn(o[nt][0] * inv0, o[nt][1] * inv0);
        *reinterpret_cast<__half2*>(ctx + o1 + col) =
            __floats2half2_rn(o[nt][2] * inv1, o[nt][3] * inv1);
    }
}

// ---------------- launch ------------------------------------------------------
extern "C" void kernel_launch(void* const* d_in, const int* in_sizes, int n_in,
                              void* d_out, int out_size)
{
    (void)in_sizes; (void)n_in; (void)out_size;
    const float* X     = (const float*)d_in[0];
    const float* Wqkv  = (const float*)d_in[1];
    const float* bqkv  = (const float*)d_in[2];
    const float* Wo    = (const float*)d_in[3];
    const float* bo    = (const float*)d_in[4];
    const float* W1    = (const float*)d_in[5];
    const float* b1    = (const float*)d_in[6];
    const float* W2    = (const float*)d_in[7];
    const float* b2    = (const float*)d_in[8];
    const float* ln1g  = (const float*)d_in[9];
    const float* ln1b  = (const float*)d_in[10];
    const float* ln2g  = (const float*)d_in[11];
    const float* ln2b  = (const float*)d_in[12];
    float* out = (float*)d_out;

    float* x1;
    cudaGetSymbolAddress((void**)&x1, g_x1);

    __half *xn, *xn2, *ctx, *h, *qsp, *wqkvf, *wof, *w1f, *w2f, *vtf;
    cudaGetSymbolAddress((void**)&xn,    g_xn);
    cudaGetSymbolAddress((void**)&xn2,   g_xn2);
    cudaGetSymbolAddress((void**)&ctx,   g_ctx);
    cudaGetSymbolAddress((void**)&h,     g_h);
    cudaGetSymbolAddress((void**)&qsp,   g_qsp);
    cudaGetSymbolAddress((void**)&wqkvf, g_wqkvf);
    cudaGetSymbolAddress((void**)&wof,   g_wof);
    cudaGetSymbolAddress((void**)&w1f,   g_w1f);
    cudaGetSymbolAddress((void**)&w2f,   g_w2f);
    cudaGetSymbolAddress((void**)&vtf,   g_vtf);

    cudaFuncSetAttribute(gemm_f16<false,false,true,true>,  cudaFuncAttributeMaxDynamicSharedMemorySize, G1SMEM);
    cudaFuncSetAttribute(gemm_f16<false,true,false,false>, cudaFuncAttributeMaxDynamicSharedMemorySize, G1SMEM);
    cudaFuncSetAttribute(gemm_f16<true,false,true,false>,  cudaFuncAttributeMaxDynamicSharedMemorySize, G1SMEM);
    cudaFuncSetAttribute(flash_mma, cudaFuncAttributeMaxDynamicSharedMemorySize, ASMEM);

    // weight transpose + convert to fp16
    wconv_f16<<<dim3(QKVROW/32, DMODEL/32), 256>>>(Wqkv, wqkvf, DMODEL, QKVROW);
    wconv_f16<<<dim3(DMODEL/32, DMODEL/32), 256>>>(Wo,   wof,   DMODEL, DMODEL);
    wconv_f16<<<dim3(DFF/32,    DMODEL/32), 256>>>(W1,   w1f,   DMODEL, DFF);
    wconv_f16<<<dim3(DMODEL/32, DFF/32),    256>>>(W2,   w2f,   DFF,    DMODEL);

    // 1. LN1 -> fp16
    ln_f16<<<NTOK, 256>>>(X, ln1g, ln1b, xn);
    // 2. QKV -> fp16, Q cols pre-scaled by 1/8
    gemm_f16<false,false,true,true><<<dim3(QKVROW/128, NTOK/128), 256, G1SMEM>>>(
        xn, wqkvf, bqkv, nullptr, nullptr, qsp, QKVROW, DMODEL);
    // 3a. V transpose
    vtrans<<<dim3(TSEQ/32, DKEY/32, BATCH*NHEADS), 256>>>(qsp, vtf);
    // 3b. MMA flash attention -> fp16 ctx
    flash_mma<<<dim3(TSEQ/128, BATCH*NHEADS), 256, ASMEM>>>(qsp, vtf, ctx);
    // 4. x1 = ctx @ Wo + bo + X  (fp32 out)
    gemm_f16<false,true,false,false><<<dim3(DMODEL/128, NTOK/128), 256, G1SMEM>>>(
        ctx, wof, bo, X, x1, nullptr, DMODEL, DMODEL);
    // 5. LN2 -> fp16
    ln_f16<<<NTOK, 256>>>(x1, ln2g, ln2b, xn2);
    // 6. h = relu(xn2 @ W1 + b1)  (fp16 out)
    gemm_f16<true,false,true,false><<<dim3(DFF/128, NTOK/128), 256, G1SMEM>>>(
        xn2, w1f, b1, nullptr, nullptr, h, DFF, DMODEL);
    // 7. out = h @ W2 + b2 + x1  (fp32 out)
    gemm_f16<false,true,false,false><<<dim3(DMODEL/128, NTOK/128), 256, G1SMEM>>>(
        h, w2f, b2, x1, out, nullptr, DMODEL, DFF);
}

// round 11
// speedup vs baseline: 8.6522x; 1.1025x over previous
#include <cuda_runtime.h>
#include <cuda_fp16.h>
#include <cstdint>
#include <cstddef>

// Problem constants
#define BATCH   2
#define TSEQ    2048
#define DMODEL  1024
#define NHEADS  16
#define DKEY    64
#define DFF     4096
#define NTOK    (BATCH*TSEQ)          // 4096
#define QKVROW  (3*NHEADS*DKEY)       // 3072

// ---------------- scratch ----------------------------------------------------
__device__ float g_x1  [(size_t)NTOK*DMODEL];

// single fp16 activations
__device__ __half g_xn  [(size_t)NTOK*DMODEL];
__device__ __half g_xn2 [(size_t)NTOK*DMODEL];
__device__ __half g_ctx [(size_t)NTOK*DMODEL];
__device__ __half g_h   [(size_t)NTOK*DFF];

// qkv output: [tok][3072] (Q scaled by 1/8 in cols 0..1023)
__device__ __half g_qsp [(size_t)NTOK*QKVROW];

// single-fp16 transposed weights [N, K] K-major
__device__ __half g_wqkvf[(size_t)QKVROW*DMODEL];
__device__ __half g_wof  [(size_t)DMODEL*DMODEL];
__device__ __half g_w1f  [(size_t)DFF*DMODEL];
__device__ __half g_w2f  [(size_t)DMODEL*DFF];

// V transposed per (b,h): [bh][d][t]
__device__ __half g_vtf[(size_t)BATCH*NHEADS*DKEY*TSEQ];

// ---------------- helpers ----------------------------------------------------
__device__ __forceinline__ uint32_t smem_u32(const void* p) {
    uint32_t a;
    asm("{ .reg .u64 t; cvta.to.shared.u64 t, %1; cvt.u32.u64 %0, t; }"
        : "=r"(a) : "l"(p));
    return a;
}
#define CP_ASYNC16(dst, src) \
    asm volatile("cp.async.cg.shared.global [%0], [%1], 16;" :: "r"(dst), "l"(src) : "memory")
#define CP_COMMIT() asm volatile("cp.async.commit_group;" ::: "memory")
#define CP_WAIT0()  asm volatile("cp.async.wait_group 0;"  ::: "memory")
#define CP_WAIT1()  asm volatile("cp.async.wait_group 1;"  ::: "memory")

__device__ __forceinline__ void ldmat4(uint32_t (&r)[4], uint32_t addr) {
    asm volatile("ldmatrix.sync.aligned.m8n8.x4.shared.b16 {%0,%1,%2,%3}, [%4];"
        : "=r"(r[0]), "=r"(r[1]), "=r"(r[2]), "=r"(r[3]) : "r"(addr));
}
__device__ __forceinline__ void mma16816h(float (&d)[4], const uint32_t (&a)[4],
                                          const uint32_t b0, const uint32_t b1) {
    asm volatile("mma.sync.aligned.m16n8k16.row.col.f32.f16.f16.f32 "
        "{%0,%1,%2,%3}, {%4,%5,%6,%7}, {%8,%9}, {%0,%1,%2,%3};"
        : "+f"(d[0]), "+f"(d[1]), "+f"(d[2]), "+f"(d[3])
        : "r"(a[0]), "r"(a[1]), "r"(a[2]), "r"(a[3]), "r"(b0), "r"(b1));
}
__device__ __forceinline__ uint32_t h2u(__half2 v) {
    union { __half2 h; uint32_t u; } c; c.h = v; return c.u;
}

// ---------------- LayerNorm -> single fp16 -----------------------------------
__inline__ __device__ float warp_sum(float v) {
    #pragma unroll
    for (int o = 16; o > 0; o >>= 1) v += __shfl_xor_sync(0xffffffffu, v, o);
    return v;
}

__global__ __launch_bounds__(256) void ln_f16(
    const float* __restrict__ x, const float* __restrict__ g,
    const float* __restrict__ b, __half* __restrict__ y)
{
    const int row = blockIdx.x;
    const int tid = threadIdx.x;
    const float* xr = x + (size_t)row * DMODEL;

    float4 v = reinterpret_cast<const float4*>(xr)[tid];
    float s  = v.x + v.y + v.z + v.w;
    float sq = v.x*v.x + v.y*v.y + v.z*v.z + v.w*v.w;

    __shared__ float sh_s[8], sh_q[8];
    float ws = warp_sum(s), wq = warp_sum(sq);
    int warp = tid >> 5, lane = tid & 31;
    if (lane == 0) { sh_s[warp] = ws; sh_q[warp] = wq; }
    __syncthreads();
    __shared__ float sh_mean, sh_rstd;
    if (tid == 0) {
        float ts = 0.f, tq = 0.f;
        #pragma unroll
        for (int i = 0; i < 8; i++) { ts += sh_s[i]; tq += sh_q[i]; }
        float mean = ts * (1.0f / DMODEL);
        float var  = tq * (1.0f / DMODEL) - mean * mean;
        sh_mean = mean; sh_rstd = rsqrtf(var + 1e-5f);
    }
    __syncthreads();
    float mean = sh_mean, rstd = sh_rstd;

    float4 gv = reinterpret_cast<const float4*>(g)[tid];
    float4 bv = reinterpret_cast<const float4*>(b)[tid];
    float ox = (v.x - mean) * rstd * gv.x + bv.x;
    float oy = (v.y - mean) * rstd * gv.y + bv.y;
    float oz = (v.z - mean) * rstd * gv.z + bv.z;
    float ow = (v.w - mean) * rstd * gv.w + bv.w;

    size_t o = (size_t)row * DMODEL + tid * 4;
    *reinterpret_cast<__half2*>(y + o)     = __floats2half2_rn(ox, oy);
    *reinterpret_cast<__half2*>(y + o + 2) = __floats2half2_rn(oz, ow);
}

// ---------------- fused weight transpose: all 4 weights in one launch --------
__global__ __launch_bounds__(256) void wconv_all(
    const float* __restrict__ Wqkv, const float* __restrict__ Wo,
    const float* __restrict__ W1,   const float* __restrict__ W2,
    __half* __restrict__ oqkv, __half* __restrict__ oo,
    __half* __restrict__ o1,   __half* __restrict__ o2)
{
    __shared__ float t[32][33];
    const int bid = blockIdx.x;
    const float* W; __half* out; int K, N, n0, k0;
    if (bid < 3072)      { W = Wqkv; out = oqkv; K = 1024; N = 3072;
                           n0 = (bid % 96) * 32;  k0 = (bid / 96) * 32; }
    else if (bid < 4096) { int b2 = bid - 3072; W = Wo; out = oo; K = 1024; N = 1024;
                           n0 = (b2 % 32) * 32;  k0 = (b2 / 32) * 32; }
    else if (bid < 8192) { int b2 = bid - 4096; W = W1; out = o1; K = 1024; N = 4096;
                           n0 = (b2 % 128) * 32; k0 = (b2 / 128) * 32; }
    else                 { int b2 = bid - 8192; W = W2; out = o2; K = 4096; N = 1024;
                           n0 = (b2 % 32) * 32;  k0 = (b2 / 32) * 32; }

    const int tx = threadIdx.x & 31, ty = threadIdx.x >> 5;
    #pragma unroll
    for (int j = 0; j < 4; j++)
        t[ty + j*8][tx] = W[(size_t)(k0 + ty + j*8) * N + n0 + tx];
    __syncthreads();
    #pragma unroll
    for (int j = 0; j < 4; j++) {
        int n = ty + j*8;
        out[(size_t)(n0 + n) * K + k0 + tx] = __float2half_rn(t[tx][n]);
    }
}

// ---------------- V transpose ------------------------------------------------
__global__ __launch_bounds__(256) void vtrans(
    const __half* __restrict__ qsp, __half* __restrict__ vt)
{
    __shared__ __half t[32][40];
    const int t0 = blockIdx.x * 32, d0 = blockIdx.y * 32;
    const int bh = blockIdx.z, b = bh >> 4, h = bh & 15;
    const int tx = threadIdx.x & 31, ty = threadIdx.x >> 5;
    #pragma unroll
    for (int j = 0; j < 4; j++) {
        int tt = ty + j*8;
        t[tt][tx] = qsp[(size_t)(b*TSEQ + t0 + tt) * QKVROW + 2048 + h*64 + d0 + tx];
    }
    __syncthreads();
    #pragma unroll
    for (int j = 0; j < 4; j++) {
        int d = ty + j*8;
        vt[((size_t)bh * 64 + d0 + d) * TSEQ + t0 + tx] = t[tx][d];
    }
}

// ---------------- 1-product fp16 GEMM, CTA 256x128, warp tile 64x64 ----------
#define GPITCH 144u
#define GT_A   (256u * GPITCH)     // 36864
#define GT_B   (128u * GPITCH)     // 18432
#define G1STG  (GT_A + GT_B)       // 55296
#define G1SMEM (3u * G1STG)        // 165888

template<bool RELU, bool RES, bool OF16, bool QKSCALE>
__global__ __launch_bounds__(256, 1) void gemm_f16(
    const __half* __restrict__ Af, const __half* __restrict__ Bf,
    const float* __restrict__ bias, const float* __restrict__ res,
    float* __restrict__ C, __half* __restrict__ Ch, int N, int K)
{
    extern __shared__ char sm[];
    const int tid = threadIdx.x, wid = tid >> 5, lane = tid & 31;
    const int m0 = blockIdx.y * 256, n0 = blockIdx.x * 128;
    const uint32_t sb = smem_u32(sm);

    const int mw = (wid & 3) * 64;      // 4 warps down M
    const int nw = (wid >> 2) * 64;     // 2 warps across N
    const int lg = lane >> 3, lr = lane & 7;

    float d[4][8][4];
    #pragma unroll
    for (int mt = 0; mt < 4; mt++)
        #pragma unroll
        for (int nt = 0; nt < 8; nt++)
            #pragma unroll
            for (int i = 0; i < 4; i++) d[mt][nt][i] = 0.f;

    const int nkt = K >> 6;

    auto loadStage = [&](int s, int k0) {
        const uint32_t st = sb + (uint32_t)s * G1STG;
        const __half* baseA = Af + (size_t)m0 * K + k0;
        const __half* baseB = Bf + (size_t)n0 * K + k0;
        #pragma unroll
        for (int i = 0; i < 8; i++) {          // A: 256 rows x 8 segs
            int lin = i * 256 + tid;
            int row = lin >> 3, seg = lin & 7;
            uint32_t off = (uint32_t)row * GPITCH + (uint32_t)seg * 16u;
            CP_ASYNC16(st + off, (const char*)(baseA + (size_t)row * K + seg * 8));
        }
        #pragma unroll
        for (int i = 0; i < 4; i++) {          // B: 128 rows x 8 segs
            int lin = i * 256 + tid;
            int row = lin >> 3, seg = lin & 7;
            uint32_t off = (uint32_t)row * GPITCH + (uint32_t)seg * 16u;
            CP_ASYNC16(st + GT_A + off, (const char*)(baseB + (size_t)row * K + seg * 8));
        }
        CP_COMMIT();
    };

    auto mmaStage = [&](int s) {
        const uint32_t AS = sb + (uint32_t)s * G1STG;
        const uint32_t BS = AS + GT_A;
        #pragma unroll
        for (int kh = 0; kh < 4; kh++) {
            uint32_t af[4][4];
            #pragma unroll
            for (int mt = 0; mt < 4; mt++) {
                uint32_t roff = (uint32_t)(mw + mt*16 + lr + ((lg & 1) << 3)) * GPITCH
                              + (uint32_t)(kh*16 + ((lg >> 1) << 3)) * 2u;
                ldmat4(af[mt], AS + roff);
            }
            #pragma unroll
            for (int bt = 0; bt < 4; bt++) {
                uint32_t roff = (uint32_t)(nw + bt*16 + lr + ((lg & 2) ? 8 : 0)) * GPITCH
                              + (uint32_t)(kh*16 + ((lg & 1) << 3)) * 2u;
                uint32_t bh[4];
                ldmat4(bh, BS + roff);
                #pragma unroll
                for (int mt = 0; mt < 4; mt++) {
                    mma16816h(d[mt][2*bt+0], af[mt], bh[0], bh[1]);
                    mma16816h(d[mt][2*bt+1], af[mt], bh[2], bh[3]);
                }
            }
        }
    };

    loadStage(0, 0);
    loadStage(1, 64);
    for (int kt = 0; kt < nkt; kt++) {
        if (kt + 1 < nkt) { CP_WAIT1(); } else { CP_WAIT0(); }
        __syncthreads();
        if (kt + 2 < nkt) loadStage((kt + 2) % 3, (kt + 2) << 6);
        mmaStage(kt % 3);
    }

    const int qr = lane >> 2;
    const int qc = (lane & 3) * 2;
    #pragma unroll
    for (int mt = 0; mt < 4; mt++) {
        const int r0 = m0 + mw + mt * 16 + qr;
        const int r1 = r0 + 8;
        #pragma unroll
        for (int nt = 0; nt < 8; nt++) {
            const int c = n0 + nw + nt * 8 + qc;
            float2 bb = *reinterpret_cast<const float2*>(bias + c);
            float2 o0, o1;
            o0.x = d[mt][nt][0] + bb.x; o0.y = d[mt][nt][1] + bb.y;
            o1.x = d[mt][nt][2] + bb.x; o1.y = d[mt][nt][3] + bb.y;
            if (QKSCALE) {
                const float sc = (c < 1024) ? 0.125f : 1.0f;
                o0.x *= sc; o0.y *= sc; o1.x *= sc; o1.y *= sc;
            }
            if (RELU) {
                o0.x = fmaxf(o0.x, 0.f); o0.y = fmaxf(o0.y, 0.f);
                o1.x = fmaxf(o1.x, 0.f); o1.y = fmaxf(o1.y, 0.f);
            }
            if (RES) {
                float2 u0 = *reinterpret_cast<const float2*>(res + (size_t)r0 * N + c);
                float2 u1 = *reinterpret_cast<const float2*>(res + (size_t)r1 * N + c);
                o0.x += u0.x; o0.y += u0.y; o1.x += u1.x; o1.y += u1.y;
            }
            if (OF16) {
                *reinterpret_cast<__half2*>(Ch + (size_t)r0 * N + c) = __floats2half2_rn(o0.x, o0.y);
                *reinterpret_cast<__half2*>(Ch + (size_t)r1 * N + c) = __floats2half2_rn(o1.x, o1.y);
            } else {
                *reinterpret_cast<float2*>(C + (size_t)r0 * N + c) = o0;
                *reinterpret_cast<float2*>(C + (size_t)r1 * N + c) = o1;
            }
        }
    }
}

// ---------------- MMA flash attention (causal), 1-product fp16 ---------------
#define APITCH 144u
#define AQ_B   (128u * APITCH)
#define AKV_B  (64u * APITCH)
#define ASTG_B (2u * AKV_B)                // K, V
#define ASMEM  (AQ_B + 3u * ASTG_B)        // 73728

__global__ __launch_bounds__(256, 1) void flash_mma(
    const __half* __restrict__ qsp, const __half* __restrict__ vtf,
    __half* __restrict__ ctx)
{
    extern __shared__ char sm[];
    const int tid = threadIdx.x, wid = tid >> 5, lane = tid & 31;
    const int q0 = (15 - blockIdx.x) * 128;
    const int bh = blockIdx.y, b = bh >> 4, h = bh & 15;
    const int mw = wid * 16;
    const int lg = lane >> 3, lr = lane & 7;
    const int qr = lane >> 2, qc = (lane & 3) * 2;

    const uint32_t sb = smem_u32(sm);
    const uint32_t QS = sb;
    const uint32_t ST = sb + AQ_B;

    {
        const __half* qb = qsp + (size_t)(b*TSEQ + q0) * QKVROW + h*64;
        #pragma unroll
        for (int i = 0; i < 4; i++) {
            int lin = i * 256 + tid;
            int row = lin >> 3, seg = lin & 7;
            uint32_t off = (uint32_t)row * APITCH + (uint32_t)seg * 16u;
            CP_ASYNC16(QS + off, (const char*)(qb + (size_t)row * QKVROW) + seg * 16);
        }
        CP_COMMIT();
    }

    auto loadKV = [&](int s, int key0) {
        const uint32_t Ks = ST + (uint32_t)s * ASTG_B;
        const uint32_t Vs = Ks + AKV_B;
        const __half* kb = qsp + (size_t)(b*TSEQ + key0) * QKVROW + 1024 + h*64;
        const __half* vb = vtf + (size_t)bh * 64 * TSEQ + key0;
        #pragma unroll
        for (int i = 0; i < 2; i++) {
            int lin = i * 256 + tid;
            int row = lin >> 3, seg = lin & 7;
            uint32_t off = (uint32_t)row * APITCH + (uint32_t)seg * 16u;
            CP_ASYNC16(Ks + off, (const char*)(kb + (size_t)row * QKVROW) + seg * 16);
            CP_ASYNC16(Vs + off, (const char*)(vb + (size_t)row * TSEQ) + seg * 16);
        }
        CP_COMMIT();
    };

    const int nkt = q0 / 64 + 2;
    loadKV(0, 0);
    loadKV(1, 64);
    CP_WAIT1();
    __syncthreads();

    uint32_t qf[4][4];
    #pragma unroll
    for (int kh = 0; kh < 4; kh++) {
        uint32_t roff = (uint32_t)(mw + lr + ((lg & 1) << 3)) * APITCH
                      + (uint32_t)(kh*16 + ((lg >> 1) << 3)) * 2u;
        ldmat4(qf[kh], QS + roff);
    }

    float o[8][4];
    #pragma unroll
    for (int nt = 0; nt < 8; nt++)
        #pragma unroll
        for (int i = 0; i < 4; i++) o[nt][i] = 0.f;
    float m0r = -1e30f, m1r = -1e30f, l0r = 0.f, l1r = 0.f;

    for (int kt = 0; kt < nkt; kt++) {
        const int key0 = kt * 64;
        if (kt > 0) {
            if (kt + 1 < nkt) { CP_WAIT1(); } else { CP_WAIT0(); }
            __syncthreads();
        }
        if (kt + 2 < nkt) loadKV((kt + 2) % 3, (kt + 2) * 64);

        if (key0 <= q0 + mw + 15) {
            const int s = kt % 3;
            const uint32_t Ks = ST + (uint32_t)s * ASTG_B;
            const uint32_t Vs = Ks + AKV_B;

            float sc[8][4];
            #pragma unroll
            for (int nt = 0; nt < 8; nt++)
                #pragma unroll
                for (int i = 0; i < 4; i++) sc[nt][i] = 0.f;

            #pragma unroll
            for (int kh = 0; kh < 4; kh++) {
                #pragma unroll
                for (int bt = 0; bt < 4; bt++) {
                    uint32_t roff = (uint32_t)(bt*16 + lr + ((lg & 2) ? 8 : 0)) * APITCH
                                  + (uint32_t)(kh*16 + ((lg & 1) << 3)) * 2u;
                    uint32_t kf[4];
                    ldmat4(kf, Ks + roff);
                    mma16816h(sc[2*bt+0], qf[kh], kf[0], kf[1]);
                    mma16816h(sc[2*bt+1], qf[kh], kf[2], kf[3]);
                }
            }

            const int row0 = q0 + mw + qr, row1 = row0 + 8;
            if (key0 + 63 > q0 + mw) {
                #pragma unroll
                for (int nt = 0; nt < 8; nt++) {
                    int c0 = key0 + nt*8 + qc;
                    if (c0     > row0) sc[nt][0] = -1e30f;
                    if (c0 + 1 > row0) sc[nt][1] = -1e30f;
                    if (c0     > row1) sc[nt][2] = -1e30f;
                    if (c0 + 1 > row1) sc[nt][3] = -1e30f;
                }
            }

            float mx0 = -1e30f, mx1 = -1e30f;
            #pragma unroll
            for (int nt = 0; nt < 8; nt++) {
                mx0 = fmaxf(mx0, fmaxf(sc[nt][0], sc[nt][1]));
                mx1 = fmaxf(mx1, fmaxf(sc[nt][2], sc[nt][3]));
            }
            mx0 = fmaxf(mx0, __shfl_xor_sync(0xffffffffu, mx0, 1));
            mx0 = fmaxf(mx0, __shfl_xor_sync(0xffffffffu, mx0, 2));
            mx1 = fmaxf(mx1, __shfl_xor_sync(0xffffffffu, mx1, 1));
            mx1 = fmaxf(mx1, __shfl_xor_sync(0xffffffffu, mx1, 2));
            float mn0 = fmaxf(m0r, mx0), mn1 = fmaxf(m1r, mx1);
            float a0 = __expf(m0r - mn0), a1 = __expf(m1r - mn1);
            float sum0 = 0.f, sum1 = 0.f;
            #pragma unroll
            for (int nt = 0; nt < 8; nt++) {
                sc[nt][0] = __expf(sc[nt][0] - mn0);
                sc[nt][1] = __expf(sc[nt][1] - mn0);
                sc[nt][2] = __expf(sc[nt][2] - mn1);
                sc[nt][3] = __expf(sc[nt][3] - mn1);
                sum0 += sc[nt][0] + sc[nt][1];
                sum1 += sc[nt][2] + sc[nt][3];
            }
            sum0 += __shfl_xor_sync(0xffffffffu, sum0, 1);
            sum0 += __shfl_xor_sync(0xffffffffu, sum0, 2);
            sum1 += __shfl_xor_sync(0xffffffffu, sum1, 1);
            sum1 += __shfl_xor_sync(0xffffffffu, sum1, 2);
            l0r = l0r * a0 + sum0;
            l1r = l1r * a1 + sum1;
            m0r = mn0; m1r = mn1;
            #pragma unroll
            for (int nt = 0; nt < 8; nt++) {
                o[nt][0] *= a0; o[nt][1] *= a0;
                o[nt][2] *= a1; o[nt][3] *= a1;
            }

            #pragma unroll
            for (int kh2 = 0; kh2 < 4; kh2++) {
                const int n0t = 2 * kh2, n1t = 2 * kh2 + 1;
                uint32_t pa[4];
                pa[0] = h2u(__floats2half2_rn(sc[n0t][0], sc[n0t][1]));
                pa[1] = h2u(__floats2half2_rn(sc[n0t][2], sc[n0t][3]));
                pa[2] = h2u(__floats2half2_rn(sc[n1t][0], sc[n1t][1]));
                pa[3] = h2u(__floats2half2_rn(sc[n1t][2], sc[n1t][3]));
                #pragma unroll
                for (int bt = 0; bt < 4; bt++) {
                    uint32_t roff = (uint32_t)(bt*16 + lr + ((lg & 2) ? 8 : 0)) * APITCH
                                  + (uint32_t)(kh2*16 + ((lg & 1) << 3)) * 2u;
                    uint32_t vf[4];
                    ldmat4(vf, Vs + roff);
                    mma16816h(o[2*bt+0], pa, vf[0], vf[1]);
                    mma16816h(o[2*bt+1], pa, vf[2], vf[3]);
                }
            }
        }
    }

    // ---- normalize + store ----
    const float inv0 = 1.f / l0r, inv1 = 1.f / l1r;
    const int row0 = q0 + mw + qr, row1 = row0 + 8;
    const size_t o0 = (size_t)(b*TSEQ + row0) * DMODEL + h*64;
    const size_t o1 = (size_t)(b*TSEQ + row1) * DMODEL + h*64;
    #pragma unroll
    for (int nt = 0; nt < 8; nt++) {
        int col = nt*8 + qc;
        *reinterpret_cast<__half2*>(ctx + o0 + col) =
            __floats2half2_rn(o[nt][0] * inv0, o[nt][1] * inv0);
        *reinterpret_cast<__half2*>(ctx + o1 + col) =
            __floats2half2_rn(o[nt][2] * inv1, o[nt][3] * inv1);
    }
}

// ---------------- launch ------------------------------------------------------
extern "C" void kernel_launch(void* const* d_in, const int* in_sizes, int n_in,
                              void* d_out, int out_size)
{
    (void)in_sizes; (void)n_in; (void)out_size;
    const float* X     = (const float*)d_in[0];
    const float* Wqkv  = (const float*)d_in[1];
    const float* bqkv  = (const float*)d_in[2];
    const float* Wo    = (const float*)d_in[3];
    const float* bo    = (const float*)d_in[4];
    const float* W1    = (const float*)d_in[5];
    const float* b1    = (const float*)d_in[6];
    const float* W2    = (const float*)d_in[7];
    const float* b2    = (const float*)d_in[8];
    const float* ln1g  = (const float*)d_in[9];
    const float* ln1b  = (const float*)d_in[10];
    const float* ln2g  = (const float*)d_in[11];
    const float* ln2b  = (const float*)d_in[12];
    float* out = (float*)d_out;

    float* x1;
    cudaGetSymbolAddress((void**)&x1, g_x1);

    __half *xn, *xn2, *ctx, *h, *qsp, *wqkvf, *wof, *w1f, *w2f, *vtf;
    cudaGetSymbolAddress((void**)&xn,    g_xn);
    cudaGetSymbolAddress((void**)&xn2,   g_xn2);
    cudaGetSymbolAddress((void**)&ctx,   g_ctx);
    cudaGetSymbolAddress((void**)&h,     g_h);
    cudaGetSymbolAddress((void**)&qsp,   g_qsp);
    cudaGetSymbolAddress((void**)&wqkvf, g_wqkvf);
    cudaGetSymbolAddress((void**)&wof,   g_wof);
    cudaGetSymbolAddress((void**)&w1f,   g_w1f);
    cudaGetSymbolAddress((void**)&w2f,   g_w2f);
    cudaGetSymbolAddress((void**)&vtf,   g_vtf);

    cudaFuncSetAttribute(gemm_f16<false,false,true,true>,  cudaFuncAttributeMaxDynamicSharedMemorySize, G1SMEM);
    cudaFuncSetAttribute(gemm_f16<false,true,false,false>, cudaFuncAttributeMaxDynamicSharedMemorySize, G1SMEM);
    cudaFuncSetAttribute(gemm_f16<true,false,true,false>,  cudaFuncAttributeMaxDynamicSharedMemorySize, G1SMEM);
    cudaFuncSetAttribute(flash_mma, cudaFuncAttributeMaxDynamicSharedMemorySize, ASMEM);

    // weight transpose + convert to fp16 (one fused launch, 12288 blocks)
    wconv_all<<<12288, 256>>>(Wqkv, Wo, W1, W2, wqkvf, wof, w1f, w2f);

    // 1. LN1 -> fp16
    ln_f16<<<NTOK, 256>>>(X, ln1g, ln1b, xn);
    // 2. QKV -> fp16, Q cols pre-scaled by 1/8
    gemm_f16<false,false,true,true><<<dim3(QKVROW/128, NTOK/256), 256, G1SMEM>>>(
        xn, wqkvf, bqkv, nullptr, nullptr, qsp, QKVROW, DMODEL);
    // 3a. V transpose
    vtrans<<<dim3(TSEQ/32, DKEY/32, BATCH*NHEADS), 256>>>(qsp, vtf);
    // 3b. MMA flash attention -> fp16 ctx
    flash_mma<<<dim3(TSEQ/128, BATCH*NHEADS), 256, ASMEM>>>(qsp, vtf, ctx);
    // 4. x1 = ctx @ Wo + bo + X  (fp32 out)
    gemm_f16<false,true,false,false><<<dim3(DMODEL/128, NTOK/256), 256, G1SMEM>>>(
        ctx, wof, bo, X, x1, nullptr, DMODEL, DMODEL);
    // 5. LN2 -> fp16
    ln_f16<<<NTOK, 256>>>(x1, ln2g, ln2b, xn2);
    // 6. h = relu(xn2 @ W1 + b1)  (fp16 out)
    gemm_f16<true,false,true,false><<<dim3(DFF/128, NTOK/256), 256, G1SMEM>>>(
        xn2, w1f, b1, nullptr, nullptr, h, DFF, DMODEL);
    // 7. out = h @ W2 + b2 + x1  (fp32 out)
    gemm_f16<false,true,false,false><<<dim3(DMODEL/128, NTOK/256), 256, G1SMEM>>>(
        h, w2f, b2, x1, out, nullptr, DMODEL, DFF);
}

// round 12
// speedup vs baseline: 8.8026x; 1.0174x over previous
#include <cuda_runtime.h>
#include <cuda_fp16.h>
#include <cstdint>
#include <cstddef>

// Problem constants
#define BATCH   2
#define TSEQ    2048
#define DMODEL  1024
#define NHEADS  16
#define DKEY    64
#define DFF     4096
#define NTOK    (BATCH*TSEQ)          // 4096
#define QKVROW  (3*NHEADS*DKEY)       // 3072

// ---------------- scratch ----------------------------------------------------
__device__ float g_x1  [(size_t)NTOK*DMODEL];

// single fp16 activations
__device__ __half g_xn  [(size_t)NTOK*DMODEL];
__device__ __half g_xn2 [(size_t)NTOK*DMODEL];
__device__ __half g_ctx [(size_t)NTOK*DMODEL];
__device__ __half g_h   [(size_t)NTOK*DFF];

// qkv output: [tok][3072] (Q scaled by 1/8 in cols 0..1023)
__device__ __half g_qsp [(size_t)NTOK*QKVROW];

// single-fp16 transposed weights [N, K] K-major
__device__ __half g_wqkvf[(size_t)QKVROW*DMODEL];
__device__ __half g_wof  [(size_t)DMODEL*DMODEL];
__device__ __half g_w1f  [(size_t)DFF*DMODEL];
__device__ __half g_w2f  [(size_t)DMODEL*DFF];

// ---------------- helpers ----------------------------------------------------
__device__ __forceinline__ uint32_t smem_u32(const void* p) {
    uint32_t a;
    asm("{ .reg .u64 t; cvta.to.shared.u64 t, %1; cvt.u32.u64 %0, t; }"
        : "=r"(a) : "l"(p));
    return a;
}
#define CP_ASYNC16(dst, src) \
    asm volatile("cp.async.cg.shared.global [%0], [%1], 16;" :: "r"(dst), "l"(src) : "memory")
#define CP_COMMIT() asm volatile("cp.async.commit_group;" ::: "memory")
#define CP_WAIT0()  asm volatile("cp.async.wait_group 0;"  ::: "memory")
#define CP_WAIT1()  asm volatile("cp.async.wait_group 1;"  ::: "memory")
#define CP_WAIT2()  asm volatile("cp.async.wait_group 2;"  ::: "memory")

__device__ __forceinline__ void ldmat4(uint32_t (&r)[4], uint32_t addr) {
    asm volatile("ldmatrix.sync.aligned.m8n8.x4.shared.b16 {%0,%1,%2,%3}, [%4];"
        : "=r"(r[0]), "=r"(r[1]), "=r"(r[2]), "=r"(r[3]) : "r"(addr));
}
__device__ __forceinline__ void ldmat4t(uint32_t (&r)[4], uint32_t addr) {
    asm volatile("ldmatrix.sync.aligned.m8n8.x4.trans.shared.b16 {%0,%1,%2,%3}, [%4];"
        : "=r"(r[0]), "=r"(r[1]), "=r"(r[2]), "=r"(r[3]) : "r"(addr));
}
__device__ __forceinline__ void mma16816h(float (&d)[4], const uint32_t (&a)[4],
                                          const uint32_t b0, const uint32_t b1) {
    asm volatile("mma.sync.aligned.m16n8k16.row.col.f32.f16.f16.f32 "
        "{%0,%1,%2,%3}, {%4,%5,%6,%7}, {%8,%9}, {%0,%1,%2,%3};"
        : "+f"(d[0]), "+f"(d[1]), "+f"(d[2]), "+f"(d[3])
        : "r"(a[0]), "r"(a[1]), "r"(a[2]), "r"(a[3]), "r"(b0), "r"(b1));
}
__device__ __forceinline__ uint32_t h2u(__half2 v) {
    union { __half2 h; uint32_t u; } c; c.h = v; return c.u;
}

// ---------------- LayerNorm -> single fp16 -----------------------------------
__inline__ __device__ float warp_sum(float v) {
    #pragma unroll
    for (int o = 16; o > 0; o >>= 1) v += __shfl_xor_sync(0xffffffffu, v, o);
    return v;
}

__global__ __launch_bounds__(256) void ln_f16(
    const float* __restrict__ x, const float* __restrict__ g,
    const float* __restrict__ b, __half* __restrict__ y)
{
    const int row = blockIdx.x;
    const int tid = threadIdx.x;
    const float* xr = x + (size_t)row * DMODEL;

    float4 v = reinterpret_cast<const float4*>(xr)[tid];
    float s  = v.x + v.y + v.z + v.w;
    float sq = v.x*v.x + v.y*v.y + v.z*v.z + v.w*v.w;

    __shared__ float sh_s[8], sh_q[8];
    float ws = warp_sum(s), wq = warp_sum(sq);
    int warp = tid >> 5, lane = tid & 31;
    if (lane == 0) { sh_s[warp] = ws; sh_q[warp] = wq; }
    __syncthreads();
    __shared__ float sh_mean, sh_rstd;
    if (tid == 0) {
        float ts = 0.f, tq = 0.f;
        #pragma unroll
        for (int i = 0; i < 8; i++) { ts += sh_s[i]; tq += sh_q[i]; }
        float mean = ts * (1.0f / DMODEL);
        float var  = tq * (1.0f / DMODEL) - mean * mean;
        sh_mean = mean; sh_rstd = rsqrtf(var + 1e-5f);
    }
    __syncthreads();
    float mean = sh_mean, rstd = sh_rstd;

    float4 gv = reinterpret_cast<const float4*>(g)[tid];
    float4 bv = reinterpret_cast<const float4*>(b)[tid];
    float ox = (v.x - mean) * rstd * gv.x + bv.x;
    float oy = (v.y - mean) * rstd * gv.y + bv.y;
    float oz = (v.z - mean) * rstd * gv.z + bv.z;
    float ow = (v.w - mean) * rstd * gv.w + bv.w;

    size_t o = (size_t)row * DMODEL + tid * 4;
    *reinterpret_cast<__half2*>(y + o)     = __floats2half2_rn(ox, oy);
    *reinterpret_cast<__half2*>(y + o + 2) = __floats2half2_rn(oz, ow);
}

// ---------------- fused weight transpose: all 4 weights in one launch --------
__global__ __launch_bounds__(256) void wconv_all(
    const float* __restrict__ Wqkv, const float* __restrict__ Wo,
    const float* __restrict__ W1,   const float* __restrict__ W2,
    __half* __restrict__ oqkv, __half* __restrict__ oo,
    __half* __restrict__ o1,   __half* __restrict__ o2)
{
    __shared__ float t[32][33];
    const int bid = blockIdx.x;
    const float* W; __half* out; int K, N, n0, k0;
    if (bid < 3072)      { W = Wqkv; out = oqkv; K = 1024; N = 3072;
                           n0 = (bid % 96) * 32;  k0 = (bid / 96) * 32; }
    else if (bid < 4096) { int b2 = bid - 3072; W = Wo; out = oo; K = 1024; N = 1024;
                           n0 = (b2 % 32) * 32;  k0 = (b2 / 32) * 32; }
    else if (bid < 8192) { int b2 = bid - 4096; W = W1; out = o1; K = 1024; N = 4096;
                           n0 = (b2 % 128) * 32; k0 = (b2 / 128) * 32; }
    else                 { int b2 = bid - 8192; W = W2; out = o2; K = 4096; N = 1024;
                           n0 = (b2 % 32) * 32;  k0 = (b2 / 32) * 32; }

    const int tx = threadIdx.x & 31, ty = threadIdx.x >> 5;
    #pragma unroll
    for (int j = 0; j < 4; j++)
        t[ty + j*8][tx] = W[(size_t)(k0 + ty + j*8) * N + n0 + tx];
    __syncthreads();
    #pragma unroll
    for (int j = 0; j < 4; j++) {
        int n = ty + j*8;
        out[(size_t)(n0 + n) * K + k0 + tx] = __float2half_rn(t[tx][n]);
    }
}

// ---------------- 1-product fp16 GEMM, CTA 256x128, warp 64x64, 4-stage ------
#define GPITCH 144u
#define GT_A   (256u * GPITCH)     // 36864
#define GT_B   (128u * GPITCH)     // 18432
#define G1STG  (GT_A + GT_B)       // 55296
#define G1SMEM (4u * G1STG)        // 221184

template<bool RELU, bool RES, bool OF16, bool QKSCALE>
__global__ __launch_bounds__(256, 1) void gemm_f16(
    const __half* __restrict__ Af, const __half* __restrict__ Bf,
    const float* __restrict__ bias, const float* __restrict__ res,
    float* __restrict__ C, __half* __restrict__ Ch, int N, int K)
{
    extern __shared__ char sm[];
    const int tid = threadIdx.x, wid = tid >> 5, lane = tid & 31;
    const int m0 = blockIdx.y * 256, n0 = blockIdx.x * 128;
    const uint32_t sb = smem_u32(sm);

    const int mw = (wid & 3) * 64;
    const int nw = (wid >> 2) * 64;
    const int lg = lane >> 3, lr = lane & 7;

    float d[4][8][4];
    #pragma unroll
    for (int mt = 0; mt < 4; mt++)
        #pragma unroll
        for (int nt = 0; nt < 8; nt++)
            #pragma unroll
            for (int i = 0; i < 4; i++) d[mt][nt][i] = 0.f;

    const int nkt = K >> 6;   // >= 16 always

    auto loadStage = [&](int s, int k0) {
        const uint32_t st = sb + (uint32_t)s * G1STG;
        const __half* baseA = Af + (size_t)m0 * K + k0;
        const __half* baseB = Bf + (size_t)n0 * K + k0;
        #pragma unroll
        for (int i = 0; i < 8; i++) {
            int lin = i * 256 + tid;
            int row = lin >> 3, seg = lin & 7;
            uint32_t off = (uint32_t)row * GPITCH + (uint32_t)seg * 16u;
            CP_ASYNC16(st + off, (const char*)(baseA + (size_t)row * K + seg * 8));
        }
        #pragma unroll
        for (int i = 0; i < 4; i++) {
            int lin = i * 256 + tid;
            int row = lin >> 3, seg = lin & 7;
            uint32_t off = (uint32_t)row * GPITCH + (uint32_t)seg * 16u;
            CP_ASYNC16(st + GT_A + off, (const char*)(baseB + (size_t)row * K + seg * 8));
        }
        CP_COMMIT();
    };

    auto mmaStage = [&](int s) {
        const uint32_t AS = sb + (uint32_t)s * G1STG;
        const uint32_t BS = AS + GT_A;
        #pragma unroll
        for (int kh = 0; kh < 4; kh++) {
            uint32_t af[4][4];
            #pragma unroll
            for (int mt = 0; mt < 4; mt++) {
                uint32_t roff = (uint32_t)(mw + mt*16 + lr + ((lg & 1) << 3)) * GPITCH
                              + (uint32_t)(kh*16 + ((lg >> 1) << 3)) * 2u;
                ldmat4(af[mt], AS + roff);
            }
            #pragma unroll
            for (int bt = 0; bt < 4; bt++) {
                uint32_t roff = (uint32_t)(nw + bt*16 + lr + ((lg & 2) ? 8 : 0)) * GPITCH
                              + (uint32_t)(kh*16 + ((lg & 1) << 3)) * 2u;
                uint32_t bh[4];
                ldmat4(bh, BS + roff);
                #pragma unroll
                for (int mt = 0; mt < 4; mt++) {
                    mma16816h(d[mt][2*bt+0], af[mt], bh[0], bh[1]);
                    mma16816h(d[mt][2*bt+1], af[mt], bh[2], bh[3]);
                }
            }
        }
    };

    loadStage(0, 0);
    loadStage(1, 64);
    loadStage(2, 128);
    for (int kt = 0; kt < nkt; kt++) {
        if (kt + 2 < nkt)      { CP_WAIT2(); }
        else if (kt + 1 < nkt) { CP_WAIT1(); }
        else                   { CP_WAIT0(); }
        __syncthreads();
        if (kt + 3 < nkt) loadStage((kt + 3) & 3, (kt + 3) << 6);
        mmaStage(kt & 3);
    }

    const int qr = lane >> 2;
    const int qc = (lane & 3) * 2;
    #pragma unroll
    for (int mt = 0; mt < 4; mt++) {
        const int r0 = m0 + mw + mt * 16 + qr;
        const int r1 = r0 + 8;
        #pragma unroll
        for (int nt = 0; nt < 8; nt++) {
            const int c = n0 + nw + nt * 8 + qc;
            float2 bb = *reinterpret_cast<const float2*>(bias + c);
            float2 o0, o1;
            o0.x = d[mt][nt][0] + bb.x; o0.y = d[mt][nt][1] + bb.y;
            o1.x = d[mt][nt][2] + bb.x; o1.y = d[mt][nt][3] + bb.y;
            if (QKSCALE) {
                const float sc = (c < 1024) ? 0.125f : 1.0f;
                o0.x *= sc; o0.y *= sc; o1.x *= sc; o1.y *= sc;
            }
            if (RELU) {
                o0.x = fmaxf(o0.x, 0.f); o0.y = fmaxf(o0.y, 0.f);
                o1.x = fmaxf(o1.x, 0.f); o1.y = fmaxf(o1.y, 0.f);
            }
            if (RES) {
                float2 u0 = *reinterpret_cast<const float2*>(res + (size_t)r0 * N + c);
                float2 u1 = *reinterpret_cast<const float2*>(res + (size_t)r1 * N + c);
                o0.x += u0.x; o0.y += u0.y; o1.x += u1.x; o1.y += u1.y;
            }
            if (OF16) {
                *reinterpret_cast<__half2*>(Ch + (size_t)r0 * N + c) = __floats2half2_rn(o0.x, o0.y);
                *reinterpret_cast<__half2*>(Ch + (size_t)r1 * N + c) = __floats2half2_rn(o1.x, o1.y);
            } else {
                *reinterpret_cast<float2*>(C + (size_t)r0 * N + c) = o0;
                *reinterpret_cast<float2*>(C + (size_t)r1 * N + c) = o1;
            }
        }
    }
}

// ---------------- MMA flash attention: V via ldmatrix.trans ------------------
#define APITCH 144u
#define AQ_B   (128u * APITCH)
#define AKV_B  (64u * APITCH)
#define ASTG_B (2u * AKV_B)                // K, V
#define ASMEM  (AQ_B + 3u * ASTG_B)        // 73728

__global__ __launch_bounds__(256, 1) void flash_mma(
    const __half* __restrict__ qsp, __half* __restrict__ ctx)
{
    extern __shared__ char sm[];
    const int tid = threadIdx.x, wid = tid >> 5, lane = tid & 31;
    const int q0 = (15 - blockIdx.x) * 128;
    const int bh = blockIdx.y, b = bh >> 4, h = bh & 15;
    const int mw = wid * 16;
    const int lg = lane >> 3, lr = lane & 7;
    const int qr = lane >> 2, qc = (lane & 3) * 2;

    const uint32_t sb = smem_u32(sm);
    const uint32_t QS = sb;
    const uint32_t ST = sb + AQ_B;

    {
        const __half* qb = qsp + (size_t)(b*TSEQ + q0) * QKVROW + h*64;
        #pragma unroll
        for (int i = 0; i < 4; i++) {
            int lin = i * 256 + tid;
            int row = lin >> 3, seg = lin & 7;
            uint32_t off = (uint32_t)row * APITCH + (uint32_t)seg * 16u;
            CP_ASYNC16(QS + off, (const char*)(qb + (size_t)row * QKVROW) + seg * 16);
        }
        CP_COMMIT();
    }

    // K rows from qsp cols 1024.., V rows from qsp cols 2048.. (natural [t][d])
    auto loadKV = [&](int s, int key0) {
        const uint32_t Ks = ST + (uint32_t)s * ASTG_B;
        const uint32_t Vs = Ks + AKV_B;
        const __half* kb = qsp + (size_t)(b*TSEQ + key0) * QKVROW + 1024 + h*64;
        const __half* vb = qsp + (size_t)(b*TSEQ + key0) * QKVROW + 2048 + h*64;
        #pragma unroll
        for (int i = 0; i < 2; i++) {
            int lin = i * 256 + tid;
            int row = lin >> 3, seg = lin & 7;
            uint32_t off = (uint32_t)row * APITCH + (uint32_t)seg * 16u;
            CP_ASYNC16(Ks + off, (const char*)(kb + (size_t)row * QKVROW) + seg * 16);
            CP_ASYNC16(Vs + off, (const char*)(vb + (size_t)row * QKVROW) + seg * 16);
        }
        CP_COMMIT();
    };

    const int nkt = q0 / 64 + 2;
    loadKV(0, 0);
    loadKV(1, 64);
    CP_WAIT1();
    __syncthreads();

    uint32_t qf[4][4];
    #pragma unroll
    for (int kh = 0; kh < 4; kh++) {
        uint32_t roff = (uint32_t)(mw + lr + ((lg & 1) << 3)) * APITCH
                      + (uint32_t)(kh*16 + ((lg >> 1) << 3)) * 2u;
        ldmat4(qf[kh], QS + roff);
    }

    float o[8][4];
    #pragma unroll
    for (int nt = 0; nt < 8; nt++)
        #pragma unroll
        for (int i = 0; i < 4; i++) o[nt][i] = 0.f;
    float m0r = -1e30f, m1r = -1e30f, l0r = 0.f, l1r = 0.f;

    for (int kt = 0; kt < nkt; kt++) {
        const int key0 = kt * 64;
        if (kt > 0) {
            if (kt + 1 < nkt) { CP_WAIT1(); } else { CP_WAIT0(); }
            __syncthreads();
        }
        if (kt + 2 < nkt) loadKV((kt + 2) % 3, (kt + 2) * 64);

        if (key0 <= q0 + mw + 15) {
            const int s = kt % 3;
            const uint32_t Ks = ST + (uint32_t)s * ASTG_B;
            const uint32_t Vs = Ks + AKV_B;

            float sc[8][4];
            #pragma unroll
            for (int nt = 0; nt < 8; nt++)
                #pragma unroll
                for (int i = 0; i < 4; i++) sc[nt][i] = 0.f;

            #pragma unroll
            for (int kh = 0; kh < 4; kh++) {
                #pragma unroll
                for (int bt = 0; bt < 4; bt++) {
                    uint32_t roff = (uint32_t)(bt*16 + lr + ((lg & 2) ? 8 : 0)) * APITCH
                                  + (uint32_t)(kh*16 + ((lg & 1) << 3)) * 2u;
                    uint32_t kf[4];
                    ldmat4(kf, Ks + roff);
                    mma16816h(sc[2*bt+0], qf[kh], kf[0], kf[1]);
                    mma16816h(sc[2*bt+1], qf[kh], kf[2], kf[3]);
                }
            }

            const int row0 = q0 + mw + qr, row1 = row0 + 8;
            if (key0 + 63 > q0 + mw) {
                #pragma unroll
                for (int nt = 0; nt < 8; nt++) {
                    int c0 = key0 + nt*8 + qc;
                    if (c0     > row0) sc[nt][0] = -1e30f;
                    if (c0 + 1 > row0) sc[nt][1] = -1e30f;
                    if (c0     > row1) sc[nt][2] = -1e30f;
                    if (c0 + 1 > row1) sc[nt][3] = -1e30f;
                }
            }

            float mx0 = -1e30f, mx1 = -1e30f;
            #pragma unroll
            for (int nt = 0; nt < 8; nt++) {
                mx0 = fmaxf(mx0, fmaxf(sc[nt][0], sc[nt][1]));
                mx1 = fmaxf(mx1, fmaxf(sc[nt][2], sc[nt][3]));
            }
            mx0 = fmaxf(mx0, __shfl_xor_sync(0xffffffffu, mx0, 1));
            mx0 = fmaxf(mx0, __shfl_xor_sync(0xffffffffu, mx0, 2));
            mx1 = fmaxf(mx1, __shfl_xor_sync(0xffffffffu, mx1, 1));
            mx1 = fmaxf(mx1, __shfl_xor_sync(0xffffffffu, mx1, 2));
            float mn0 = fmaxf(m0r, mx0), mn1 = fmaxf(m1r, mx1);
            float a0 = __expf(m0r - mn0), a1 = __expf(m1r - mn1);
            float sum0 = 0.f, sum1 = 0.f;
            #pragma unroll
            for (int nt = 0; nt < 8; nt++) {
                sc[nt][0] = __expf(sc[nt][0] - mn0);
                sc[nt][1] = __expf(sc[nt][1] - mn0);
                sc[nt][2] = __expf(sc[nt][2] - mn1);
                sc[nt][3] = __expf(sc[nt][3] - mn1);
                sum0 += sc[nt][0] + sc[nt][1];
                sum1 += sc[nt][2] + sc[nt][3];
            }
            sum0 += __shfl_xor_sync(0xffffffffu, sum0, 1);
            sum0 += __shfl_xor_sync(0xffffffffu, sum0, 2);
            sum1 += __shfl_xor_sync(0xffffffffu, sum1, 1);
            sum1 += __shfl_xor_sync(0xffffffffu, sum1, 2);
            l0r = l0r * a0 + sum0;
            l1r = l1r * a1 + sum1;
            m0r = mn0; m1r = mn1;
            #pragma unroll
            for (int nt = 0; nt < 8; nt++) {
                o[nt][0] *= a0; o[nt][1] *= a0;
                o[nt][2] *= a1; o[nt][3] *= a1;
            }

            // P @ V with V staged [t][d]; ldmatrix.trans yields [d][t] fragments
            #pragma unroll
            for (int kh2 = 0; kh2 < 4; kh2++) {
                const int n0t = 2 * kh2, n1t = 2 * kh2 + 1;
                uint32_t pa[4];
                pa[0] = h2u(__floats2half2_rn(sc[n0t][0], sc[n0t][1]));
                pa[1] = h2u(__floats2half2_rn(sc[n0t][2], sc[n0t][3]));
                pa[2] = h2u(__floats2half2_rn(sc[n1t][0], sc[n1t][1]));
                pa[3] = h2u(__floats2half2_rn(sc[n1t][2], sc[n1t][3]));
                #pragma unroll
                for (int bt = 0; bt < 4; bt++) {
                    // rows = t (k dim), cols = d (n dim)
                    uint32_t roff = (uint32_t)(kh2*16 + lr + ((lg & 1) << 3)) * APITCH
                                  + (uint32_t)(bt*16 + ((lg & 2) ? 8 : 0)) * 2u;
                    uint32_t vf[4];
                    ldmat4t(vf, Vs + roff);
                    mma16816h(o[2*bt+0], pa, vf[0], vf[1]);
                    mma16816h(o[2*bt+1], pa, vf[2], vf[3]);
                }
            }
        }
    }

    // ---- normalize + store ----
    const float inv0 = 1.f / l0r, inv1 = 1.f / l1r;
    const int row0 = q0 + mw + qr, row1 = row0 + 8;
    const size_t o0 = (size_t)(b*TSEQ + row0) * DMODEL + h*64;
    const size_t o1 = (size_t)(b*TSEQ + row1) * DMODEL + h*64;
    #pragma unroll
    for (int nt = 0; nt < 8; nt++) {
        int col = nt*8 + qc;
        *reinterpret_cast<__half2*>(ctx + o0 + col) =
            __floats2half2_rn(o[nt][0] * inv0, o[nt][1] * inv0);
        *reinterpret_cast<__half2*>(ctx + o1 + col) =
            __floats2half2_rn(o[nt][2] * inv1, o[nt][3] * inv1);
    }
}

// ---------------- launch ------------------------------------------------------
extern "C" void kernel_launch(void* const* d_in, const int* in_sizes, int n_in,
                              void* d_out, int out_size)
{
    (void)in_sizes; (void)n_in; (void)out_size;
    const float* X     = (const float*)d_in[0];
    const float* Wqkv  = (const float*)d_in[1];
    const float* bqkv  = (const float*)d_in[2];
    const float* Wo    = (const float*)d_in[3];
    const float* bo    = (const float*)d_in[4];
    const float* W1    = (const float*)d_in[5];
    const float* b1    = (const float*)d_in[6];
    const float* W2    = (const float*)d_in[7];
    const float* b2    = (const float*)d_in[8];
    const float* ln1g  = (const float*)d_in[9];
    const float* ln1b  = (const float*)d_in[10];
    const float* ln2g  = (const float*)d_in[11];
    const float* ln2b  = (const float*)d_in[12];
    float* out = (float*)d_out;

    float* x1;
    cudaGetSymbolAddress((void**)&x1, g_x1);

    __half *xn, *xn2, *ctx, *h, *qsp, *wqkvf, *wof, *w1f, *w2f;
    cudaGetSymbolAddress((void**)&xn,    g_xn);
    cudaGetSymbolAddress((void**)&xn2,   g_xn2);
    cudaGetSymbolAddress((void**)&ctx,   g_ctx);
    cudaGetSymbolAddress((void**)&h,     g_h);
    cudaGetSymbolAddress((void**)&qsp,   g_qsp);
    cudaGetSymbolAddress((void**)&wqkvf, g_wqkvf);
    cudaGetSymbolAddress((void**)&wof,   g_wof);
    cudaGetSymbolAddress((void**)&w1f,   g_w1f);
    cudaGetSymbolAddress((void**)&w2f,   g_w2f);

    cudaFuncSetAttribute(gemm_f16<false,false,true,true>,  cudaFuncAttributeMaxDynamicSharedMemorySize, G1SMEM);
    cudaFuncSetAttribute(gemm_f16<false,true,false,false>, cudaFuncAttributeMaxDynamicSharedMemorySize, G1SMEM);
    cudaFuncSetAttribute(gemm_f16<true,false,true,false>,  cudaFuncAttributeMaxDynamicSharedMemorySize, G1SMEM);
    cudaFuncSetAttribute(flash_mma, cudaFuncAttributeMaxDynamicSharedMemorySize, ASMEM);

    // weight transpose + convert to fp16 (one fused launch)
    wconv_all<<<12288, 256>>>(Wqkv, Wo, W1, W2, wqkvf, wof, w1f, w2f);

    // 1. LN1 -> fp16
    ln_f16<<<NTOK, 256>>>(X, ln1g, ln1b, xn);
    // 2. QKV -> fp16, Q cols pre-scaled by 1/8
    gemm_f16<false,false,true,true><<<dim3(QKVROW/128, NTOK/256), 256, G1SMEM>>>(
        xn, wqkvf, bqkv, nullptr, nullptr, qsp, QKVROW, DMODEL);
    // 3. MMA flash attention (V transposed in-LDSM) -> fp16 ctx
    flash_mma<<<dim3(TSEQ/128, BATCH*NHEADS), 256, ASMEM>>>(qsp, ctx);
    // 4. x1 = ctx @ Wo + bo + X  (fp32 out)
    gemm_f16<false,true,false,false><<<dim3(DMODEL/128, NTOK/256), 256, G1SMEM>>>(
        ctx, wof, bo, X, x1, nullptr, DMODEL, DMODEL);
    // 5. LN2 -> fp16
    ln_f16<<<NTOK, 256>>>(x1, ln2g, ln2b, xn2);
    // 6. h = relu(xn2 @ W1 + b1)  (fp16 out)
    gemm_f16<true,false,true,false><<<dim3(DFF/128, NTOK/256), 256, G1SMEM>>>(
        xn2, w1f, b1, nullptr, nullptr, h, DFF, DMODEL);
    // 7. out = h @ W2 + b2 + x1  (fp32 out)
    gemm_f16<false,true,false,false><<<dim3(DMODEL/128, NTOK/256), 256, G1SMEM>>>(
        h, w2f, b2, x1, out, nullptr, DMODEL, DFF);
}

// round 13
// speedup vs baseline: 8.9152x; 1.0128x over previous
#include <cuda_runtime.h>
#include <cuda_fp16.h>
#include <cstdint>
#include <cstddef>

// Problem constants
#define BATCH   2
#define TSEQ    2048
#define DMODEL  1024
#define NHEADS  16
#define DKEY    64
#define DFF     4096
#define NTOK    (BATCH*TSEQ)          // 4096
#define QKVROW  (3*NHEADS*DKEY)       // 3072

// ---------------- scratch ----------------------------------------------------
__device__ float g_x1  [(size_t)NTOK*DMODEL];

// single fp16 activations
__device__ __half g_xn  [(size_t)NTOK*DMODEL];
__device__ __half g_xn2 [(size_t)NTOK*DMODEL];
__device__ __half g_ctx [(size_t)NTOK*DMODEL];
__device__ __half g_h   [(size_t)NTOK*DFF];

// qkv output: [tok][3072] (Q scaled by 1/8 in cols 0..1023)
__device__ __half g_qsp [(size_t)NTOK*QKVROW];

// single-fp16 transposed weights [N, K] K-major
__device__ __half g_wqkvf[(size_t)QKVROW*DMODEL];
__device__ __half g_wof  [(size_t)DMODEL*DMODEL];
__device__ __half g_w1f  [(size_t)DFF*DMODEL];
__device__ __half g_w2f  [(size_t)DMODEL*DFF];

// ---------------- helpers ----------------------------------------------------
__device__ __forceinline__ uint32_t smem_u32(const void* p) {
    uint32_t a;
    asm("{ .reg .u64 t; cvta.to.shared.u64 t, %1; cvt.u32.u64 %0, t; }"
        : "=r"(a) : "l"(p));
    return a;
}
#define CP_ASYNC16(dst, src) \
    asm volatile("cp.async.cg.shared.global [%0], [%1], 16;" :: "r"(dst), "l"(src) : "memory")
#define CP_COMMIT() asm volatile("cp.async.commit_group;" ::: "memory")
#define CP_WAIT0()  asm volatile("cp.async.wait_group 0;"  ::: "memory")
#define CP_WAIT1()  asm volatile("cp.async.wait_group 1;"  ::: "memory")
#define CP_WAIT2()  asm volatile("cp.async.wait_group 2;"  ::: "memory")

__device__ __forceinline__ void ldmat4(uint32_t (&r)[4], uint32_t addr) {
    asm volatile("ldmatrix.sync.aligned.m8n8.x4.shared.b16 {%0,%1,%2,%3}, [%4];"
        : "=r"(r[0]), "=r"(r[1]), "=r"(r[2]), "=r"(r[3]) : "r"(addr));
}
__device__ __forceinline__ void ldmat4t(uint32_t (&r)[4], uint32_t addr) {
    asm volatile("ldmatrix.sync.aligned.m8n8.x4.trans.shared.b16 {%0,%1,%2,%3}, [%4];"
        : "=r"(r[0]), "=r"(r[1]), "=r"(r[2]), "=r"(r[3]) : "r"(addr));
}
__device__ __forceinline__ void mma16816h(float (&d)[4], const uint32_t (&a)[4],
                                          const uint32_t b0, const uint32_t b1) {
    asm volatile("mma.sync.aligned.m16n8k16.row.col.f32.f16.f16.f32 "
        "{%0,%1,%2,%3}, {%4,%5,%6,%7}, {%8,%9}, {%0,%1,%2,%3};"
        : "+f"(d[0]), "+f"(d[1]), "+f"(d[2]), "+f"(d[3])
        : "r"(a[0]), "r"(a[1]), "r"(a[2]), "r"(a[3]), "r"(b0), "r"(b1));
}
__device__ __forceinline__ uint32_t h2u(__half2 v) {
    union { __half2 h; uint32_t u; } c; c.h = v; return c.u;
}

// ---------------- LayerNorm -> single fp16 -----------------------------------
__inline__ __device__ float warp_sum(float v) {
    #pragma unroll
    for (int o = 16; o > 0; o >>= 1) v += __shfl_xor_sync(0xffffffffu, v, o);
    return v;
}

__global__ __launch_bounds__(256) void ln_f16(
    const float* __restrict__ x, const float* __restrict__ g,
    const float* __restrict__ b, __half* __restrict__ y)
{
    const int row = blockIdx.x;
    const int tid = threadIdx.x;
    const float* xr = x + (size_t)row * DMODEL;

    float4 v = reinterpret_cast<const float4*>(xr)[tid];
    float s  = v.x + v.y + v.z + v.w;
    float sq = v.x*v.x + v.y*v.y + v.z*v.z + v.w*v.w;

    __shared__ float sh_s[8], sh_q[8];
    float ws = warp_sum(s), wq = warp_sum(sq);
    int warp = tid >> 5, lane = tid & 31;
    if (lane == 0) { sh_s[warp] = ws; sh_q[warp] = wq; }
    __syncthreads();
    __shared__ float sh_mean, sh_rstd;
    if (tid == 0) {
        float ts = 0.f, tq = 0.f;
        #pragma unroll
        for (int i = 0; i < 8; i++) { ts += sh_s[i]; tq += sh_q[i]; }
        float mean = ts * (1.0f / DMODEL);
        float var  = tq * (1.0f / DMODEL) - mean * mean;
        sh_mean = mean; sh_rstd = rsqrtf(var + 1e-5f);
    }
    __syncthreads();
    float mean = sh_mean, rstd = sh_rstd;

    float4 gv = reinterpret_cast<const float4*>(g)[tid];
    float4 bv = reinterpret_cast<const float4*>(b)[tid];
    float ox = (v.x - mean) * rstd * gv.x + bv.x;
    float oy = (v.y - mean) * rstd * gv.y + bv.y;
    float oz = (v.z - mean) * rstd * gv.z + bv.z;
    float ow = (v.w - mean) * rstd * gv.w + bv.w;

    size_t o = (size_t)row * DMODEL + tid * 4;
    *reinterpret_cast<__half2*>(y + o)     = __floats2half2_rn(ox, oy);
    *reinterpret_cast<__half2*>(y + o + 2) = __floats2half2_rn(oz, ow);
}

// ---------------- fused weight transpose: all 4 weights in one launch --------
__global__ __launch_bounds__(256) void wconv_all(
    const float* __restrict__ Wqkv, const float* __restrict__ Wo,
    const float* __restrict__ W1,   const float* __restrict__ W2,
    __half* __restrict__ oqkv, __half* __restrict__ oo,
    __half* __restrict__ o1,   __half* __restrict__ o2)
{
    __shared__ float t[32][33];
    const int bid = blockIdx.x;
    const float* W; __half* out; int K, N, n0, k0;
    if (bid < 3072)      { W = Wqkv; out = oqkv; K = 1024; N = 3072;
                           n0 = (bid % 96) * 32;  k0 = (bid / 96) * 32; }
    else if (bid < 4096) { int b2 = bid - 3072; W = Wo; out = oo; K = 1024; N = 1024;
                           n0 = (b2 % 32) * 32;  k0 = (b2 / 32) * 32; }
    else if (bid < 8192) { int b2 = bid - 4096; W = W1; out = o1; K = 1024; N = 4096;
                           n0 = (b2 % 128) * 32; k0 = (b2 / 128) * 32; }
    else                 { int b2 = bid - 8192; W = W2; out = o2; K = 4096; N = 1024;
                           n0 = (b2 % 32) * 32;  k0 = (b2 / 32) * 32; }

    const int tx = threadIdx.x & 31, ty = threadIdx.x >> 5;
    #pragma unroll
    for (int j = 0; j < 4; j++)
        t[ty + j*8][tx] = W[(size_t)(k0 + ty + j*8) * N + n0 + tx];
    __syncthreads();
    #pragma unroll
    for (int j = 0; j < 4; j++) {
        int n = ty + j*8;
        out[(size_t)(n0 + n) * K + k0 + tx] = __float2half_rn(t[tx][n]);
    }
}

// ---------------- 1-product fp16 GEMM, CTA 256x128, warp 64x64, 4-stage ------
#define GPITCH 144u
#define GT_A   (256u * GPITCH)     // 36864
#define GT_B   (128u * GPITCH)     // 18432
#define G1STG  (GT_A + GT_B)       // 55296
#define G1SMEM (4u * G1STG)        // 221184

template<bool RELU, bool RES, bool OF16, bool QKSCALE>
__global__ __launch_bounds__(256, 1) void gemm_f16(
    const __half* __restrict__ Af, const __half* __restrict__ Bf,
    const float* __restrict__ bias, const float* __restrict__ res,
    float* __restrict__ C, __half* __restrict__ Ch, int N, int K)
{
    extern __shared__ char sm[];
    const int tid = threadIdx.x, wid = tid >> 5, lane = tid & 31;
    const int m0 = blockIdx.y * 256, n0 = blockIdx.x * 128;
    const uint32_t sb = smem_u32(sm);

    const int mw = (wid & 3) * 64;
    const int nw = (wid >> 2) * 64;
    const int lg = lane >> 3, lr = lane & 7;

    float d[4][8][4];
    #pragma unroll
    for (int mt = 0; mt < 4; mt++)
        #pragma unroll
        for (int nt = 0; nt < 8; nt++)
            #pragma unroll
            for (int i = 0; i < 4; i++) d[mt][nt][i] = 0.f;

    const int nkt = K >> 6;

    auto loadStage = [&](int s, int k0) {
        const uint32_t st = sb + (uint32_t)s * G1STG;
        const __half* baseA = Af + (size_t)m0 * K + k0;
        const __half* baseB = Bf + (size_t)n0 * K + k0;
        #pragma unroll
        for (int i = 0; i < 8; i++) {
            int lin = i * 256 + tid;
            int row = lin >> 3, seg = lin & 7;
            uint32_t off = (uint32_t)row * GPITCH + (uint32_t)seg * 16u;
            CP_ASYNC16(st + off, (const char*)(baseA + (size_t)row * K + seg * 8));
        }
        #pragma unroll
        for (int i = 0; i < 4; i++) {
            int lin = i * 256 + tid;
            int row = lin >> 3, seg = lin & 7;
            uint32_t off = (uint32_t)row * GPITCH + (uint32_t)seg * 16u;
            CP_ASYNC16(st + GT_A + off, (const char*)(baseB + (size_t)row * K + seg * 8));
        }
        CP_COMMIT();
    };

    auto mmaStage = [&](int s) {
        const uint32_t AS = sb + (uint32_t)s * G1STG;
        const uint32_t BS = AS + GT_A;
        #pragma unroll
        for (int kh = 0; kh < 4; kh++) {
            uint32_t af[4][4];
            #pragma unroll
            for (int mt = 0; mt < 4; mt++) {
                uint32_t roff = (uint32_t)(mw + mt*16 + lr + ((lg & 1) << 3)) * GPITCH
                              + (uint32_t)(kh*16 + ((lg >> 1) << 3)) * 2u;
                ldmat4(af[mt], AS + roff);
            }
            #pragma unroll
            for (int bt = 0; bt < 4; bt++) {
                uint32_t roff = (uint32_t)(nw + bt*16 + lr + ((lg & 2) ? 8 : 0)) * GPITCH
                              + (uint32_t)(kh*16 + ((lg & 1) << 3)) * 2u;
                uint32_t bh[4];
                ldmat4(bh, BS + roff);
                #pragma unroll
                for (int mt = 0; mt < 4; mt++) {
                    mma16816h(d[mt][2*bt+0], af[mt], bh[0], bh[1]);
                    mma16816h(d[mt][2*bt+1], af[mt], bh[2], bh[3]);
                }
            }
        }
    };

    loadStage(0, 0);
    loadStage(1, 64);
    loadStage(2, 128);
    for (int kt = 0; kt < nkt; kt++) {
        if (kt + 2 < nkt)      { CP_WAIT2(); }
        else if (kt + 1 < nkt) { CP_WAIT1(); }
        else                   { CP_WAIT0(); }
        __syncthreads();
        if (kt + 3 < nkt) loadStage((kt + 3) & 3, (kt + 3) << 6);
        mmaStage(kt & 3);
    }

    const int qr = lane >> 2;
    const int qc = (lane & 3) * 2;
    #pragma unroll
    for (int mt = 0; mt < 4; mt++) {
        const int r0 = m0 + mw + mt * 16 + qr;
        const int r1 = r0 + 8;
        #pragma unroll
        for (int nt = 0; nt < 8; nt++) {
            const int c = n0 + nw + nt * 8 + qc;
            float2 bb = *reinterpret_cast<const float2*>(bias + c);
            float2 o0, o1;
            o0.x = d[mt][nt][0] + bb.x; o0.y = d[mt][nt][1] + bb.y;
            o1.x = d[mt][nt][2] + bb.x; o1.y = d[mt][nt][3] + bb.y;
            if (QKSCALE) {
                const float sc = (c < 1024) ? 0.125f : 1.0f;
                o0.x *= sc; o0.y *= sc; o1.x *= sc; o1.y *= sc;
            }
            if (RELU) {
                o0.x = fmaxf(o0.x, 0.f); o0.y = fmaxf(o0.y, 0.f);
                o1.x = fmaxf(o1.x, 0.f); o1.y = fmaxf(o1.y, 0.f);
            }
            if (RES) {
                float2 u0 = *reinterpret_cast<const float2*>(res + (size_t)r0 * N + c);
                float2 u1 = *reinterpret_cast<const float2*>(res + (size_t)r1 * N + c);
                o0.x += u0.x; o0.y += u0.y; o1.x += u1.x; o1.y += u1.y;
            }
            if (OF16) {
                *reinterpret_cast<__half2*>(Ch + (size_t)r0 * N + c) = __floats2half2_rn(o0.x, o0.y);
                *reinterpret_cast<__half2*>(Ch + (size_t)r1 * N + c) = __floats2half2_rn(o1.x, o1.y);
            } else {
                *reinterpret_cast<float2*>(C + (size_t)r0 * N + c) = o0;
                *reinterpret_cast<float2*>(C + (size_t)r1 * N + c) = o1;
            }
        }
    }
}

// ---------------- MMA flash attention: 2 CTAs/SM via register cap ------------
#define APITCH 144u
#define AQ_B   (128u * APITCH)
#define AKV_B  (64u * APITCH)
#define ASTG_B (2u * AKV_B)                // K, V
#define ASMEM  (AQ_B + 3u * ASTG_B)        // 73728

__global__ __launch_bounds__(256, 2) void flash_mma(
    const __half* __restrict__ qsp, __half* __restrict__ ctx)
{
    extern __shared__ char sm[];
    const int tid = threadIdx.x, wid = tid >> 5, lane = tid & 31;
    const int q0 = (15 - blockIdx.x) * 128;
    const int bh = blockIdx.y, b = bh >> 4, h = bh & 15;
    const int mw = wid * 16;
    const int lg = lane >> 3, lr = lane & 7;
    const int qr = lane >> 2, qc = (lane & 3) * 2;

    const uint32_t sb = smem_u32(sm);
    const uint32_t QS = sb;
    const uint32_t ST = sb + AQ_B;

    {
        const __half* qb = qsp + (size_t)(b*TSEQ + q0) * QKVROW + h*64;
        #pragma unroll
        for (int i = 0; i < 4; i++) {
            int lin = i * 256 + tid;
            int row = lin >> 3, seg = lin & 7;
            uint32_t off = (uint32_t)row * APITCH + (uint32_t)seg * 16u;
            CP_ASYNC16(QS + off, (const char*)(qb + (size_t)row * QKVROW) + seg * 16);
        }
        CP_COMMIT();
    }

    auto loadKV = [&](int s, int key0) {
        const uint32_t Ks = ST + (uint32_t)s * ASTG_B;
        const uint32_t Vs = Ks + AKV_B;
        const __half* kb = qsp + (size_t)(b*TSEQ + key0) * QKVROW + 1024 + h*64;
        const __half* vb = qsp + (size_t)(b*TSEQ + key0) * QKVROW + 2048 + h*64;
        #pragma unroll
        for (int i = 0; i < 2; i++) {
            int lin = i * 256 + tid;
            int row = lin >> 3, seg = lin & 7;
            uint32_t off = (uint32_t)row * APITCH + (uint32_t)seg * 16u;
            CP_ASYNC16(Ks + off, (const char*)(kb + (size_t)row * QKVROW) + seg * 16);
            CP_ASYNC16(Vs + off, (const char*)(vb + (size_t)row * QKVROW) + seg * 16);
        }
        CP_COMMIT();
    };

    const int nkt = q0 / 64 + 2;
    loadKV(0, 0);
    loadKV(1, 64);
    CP_WAIT1();
    __syncthreads();

    uint32_t qf[4][4];
    #pragma unroll
    for (int kh = 0; kh < 4; kh++) {
        uint32_t roff = (uint32_t)(mw + lr + ((lg & 1) << 3)) * APITCH
                      + (uint32_t)(kh*16 + ((lg >> 1) << 3)) * 2u;
        ldmat4(qf[kh], QS + roff);
    }

    float o[8][4];
    #pragma unroll
    for (int nt = 0; nt < 8; nt++)
        #pragma unroll
        for (int i = 0; i < 4; i++) o[nt][i] = 0.f;
    float m0r = -1e30f, m1r = -1e30f, l0r = 0.f, l1r = 0.f;

    for (int kt = 0; kt < nkt; kt++) {
        const int key0 = kt * 64;
        if (kt > 0) {
            if (kt + 1 < nkt) { CP_WAIT1(); } else { CP_WAIT0(); }
            __syncthreads();
        }
        if (kt + 2 < nkt) loadKV((kt + 2) % 3, (kt + 2) * 64);

        if (key0 <= q0 + mw + 15) {
            const int s = kt % 3;
            const uint32_t Ks = ST + (uint32_t)s * ASTG_B;
            const uint32_t Vs = Ks + AKV_B;

            float sc[8][4];
            #pragma unroll
            for (int nt = 0; nt < 8; nt++)
                #pragma unroll
                for (int i = 0; i < 4; i++) sc[nt][i] = 0.f;

            #pragma unroll
            for (int kh = 0; kh < 4; kh++) {
                #pragma unroll
                for (int bt = 0; bt < 4; bt++) {
                    uint32_t roff = (uint32_t)(bt*16 + lr + ((lg & 2) ? 8 : 0)) * APITCH
                                  + (uint32_t)(kh*16 + ((lg & 1) << 3)) * 2u;
                    uint32_t kf[4];
                    ldmat4(kf, Ks + roff);
                    mma16816h(sc[2*bt+0], qf[kh], kf[0], kf[1]);
                    mma16816h(sc[2*bt+1], qf[kh], kf[2], kf[3]);
                }
            }

            const int row0 = q0 + mw + qr, row1 = row0 + 8;
            if (key0 + 63 > q0 + mw) {
                #pragma unroll
                for (int nt = 0; nt < 8; nt++) {
                    int c0 = key0 + nt*8 + qc;
                    if (c0     > row0) sc[nt][0] = -1e30f;
                    if (c0 + 1 > row0) sc[nt][1] = -1e30f;
                    if (c0     > row1) sc[nt][2] = -1e30f;
                    if (c0 + 1 > row1) sc[nt][3] = -1e30f;
                }
            }

            float mx0 = -1e30f, mx1 = -1e30f;
            #pragma unroll
            for (int nt = 0; nt < 8; nt++) {
                mx0 = fmaxf(mx0, fmaxf(sc[nt][0], sc[nt][1]));
                mx1 = fmaxf(mx1, fmaxf(sc[nt][2], sc[nt][3]));
            }
            mx0 = fmaxf(mx0, __shfl_xor_sync(0xffffffffu, mx0, 1));
            mx0 = fmaxf(mx0, __shfl_xor_sync(0xffffffffu, mx0, 2));
            mx1 = fmaxf(mx1, __shfl_xor_sync(0xffffffffu, mx1, 1));
            mx1 = fmaxf(mx1, __shfl_xor_sync(0xffffffffu, mx1, 2));
            float mn0 = fmaxf(m0r, mx0), mn1 = fmaxf(m1r, mx1);
            float a0 = __expf(m0r - mn0), a1 = __expf(m1r - mn1);
            float sum0 = 0.f, sum1 = 0.f;
            #pragma unroll
            for (int nt = 0; nt < 8; nt++) {
                sc[nt][0] = __expf(sc[nt][0] - mn0);
                sc[nt][1] = __expf(sc[nt][1] - mn0);
                sc[nt][2] = __expf(sc[nt][2] - mn1);
                sc[nt][3] = __expf(sc[nt][3] - mn1);
                sum0 += sc[nt][0] + sc[nt][1];
                sum1 += sc[nt][2] + sc[nt][3];
            }
            sum0 += __shfl_xor_sync(0xffffffffu, sum0, 1);
            sum0 += __shfl_xor_sync(0xffffffffu, sum0, 2);
            sum1 += __shfl_xor_sync(0xffffffffu, sum1, 1);
            sum1 += __shfl_xor_sync(0xffffffffu, sum1, 2);
            l0r = l0r * a0 + sum0;
            l1r = l1r * a1 + sum1;
            m0r = mn0; m1r = mn1;
            #pragma unroll
            for (int nt = 0; nt < 8; nt++) {
                o[nt][0] *= a0; o[nt][1] *= a0;
                o[nt][2] *= a1; o[nt][3] *= a1;
            }

            #pragma unroll
            for (int kh2 = 0; kh2 < 4; kh2++) {
                const int n0t = 2 * kh2, n1t = 2 * kh2 + 1;
                uint32_t pa[4];
                pa[0] = h2u(__floats2half2_rn(sc[n0t][0], sc[n0t][1]));
                pa[1] = h2u(__floats2half2_rn(sc[n0t][2], sc[n0t][3]));
                pa[2] = h2u(__floats2half2_rn(sc[n1t][0], sc[n1t][1]));
                pa[3] = h2u(__floats2half2_rn(sc[n1t][2], sc[n1t][3]));
                #pragma unroll
                for (int bt = 0; bt < 4; bt++) {
                    uint32_t roff = (uint32_t)(kh2*16 + lr + ((lg & 1) << 3)) * APITCH
                                  + (uint32_t)(bt*16 + ((lg & 2) ? 8 : 0)) * 2u;
                    uint32_t vf[4];
                    ldmat4t(vf, Vs + roff);
                    mma16816h(o[2*bt+0], pa, vf[0], vf[1]);
                    mma16816h(o[2*bt+1], pa, vf[2], vf[3]);
                }
            }
        }
    }

    // ---- normalize + store ----
    const float inv0 = 1.f / l0r, inv1 = 1.f / l1r;
    const int row0 = q0 + mw + qr, row1 = row0 + 8;
    const size_t o0 = (size_t)(b*TSEQ + row0) * DMODEL + h*64;
    const size_t o1 = (size_t)(b*TSEQ + row1) * DMODEL + h*64;
    #pragma unroll
    for (int nt = 0; nt < 8; nt++) {
        int col = nt*8 + qc;
        *reinterpret_cast<__half2*>(ctx + o0 + col) =
            __floats2half2_rn(o[nt][0] * inv0, o[nt][1] * inv0);
        *reinterpret_cast<__half2*>(ctx + o1 + col) =
            __floats2half2_rn(o[nt][2] * inv1, o[nt][3] * inv1);
    }
}

// ---------------- launch ------------------------------------------------------
extern "C" void kernel_launch(void* const* d_in, const int* in_sizes, int n_in,
                              void* d_out, int out_size)
{
    (void)in_sizes; (void)n_in; (void)out_size;
    const float* X     = (const float*)d_in[0];
    const float* Wqkv  = (const float*)d_in[1];
    const float* bqkv  = (const float*)d_in[2];
    const float* Wo    = (const float*)d_in[3];
    const float* bo    = (const float*)d_in[4];
    const float* W1    = (const float*)d_in[5];
    const float* b1    = (const float*)d_in[6];
    const float* W2    = (const float*)d_in[7];
    const float* b2    = (const float*)d_in[8];
    const float* ln1g  = (const float*)d_in[9];
    const float* ln1b  = (const float*)d_in[10];
    const float* ln2g  = (const float*)d_in[11];
    const float* ln2b  = (const float*)d_in[12];
    float* out = (float*)d_out;

    float* x1;
    cudaGetSymbolAddress((void**)&x1, g_x1);

    __half *xn, *xn2, *ctx, *h, *qsp, *wqkvf, *wof, *w1f, *w2f;
    cudaGetSymbolAddress((void**)&xn,    g_xn);
    cudaGetSymbolAddress((void**)&xn2,   g_xn2);
    cudaGetSymbolAddress((void**)&ctx,   g_ctx);
    cudaGetSymbolAddress((void**)&h,     g_h);
    cudaGetSymbolAddress((void**)&qsp,   g_qsp);
    cudaGetSymbolAddress((void**)&wqkvf, g_wqkvf);
    cudaGetSymbolAddress((void**)&wof,   g_wof);
    cudaGetSymbolAddress((void**)&w1f,   g_w1f);
    cudaGetSymbolAddress((void**)&w2f,   g_w2f);

    cudaFuncSetAttribute(gemm_f16<false,false,true,true>,  cudaFuncAttributeMaxDynamicSharedMemorySize, G1SMEM);
    cudaFuncSetAttribute(gemm_f16<false,true,false,false>, cudaFuncAttributeMaxDynamicSharedMemorySize, G1SMEM);
    cudaFuncSetAttribute(gemm_f16<true,false,true,false>,  cudaFuncAttributeMaxDynamicSharedMemorySize, G1SMEM);
    cudaFuncSetAttribute(flash_mma, cudaFuncAttributeMaxDynamicSharedMemorySize, ASMEM);

    // weight transpose + convert to fp16 (one fused launch)
    wconv_all<<<12288, 256>>>(Wqkv, Wo, W1, W2, wqkvf, wof, w1f, w2f);

    // 1. LN1 -> fp16
    ln_f16<<<NTOK, 256>>>(X, ln1g, ln1b, xn);
    // 2. QKV -> fp16, Q cols pre-scaled by 1/8
    gemm_f16<false,false,true,true><<<dim3(QKVROW/128, NTOK/256), 256, G1SMEM>>>(
        xn, wqkvf, bqkv, nullptr, nullptr, qsp, QKVROW, DMODEL);
    // 3. MMA flash attention (V transposed in-LDSM) -> fp16 ctx
    flash_mma<<<dim3(TSEQ/128, BATCH*NHEADS), 256, ASMEM>>>(qsp, ctx);
    // 4. x1 = ctx @ Wo + bo + X  (fp32 out)
    gemm_f16<false,true,false,false><<<dim3(DMODEL/128, NTOK/256), 256, G1SMEM>>>(
        ctx, wof, bo, X, x1, nullptr, DMODEL, DMODEL);
    // 5. LN2 -> fp16
    ln_f16<<<NTOK, 256>>>(x1, ln2g, ln2b, xn2);
    // 6. h = relu(xn2 @ W1 + b1)  (fp16 out)
    gemm_f16<true,false,true,false><<<dim3(DFF/128, NTOK/256), 256, G1SMEM>>>(
        xn2, w1f, b1, nullptr, nullptr, h, DFF, DMODEL);
    // 7. out = h @ W2 + b2 + x1  (fp32 out)
    gemm_f16<false,true,false,false><<<dim3(DMODEL/128, NTOK/256), 256, G1SMEM>>>(
        h, w2f, b2, x1, out, nullptr, DMODEL, DFF);
}